// round 1
// baseline (speedup 1.0000x reference)
#include <cuda_runtime.h>
#include <math.h>

// Problem constants
#define B_SZ 4
#define T_SZ 4096
#define V_SZ 1024
#define C_SZ 256
#define L_SZ 64                 // chunk length
#define NCH  64                 // chunks per batch (T/L)
#define BT   (B_SZ * T_SZ)      // 16384

// ---------------- scratch (static __device__ arrays; no runtime alloc) -----
__device__ float g_W  [4 * V_SZ * C_SZ];                    // 4 MB  (Wq,Wk,Wv,Wo)
__device__ float g_QKV[3 * BT * C_SZ];                      // 48 MB (Q,K,V)
__device__ float g_AS [B_SZ * NCH * C_SZ * C_SZ];           // 64 MB (A_c, then states in-place)
__device__ float g_R  [BT * C_SZ];                          // 16 MB (retrieved)

__device__ __forceinline__ float get_decay(const float* dl) {
    return 1.0f / (1.0f + expf(-dl[0]));
}

// ===========================================================================
// Generic 128x128x8 SGEMM, C = A[M,K] @ B[K,N]   ("nn")
// blockIdx.z selects B/C slab via strides (used for the 3 QKV projections).
// ===========================================================================
__global__ void __launch_bounds__(256) sgemm_nn(
    const float* __restrict__ A, const float* __restrict__ Bbase,
    float* __restrict__ Cbase, int M, int N, int K, size_t sB, size_t sC)
{
    const float* B = Bbase + (size_t)blockIdx.z * sB;
    float* C = Cbase + (size_t)blockIdx.z * sC;
    __shared__ float As[8][128];
    __shared__ float Bs[8][128];
    const int tid = threadIdx.x;
    const int m0 = blockIdx.y * 128, n0 = blockIdx.x * 128;
    const int tr = tid >> 4, tc = tid & 15;          // 16x16 thread grid, 8x8 each
    const int ar = tid >> 1, ac = (tid & 1) * 4;     // A tile load
    const int br = tid >> 5, bc = (tid & 31) * 4;    // B tile load
    float acc[8][8] = {};
    const float* Aptr = A + (size_t)(m0 + ar) * K + ac;
    const float* Bptr = B + (size_t)br * N + n0 + bc;
    for (int k0 = 0; k0 < K; k0 += 8) {
        float4 av = *(const float4*)(Aptr + k0);
        As[ac + 0][ar] = av.x; As[ac + 1][ar] = av.y;
        As[ac + 2][ar] = av.z; As[ac + 3][ar] = av.w;
        float4 bv = *(const float4*)(Bptr + (size_t)k0 * N);
        *(float4*)&Bs[br][bc] = bv;
        __syncthreads();
#pragma unroll
        for (int kk = 0; kk < 8; kk++) {
            float a[8], b[8];
#pragma unroll
            for (int i = 0; i < 8; i++) a[i] = As[kk][tr * 8 + i];
#pragma unroll
            for (int j = 0; j < 8; j++) b[j] = Bs[kk][tc * 8 + j];
#pragma unroll
            for (int i = 0; i < 8; i++)
#pragma unroll
                for (int j = 0; j < 8; j++)
                    acc[i][j] = fmaf(a[i], b[j], acc[i][j]);
        }
        __syncthreads();
    }
#pragma unroll
    for (int i = 0; i < 8; i++) {
        float* Cp = C + (size_t)(m0 + tr * 8 + i) * N + n0 + tc * 8;
#pragma unroll
        for (int j = 0; j < 8; j += 4) {
            float4 v = make_float4(acc[i][j], acc[i][j + 1], acc[i][j + 2], acc[i][j + 3]);
            *(float4*)(Cp + j) = v;
        }
    }
}

// ===========================================================================
// Generic 128x128x8 SGEMM, C = A[M,K] @ B[N,K]^T   ("nt")
// blockIdx.z selects among 4 B pointers (weight build / output projection).
// Optional scale read from device pointer (out_scale).
// ===========================================================================
__global__ void __launch_bounds__(256) sgemm_nt(
    const float* __restrict__ A,
    const float* __restrict__ B0, const float* __restrict__ B1,
    const float* __restrict__ B2, const float* __restrict__ B3,
    float* __restrict__ Cbase, int M, int N, int K, size_t sC,
    const float* __restrict__ scale_ptr)
{
    const float* B = (blockIdx.z == 0) ? B0 : (blockIdx.z == 1) ? B1
                   : (blockIdx.z == 2) ? B2 : B3;
    float* C = Cbase + (size_t)blockIdx.z * sC;
    __shared__ float As[8][128];
    __shared__ float Bs[8][128];
    const int tid = threadIdx.x;
    const int m0 = blockIdx.y * 128, n0 = blockIdx.x * 128;
    const int tr = tid >> 4, tc = tid & 15;
    const int ar = tid >> 1, ac = (tid & 1) * 4;
    float acc[8][8] = {};
    const float* Aptr = A + (size_t)(m0 + ar) * K + ac;
    const float* Bptr = B + (size_t)(n0 + ar) * K + ac;  // B rows are N dim
    for (int k0 = 0; k0 < K; k0 += 8) {
        float4 av = *(const float4*)(Aptr + k0);
        As[ac + 0][ar] = av.x; As[ac + 1][ar] = av.y;
        As[ac + 2][ar] = av.z; As[ac + 3][ar] = av.w;
        float4 bv = *(const float4*)(Bptr + k0);
        Bs[ac + 0][ar] = bv.x; Bs[ac + 1][ar] = bv.y;
        Bs[ac + 2][ar] = bv.z; Bs[ac + 3][ar] = bv.w;
        __syncthreads();
#pragma unroll
        for (int kk = 0; kk < 8; kk++) {
            float a[8], b[8];
#pragma unroll
            for (int i = 0; i < 8; i++) a[i] = As[kk][tr * 8 + i];
#pragma unroll
            for (int j = 0; j < 8; j++) b[j] = Bs[kk][tc * 8 + j];
#pragma unroll
            for (int i = 0; i < 8; i++)
#pragma unroll
                for (int j = 0; j < 8; j++)
                    acc[i][j] = fmaf(a[i], b[j], acc[i][j]);
        }
        __syncthreads();
    }
    float alpha = scale_ptr ? scale_ptr[0] : 1.0f;
#pragma unroll
    for (int i = 0; i < 8; i++) {
        float* Cp = C + (size_t)(m0 + tr * 8 + i) * N + n0 + tc * 8;
#pragma unroll
        for (int j = 0; j < 8; j += 4) {
            float4 v = make_float4(acc[i][j] * alpha, acc[i][j + 1] * alpha,
                                   acc[i][j + 2] * alpha, acc[i][j + 3] * alpha);
            *(float4*)(Cp + j) = v;
        }
    }
}

// ===========================================================================
// Per-chunk decayed KV outer-product sums:
//   A_c[c1,c2] = sum_{r<64} decay^r * K[cL+r,c1] * V[cL+r,c2]   (256x256)
// grid (2,2, B*NCH), 256 threads, 128x128 tile, "tn" layout (no transposes).
// ===========================================================================
__global__ void __launch_bounds__(256) chunk_kv_kernel(const float* __restrict__ dlp)
{
    const int z = blockIdx.z;
    const int b = z >> 6, c = z & 63;
    const size_t rowbase = ((size_t)b * T_SZ + (size_t)c * L_SZ) * C_SZ;
    const float* Kp = g_QKV + (size_t)BT * C_SZ + rowbase;
    const float* Vp = g_QKV + 2 * (size_t)BT * C_SZ + rowbase;
    float* Cp = g_AS + (size_t)z * C_SZ * C_SZ;
    const float decay = get_decay(dlp);
    const float lg2d = log2f(decay);

    __shared__ float As[8][128];
    __shared__ float Bs[8][128];
    const int tid = threadIdx.x;
    const int m0 = blockIdx.y * 128, n0 = blockIdx.x * 128;
    const int tr = tid >> 4, tc = tid & 15;
    const int lr = tid >> 5, lc = (tid & 31) * 4;
    float acc[8][8] = {};
    for (int k0 = 0; k0 < L_SZ; k0 += 8) {
        const float sc = exp2f((float)(k0 + lr) * lg2d);   // decay^r
        float4 av = *(const float4*)&Kp[(size_t)(k0 + lr) * C_SZ + m0 + lc];
        av.x *= sc; av.y *= sc; av.z *= sc; av.w *= sc;
        *(float4*)&As[lr][lc] = av;
        float4 bv = *(const float4*)&Vp[(size_t)(k0 + lr) * C_SZ + n0 + lc];
        *(float4*)&Bs[lr][lc] = bv;
        __syncthreads();
#pragma unroll
        for (int kk = 0; kk < 8; kk++) {
            float a[8], bb[8];
#pragma unroll
            for (int i = 0; i < 8; i++) a[i] = As[kk][tr * 8 + i];
#pragma unroll
            for (int j = 0; j < 8; j++) bb[j] = Bs[kk][tc * 8 + j];
#pragma unroll
            for (int i = 0; i < 8; i++)
#pragma unroll
                for (int j = 0; j < 8; j++)
                    acc[i][j] = fmaf(a[i], bb[j], acc[i][j]);
        }
        __syncthreads();
    }
#pragma unroll
    for (int i = 0; i < 8; i++) {
        float* Op = Cp + (size_t)(m0 + tr * 8 + i) * C_SZ + n0 + tc * 8;
#pragma unroll
        for (int j = 0; j < 8; j += 4)
            *(float4*)(Op + j) = make_float4(acc[i][j], acc[i][j + 1],
                                             acc[i][j + 2], acc[i][j + 3]);
    }
}

// ===========================================================================
// Backward state scan over chunks (in-place on g_AS):
//   run = 0; for c = NCH-1..0: { S_used[c] = run; run = A[c] + decay^L * run; }
// After this, g_AS[b][c] holds the state seen by chunk c.
// ===========================================================================
__global__ void scan_kernel(const float* __restrict__ dlp)
{
    const int e = blockIdx.x * blockDim.x + threadIdx.x;   // 0..65535
    const int b = blockIdx.y;
    const float decay = get_decay(dlp);
    const float dL = exp2f((float)L_SZ * log2f(decay));    // decay^64
    float run = 0.0f;
    float* base = g_AS + (size_t)b * NCH * (C_SZ * C_SZ) + e;
    for (int c = NCH - 1; c >= 0; c--) {
        float* p = base + (size_t)c * (C_SZ * C_SZ);
        float v = *p;
        *p = run;
        run = fmaf(dL, run, v);
    }
}

// ===========================================================================
// Per-chunk attention:
//   P[i,j] = (j>i) ? decay^(j-i-1) * (q_i . k_j) : 0        (intra, 64x64)
//   R[i,:] = P @ V_c  +  decay^(63-i) * (q_i @ S_c)          (64x256)
// grid (NCH, B), 256 threads.
// ===========================================================================
__global__ void __launch_bounds__(256) attn_kernel(const float* __restrict__ dlp)
{
    const int c = blockIdx.x, b = blockIdx.y;
    const size_t base = ((size_t)b * T_SZ + (size_t)c * L_SZ) * C_SZ;
    const float* Q  = g_QKV + base;
    const float* Kp = g_QKV + (size_t)BT * C_SZ + base;
    const float* Vp = g_QKV + 2 * (size_t)BT * C_SZ + base;
    const float* S  = g_AS + ((size_t)(b * NCH + c)) * (C_SZ * C_SZ);
    float* R = g_R + base;
    const float decay = get_decay(dlp);
    const float lg2d = log2f(decay);
    const int tid = threadIdx.x;

    __shared__ float P[64][65];
    __shared__ float Ta[16][64];
    __shared__ float Tb[16][64];
    __shared__ float Ws[8][256];    // V / S staging
    __shared__ float Qs[8][64];     // Dq-scaled Q staging

    // ---- Phase 1: P = mask-weighted Q K^T ----
    {
        const int tr = tid >> 4, tc = tid & 15;        // 16x16 grid, 4x4 each
        const int lrow = tid >> 2, lc4 = (tid & 3) * 4;
        float acc[4][4] = {};
        for (int k0 = 0; k0 < C_SZ; k0 += 16) {
            float4 qv = *(const float4*)&Q [(size_t)lrow * C_SZ + k0 + lc4];
            Ta[lc4 + 0][lrow] = qv.x; Ta[lc4 + 1][lrow] = qv.y;
            Ta[lc4 + 2][lrow] = qv.z; Ta[lc4 + 3][lrow] = qv.w;
            float4 kv = *(const float4*)&Kp[(size_t)lrow * C_SZ + k0 + lc4];
            Tb[lc4 + 0][lrow] = kv.x; Tb[lc4 + 1][lrow] = kv.y;
            Tb[lc4 + 2][lrow] = kv.z; Tb[lc4 + 3][lrow] = kv.w;
            __syncthreads();
#pragma unroll
            for (int kk = 0; kk < 16; kk++) {
                float a[4], bb[4];
#pragma unroll
                for (int i = 0; i < 4; i++) a[i] = Ta[kk][tr * 4 + i];
#pragma unroll
                for (int j = 0; j < 4; j++) bb[j] = Tb[kk][tc * 4 + j];
#pragma unroll
                for (int i = 0; i < 4; i++)
#pragma unroll
                    for (int j = 0; j < 4; j++)
                        acc[i][j] = fmaf(a[i], bb[j], acc[i][j]);
            }
            __syncthreads();
        }
#pragma unroll
        for (int ii = 0; ii < 4; ii++)
#pragma unroll
            for (int jj = 0; jj < 4; jj++) {
                int i = tr * 4 + ii, j = tc * 4 + jj;
                P[i][j] = (j > i) ? acc[ii][jj] * exp2f((float)(j - i - 1) * lg2d) : 0.0f;
            }
    }
    __syncthreads();

    // ---- Phase 2: R = P @ V + (Dq*Q) @ S ----
    {
        const int tr = tid >> 5, tc = tid & 31;        // 8x32 grid, 8x8 each
        const int lr = tid >> 5, lc8 = (tid & 31) * 8;
        float acc[8][8] = {};
        // P @ V  (K-dim = 64)
        for (int k0 = 0; k0 < L_SZ; k0 += 8) {
            *(float4*)&Ws[lr][lc8]     = *(const float4*)&Vp[(size_t)(k0 + lr) * C_SZ + lc8];
            *(float4*)&Ws[lr][lc8 + 4] = *(const float4*)&Vp[(size_t)(k0 + lr) * C_SZ + lc8 + 4];
            __syncthreads();
#pragma unroll
            for (int kk = 0; kk < 8; kk++) {
                float a[8], bb[8];
#pragma unroll
                for (int i = 0; i < 8; i++) a[i] = P[tr * 8 + i][k0 + kk];
#pragma unroll
                for (int j = 0; j < 8; j++) bb[j] = Ws[kk][tc * 8 + j];
#pragma unroll
                for (int i = 0; i < 8; i++)
#pragma unroll
                    for (int j = 0; j < 8; j++)
                        acc[i][j] = fmaf(a[i], bb[j], acc[i][j]);
            }
            __syncthreads();
        }
        // (Dq*Q) @ S  (K-dim = 256)
        for (int k0 = 0; k0 < C_SZ; k0 += 8) {
            if (tid < 128) {
                int row = tid >> 1, c4 = (tid & 1) * 4;
                float dq = exp2f((float)(63 - row) * lg2d);
                float4 qv = *(const float4*)&Q[(size_t)row * C_SZ + k0 + c4];
                Qs[c4 + 0][row] = qv.x * dq; Qs[c4 + 1][row] = qv.y * dq;
                Qs[c4 + 2][row] = qv.z * dq; Qs[c4 + 3][row] = qv.w * dq;
            }
            *(float4*)&Ws[lr][lc8]     = *(const float4*)&S[(size_t)(k0 + lr) * C_SZ + lc8];
            *(float4*)&Ws[lr][lc8 + 4] = *(const float4*)&S[(size_t)(k0 + lr) * C_SZ + lc8 + 4];
            __syncthreads();
#pragma unroll
            for (int kk = 0; kk < 8; kk++) {
                float a[8], bb[8];
#pragma unroll
                for (int i = 0; i < 8; i++) a[i] = Qs[kk][tr * 8 + i];
#pragma unroll
                for (int j = 0; j < 8; j++) bb[j] = Ws[kk][tc * 8 + j];
#pragma unroll
                for (int i = 0; i < 8; i++)
#pragma unroll
                    for (int j = 0; j < 8; j++)
                        acc[i][j] = fmaf(a[i], bb[j], acc[i][j]);
            }
            __syncthreads();
        }
#pragma unroll
        for (int i = 0; i < 8; i++) {
            float* Rp = R + (size_t)(tr * 8 + i) * C_SZ + tc * 8;
#pragma unroll
            for (int j = 0; j < 8; j += 4)
                *(float4*)(Rp + j) = make_float4(acc[i][j], acc[i][j + 1],
                                                 acc[i][j + 2], acc[i][j + 3]);
        }
    }
}

// ===========================================================================
extern "C" void kernel_launch(void* const* d_in, const int* in_sizes, int n_in,
                              void* d_out, int out_size)
{
    const float* x     = (const float*)d_in[0];
    const float* basis = (const float*)d_in[1];
    const float* qc    = (const float*)d_in[2];
    const float* kc    = (const float*)d_in[3];
    const float* vc    = (const float*)d_in[4];
    const float* oc    = (const float*)d_in[5];
    const float* dl    = (const float*)d_in[6];
    const float* os    = (const float*)d_in[7];
    float* out = (float*)d_out;

    float *pW, *pQKV, *pR;
    cudaGetSymbolAddress((void**)&pW,   g_W);
    cudaGetSymbolAddress((void**)&pQKV, g_QKV);
    cudaGetSymbolAddress((void**)&pR,   g_R);

    // 1. Weight build: W[z] = basis @ coeffs[z]^T   [1024,256]
    sgemm_nt<<<dim3(2, 8, 4), 256>>>(basis, qc, kc, vc, oc, pW,
                                     1024, 256, 256, (size_t)1024 * 256, nullptr);
    // 2. QKV projections: QKV[z] = x @ W[z]   [16384,256]
    sgemm_nn<<<dim3(2, 128, 3), 256>>>(x, pW, pQKV, 16384, 256, 1024,
                                       (size_t)1024 * 256, (size_t)16384 * 256);
    // 3. Per-chunk decayed KV sums
    chunk_kv_kernel<<<dim3(2, 2, B_SZ * NCH), 256>>>(dl);
    // 4. Backward state scan (in place)
    scan_kernel<<<dim3(256, B_SZ), 256>>>(dl);
    // 5. Per-chunk attention -> retrieved
    attn_kernel<<<dim3(NCH, B_SZ), 256>>>(dl);
    // 6. Output projection: out = R @ Wo^T * out_scale   [16384,1024]
    const float* Wo = pW + 3 * (size_t)1024 * 256;
    sgemm_nt<<<dim3(8, 128, 1), 256>>>(pR, Wo, Wo, Wo, Wo, out,
                                       16384, 1024, 256, 0, os);
}

// round 2
// speedup vs baseline: 1.0542x; 1.0542x over previous
#include <cuda_runtime.h>
#include <math.h>

// Problem constants
#define B_SZ 4
#define T_SZ 4096
#define V_SZ 1024
#define C_SZ 256
#define L_SZ 64                 // chunk length
#define NCH  64                 // chunks per batch (T/L)
#define BT   (B_SZ * T_SZ)      // 16384

typedef unsigned long long ull;

// ---------------- scratch (static __device__ arrays; no runtime alloc) -----
__device__ float g_W  [4 * V_SZ * C_SZ];                    // 4 MB  (Wq,Wk,Wv,Wo)
__device__ float g_QKV[3 * BT * C_SZ];                      // 48 MB (Q,K,V)
__device__ float g_AS [B_SZ * NCH * C_SZ * C_SZ];           // 64 MB (A_c, then states in-place)
__device__ float g_R  [BT * C_SZ];                          // 16 MB (retrieved)

__device__ __forceinline__ float get_decay(const float* dl) {
    return 1.0f / (1.0f + expf(-dl[0]));
}

// ---- packed fp32x2 helpers (sm_100+: FFMA2 — 2 exact fp32 FMAs per issue) --
__device__ __forceinline__ ull pack2(float x) {
    ull r;
    asm("mov.b64 %0, {%1, %1};" : "=l"(r) : "f"(x));
    return r;
}
__device__ __forceinline__ void ffma2(ull& c, ull a, ull b) {
    asm("fma.rn.f32x2 %0, %1, %2, %0;" : "+l"(c) : "l"(a), "l"(b));
}

// ===========================================================================
// 128x128x8 SGEMM, C = A[M,K] @ B[K,N]  ("nn"), double-buffered, f32x2 core.
// blockIdx.z selects B/C slab via strides (used for the 3 QKV projections).
// ===========================================================================
__global__ void __launch_bounds__(256) sgemm_nn(
    const float* __restrict__ A, const float* __restrict__ Bbase,
    float* __restrict__ Cbase, int M, int N, int K, size_t sB, size_t sC)
{
    const float* B = Bbase + (size_t)blockIdx.z * sB;
    float* C = Cbase + (size_t)blockIdx.z * sC;
    __shared__ __align__(16) float As[2][8][128];
    __shared__ __align__(16) float Bs[2][8][128];
    const int tid = threadIdx.x;
    const int m0 = blockIdx.y * 128, n0 = blockIdx.x * 128;
    const int tr = tid >> 4, tc = tid & 15;          // 16x16 thread grid, 8x8 each
    const int ar = tid >> 1, ac = (tid & 1) * 4;     // A tile load
    const int br = tid >> 5, bc = (tid & 31) * 4;    // B tile load
    ull acc[8][4] = {};
    const float* Aptr = A + (size_t)(m0 + ar) * K + ac;
    const float* Bptr = B + (size_t)br * N + n0 + bc;

    // prologue: stage k0 = 0
    {
        float4 av = *(const float4*)(Aptr);
        As[0][ac + 0][ar] = av.x; As[0][ac + 1][ar] = av.y;
        As[0][ac + 2][ar] = av.z; As[0][ac + 3][ar] = av.w;
        *(float4*)&Bs[0][br][bc] = *(const float4*)(Bptr);
    }
    __syncthreads();

    int buf = 0;
    for (int k0 = 0; k0 < K; k0 += 8) {
        const bool more = (k0 + 8 < K);
        float4 avn, bvn;
        if (more) {
            avn = *(const float4*)(Aptr + k0 + 8);
            bvn = *(const float4*)(Bptr + (size_t)(k0 + 8) * N);
        }
#pragma unroll
        for (int kk = 0; kk < 8; kk++) {
            const ull* bp = (const ull*)&Bs[buf][kk][tc * 8];
            ull b0 = bp[0], b1 = bp[1], b2 = bp[2], b3 = bp[3];
            const float* ap = &As[buf][kk][tr * 8];
#pragma unroll
            for (int i = 0; i < 8; i++) {
                ull a2 = pack2(ap[i]);
                ffma2(acc[i][0], a2, b0); ffma2(acc[i][1], a2, b1);
                ffma2(acc[i][2], a2, b2); ffma2(acc[i][3], a2, b3);
            }
        }
        if (more) {
            As[buf ^ 1][ac + 0][ar] = avn.x; As[buf ^ 1][ac + 1][ar] = avn.y;
            As[buf ^ 1][ac + 2][ar] = avn.z; As[buf ^ 1][ac + 3][ar] = avn.w;
            *(float4*)&Bs[buf ^ 1][br][bc] = bvn;
            __syncthreads();
            buf ^= 1;
        }
    }
#pragma unroll
    for (int i = 0; i < 8; i++) {
        float* Cp = C + (size_t)(m0 + tr * 8 + i) * N + n0 + tc * 8;
        float2 p0 = *(float2*)&acc[i][0], p1 = *(float2*)&acc[i][1];
        float2 p2 = *(float2*)&acc[i][2], p3 = *(float2*)&acc[i][3];
        *(float4*)(Cp)     = make_float4(p0.x, p0.y, p1.x, p1.y);
        *(float4*)(Cp + 4) = make_float4(p2.x, p2.y, p3.x, p3.y);
    }
}

// ===========================================================================
// 128x128x8 SGEMM, C = A[M,K] @ B[N,K]^T ("nt"), double-buffered, f32x2 core.
// blockIdx.z selects among 4 B pointers. Optional device-scalar scale.
// ===========================================================================
__global__ void __launch_bounds__(256) sgemm_nt(
    const float* __restrict__ A,
    const float* __restrict__ B0, const float* __restrict__ B1,
    const float* __restrict__ B2, const float* __restrict__ B3,
    float* __restrict__ Cbase, int M, int N, int K, size_t sC,
    const float* __restrict__ scale_ptr)
{
    const float* B = (blockIdx.z == 0) ? B0 : (blockIdx.z == 1) ? B1
                   : (blockIdx.z == 2) ? B2 : B3;
    float* C = Cbase + (size_t)blockIdx.z * sC;
    __shared__ __align__(16) float As[2][8][128];
    __shared__ __align__(16) float Bs[2][8][128];
    const int tid = threadIdx.x;
    const int m0 = blockIdx.y * 128, n0 = blockIdx.x * 128;
    const int tr = tid >> 4, tc = tid & 15;
    const int ar = tid >> 1, ac = (tid & 1) * 4;
    ull acc[8][4] = {};
    const float* Aptr = A + (size_t)(m0 + ar) * K + ac;
    const float* Bptr = B + (size_t)(n0 + ar) * K + ac;  // B rows are N dim

    {
        float4 av = *(const float4*)(Aptr);
        As[0][ac + 0][ar] = av.x; As[0][ac + 1][ar] = av.y;
        As[0][ac + 2][ar] = av.z; As[0][ac + 3][ar] = av.w;
        float4 bv = *(const float4*)(Bptr);
        Bs[0][ac + 0][ar] = bv.x; Bs[0][ac + 1][ar] = bv.y;
        Bs[0][ac + 2][ar] = bv.z; Bs[0][ac + 3][ar] = bv.w;
    }
    __syncthreads();

    int buf = 0;
    for (int k0 = 0; k0 < K; k0 += 8) {
        const bool more = (k0 + 8 < K);
        float4 avn, bvn;
        if (more) {
            avn = *(const float4*)(Aptr + k0 + 8);
            bvn = *(const float4*)(Bptr + k0 + 8);
        }
#pragma unroll
        for (int kk = 0; kk < 8; kk++) {
            const ull* bp = (const ull*)&Bs[buf][kk][tc * 8];
            ull b0 = bp[0], b1 = bp[1], b2 = bp[2], b3 = bp[3];
            const float* ap = &As[buf][kk][tr * 8];
#pragma unroll
            for (int i = 0; i < 8; i++) {
                ull a2 = pack2(ap[i]);
                ffma2(acc[i][0], a2, b0); ffma2(acc[i][1], a2, b1);
                ffma2(acc[i][2], a2, b2); ffma2(acc[i][3], a2, b3);
            }
        }
        if (more) {
            As[buf ^ 1][ac + 0][ar] = avn.x; As[buf ^ 1][ac + 1][ar] = avn.y;
            As[buf ^ 1][ac + 2][ar] = avn.z; As[buf ^ 1][ac + 3][ar] = avn.w;
            Bs[buf ^ 1][ac + 0][ar] = bvn.x; Bs[buf ^ 1][ac + 1][ar] = bvn.y;
            Bs[buf ^ 1][ac + 2][ar] = bvn.z; Bs[buf ^ 1][ac + 3][ar] = bvn.w;
            __syncthreads();
            buf ^= 1;
        }
    }
    const float alpha = scale_ptr ? scale_ptr[0] : 1.0f;
#pragma unroll
    for (int i = 0; i < 8; i++) {
        float* Cp = C + (size_t)(m0 + tr * 8 + i) * N + n0 + tc * 8;
        float2 p0 = *(float2*)&acc[i][0], p1 = *(float2*)&acc[i][1];
        float2 p2 = *(float2*)&acc[i][2], p3 = *(float2*)&acc[i][3];
        *(float4*)(Cp)     = make_float4(p0.x * alpha, p0.y * alpha, p1.x * alpha, p1.y * alpha);
        *(float4*)(Cp + 4) = make_float4(p2.x * alpha, p2.y * alpha, p3.x * alpha, p3.y * alpha);
    }
}

// ===========================================================================
// Per-chunk decayed KV outer-product sums:
//   A_c[c1,c2] = sum_{r<64} decay^r * K[cL+r,c1] * V[cL+r,c2]   (256x256)
// grid (2,2, B*NCH), 256 threads, 128x128 tile, f32x2 core.
// ===========================================================================
__global__ void __launch_bounds__(256) chunk_kv_kernel(const float* __restrict__ dlp)
{
    const int z = blockIdx.z;
    const int b = z >> 6, c = z & 63;
    const size_t rowbase = ((size_t)b * T_SZ + (size_t)c * L_SZ) * C_SZ;
    const float* Kp = g_QKV + (size_t)BT * C_SZ + rowbase;
    const float* Vp = g_QKV + 2 * (size_t)BT * C_SZ + rowbase;
    float* Cp = g_AS + (size_t)z * C_SZ * C_SZ;
    const float decay = get_decay(dlp);
    const float lg2d = log2f(decay);

    __shared__ __align__(16) float As[8][128];
    __shared__ __align__(16) float Bs[8][128];
    const int tid = threadIdx.x;
    const int m0 = blockIdx.y * 128, n0 = blockIdx.x * 128;
    const int tr = tid >> 4, tc = tid & 15;
    const int lr = tid >> 5, lc = (tid & 31) * 4;
    ull acc[8][4] = {};
    for (int k0 = 0; k0 < L_SZ; k0 += 8) {
        const float sc = exp2f((float)(k0 + lr) * lg2d);   // decay^r
        float4 av = *(const float4*)&Kp[(size_t)(k0 + lr) * C_SZ + m0 + lc];
        av.x *= sc; av.y *= sc; av.z *= sc; av.w *= sc;
        *(float4*)&As[lr][lc] = av;
        *(float4*)&Bs[lr][lc] = *(const float4*)&Vp[(size_t)(k0 + lr) * C_SZ + n0 + lc];
        __syncthreads();
#pragma unroll
        for (int kk = 0; kk < 8; kk++) {
            const ull* bp = (const ull*)&Bs[kk][tc * 8];
            ull b0 = bp[0], b1 = bp[1], b2 = bp[2], b3 = bp[3];
            const float* ap = &As[kk][tr * 8];
#pragma unroll
            for (int i = 0; i < 8; i++) {
                ull a2 = pack2(ap[i]);
                ffma2(acc[i][0], a2, b0); ffma2(acc[i][1], a2, b1);
                ffma2(acc[i][2], a2, b2); ffma2(acc[i][3], a2, b3);
            }
        }
        __syncthreads();
    }
#pragma unroll
    for (int i = 0; i < 8; i++) {
        float* Op = Cp + (size_t)(m0 + tr * 8 + i) * C_SZ + n0 + tc * 8;
        float2 p0 = *(float2*)&acc[i][0], p1 = *(float2*)&acc[i][1];
        float2 p2 = *(float2*)&acc[i][2], p3 = *(float2*)&acc[i][3];
        *(float4*)(Op)     = make_float4(p0.x, p0.y, p1.x, p1.y);
        *(float4*)(Op + 4) = make_float4(p2.x, p2.y, p3.x, p3.y);
    }
}

// ===========================================================================
// Backward state scan over chunks (in-place on g_AS):
//   run = 0; for c = NCH-1..0: { S_used[c] = run; run = A[c] + decay^L * run; }
// ===========================================================================
__global__ void scan_kernel(const float* __restrict__ dlp)
{
    const int e = blockIdx.x * blockDim.x + threadIdx.x;   // 0..65535
    const int b = blockIdx.y;
    const float decay = get_decay(dlp);
    const float dL = exp2f((float)L_SZ * log2f(decay));    // decay^64
    float run = 0.0f;
    float* base = g_AS + (size_t)b * NCH * (C_SZ * C_SZ) + e;
    for (int c = NCH - 1; c >= 0; c--) {
        float* p = base + (size_t)c * (C_SZ * C_SZ);
        float v = *p;
        *p = run;
        run = fmaf(dL, run, v);
    }
}

// ===========================================================================
// Per-chunk attention:
//   P[i,j] = (j>i) ? decay^(j-i-1) * (q_i . k_j) : 0        (intra, 64x64)
//   R[i,:] = P @ V_c  +  decay^(63-i) * (q_i @ S_c)          (64x256)
// grid (NCH, B), 256 threads.
// ===========================================================================
__global__ void __launch_bounds__(256) attn_kernel(const float* __restrict__ dlp)
{
    const int c = blockIdx.x, b = blockIdx.y;
    const size_t base = ((size_t)b * T_SZ + (size_t)c * L_SZ) * C_SZ;
    const float* Q  = g_QKV + base;
    const float* Kp = g_QKV + (size_t)BT * C_SZ + base;
    const float* Vp = g_QKV + 2 * (size_t)BT * C_SZ + base;
    const float* S  = g_AS + ((size_t)(b * NCH + c)) * (C_SZ * C_SZ);
    float* R = g_R + base;
    const float decay = get_decay(dlp);
    const float lg2d = log2f(decay);
    const int tid = threadIdx.x;

    __shared__ __align__(16) float P[64][66];
    __shared__ __align__(16) float Ta[16][64];
    __shared__ __align__(16) float Tb[16][64];
    __shared__ __align__(16) float Ws[8][256];    // V / S staging
    __shared__ __align__(16) float Qs[8][64];     // Dq-scaled Q staging

    // ---- Phase 1: P = mask-weighted Q K^T ----
    {
        const int tr = tid >> 4, tc = tid & 15;        // 16x16 grid, 4x4 each
        const int lrow = tid >> 2, lc4 = (tid & 3) * 4;
        ull acc[4][2] = {};
        for (int k0 = 0; k0 < C_SZ; k0 += 16) {
            float4 qv = *(const float4*)&Q [(size_t)lrow * C_SZ + k0 + lc4];
            Ta[lc4 + 0][lrow] = qv.x; Ta[lc4 + 1][lrow] = qv.y;
            Ta[lc4 + 2][lrow] = qv.z; Ta[lc4 + 3][lrow] = qv.w;
            float4 kv = *(const float4*)&Kp[(size_t)lrow * C_SZ + k0 + lc4];
            Tb[lc4 + 0][lrow] = kv.x; Tb[lc4 + 1][lrow] = kv.y;
            Tb[lc4 + 2][lrow] = kv.z; Tb[lc4 + 3][lrow] = kv.w;
            __syncthreads();
#pragma unroll
            for (int kk = 0; kk < 16; kk++) {
                const ull* bp = (const ull*)&Tb[kk][tc * 4];
                ull b0 = bp[0], b1 = bp[1];
                const float* ap = &Ta[kk][tr * 4];
#pragma unroll
                for (int i = 0; i < 4; i++) {
                    ull a2 = pack2(ap[i]);
                    ffma2(acc[i][0], a2, b0); ffma2(acc[i][1], a2, b1);
                }
            }
            __syncthreads();
        }
#pragma unroll
        for (int ii = 0; ii < 4; ii++) {
            const float2 q0 = *(float2*)&acc[ii][0];
            const float2 q1 = *(float2*)&acc[ii][1];
            float vv[4] = {q0.x, q0.y, q1.x, q1.y};
#pragma unroll
            for (int jj = 0; jj < 4; jj++) {
                int i = tr * 4 + ii, j = tc * 4 + jj;
                P[i][j] = (j > i) ? vv[jj] * exp2f((float)(j - i - 1) * lg2d) : 0.0f;
            }
        }
    }
    __syncthreads();

    // ---- Phase 2: R = P @ V + (Dq*Q) @ S ----
    {
        const int tr = tid >> 5, tc = tid & 31;        // 8x32 grid, 8x8 each
        const int lr = tid >> 5, lc8 = (tid & 31) * 8;
        ull acc[8][4] = {};
        // P @ V  (K-dim = 64)
        for (int k0 = 0; k0 < L_SZ; k0 += 8) {
            *(float4*)&Ws[lr][lc8]     = *(const float4*)&Vp[(size_t)(k0 + lr) * C_SZ + lc8];
            *(float4*)&Ws[lr][lc8 + 4] = *(const float4*)&Vp[(size_t)(k0 + lr) * C_SZ + lc8 + 4];
            __syncthreads();
#pragma unroll
            for (int kk = 0; kk < 8; kk++) {
                const ull* bp = (const ull*)&Ws[kk][tc * 8];
                ull b0 = bp[0], b1 = bp[1], b2 = bp[2], b3 = bp[3];
#pragma unroll
                for (int i = 0; i < 8; i++) {
                    ull a2 = pack2(P[tr * 8 + i][k0 + kk]);
                    ffma2(acc[i][0], a2, b0); ffma2(acc[i][1], a2, b1);
                    ffma2(acc[i][2], a2, b2); ffma2(acc[i][3], a2, b3);
                }
            }
            __syncthreads();
        }
        // (Dq*Q) @ S  (K-dim = 256)
        for (int k0 = 0; k0 < C_SZ; k0 += 8) {
            if (tid < 128) {
                int row = tid >> 1, c4 = (tid & 1) * 4;
                float dq = exp2f((float)(63 - row) * lg2d);
                float4 qv = *(const float4*)&Q[(size_t)row * C_SZ + k0 + c4];
                Qs[c4 + 0][row] = qv.x * dq; Qs[c4 + 1][row] = qv.y * dq;
                Qs[c4 + 2][row] = qv.z * dq; Qs[c4 + 3][row] = qv.w * dq;
            }
            *(float4*)&Ws[lr][lc8]     = *(const float4*)&S[(size_t)(k0 + lr) * C_SZ + lc8];
            *(float4*)&Ws[lr][lc8 + 4] = *(const float4*)&S[(size_t)(k0 + lr) * C_SZ + lc8 + 4];
            __syncthreads();
#pragma unroll
            for (int kk = 0; kk < 8; kk++) {
                const ull* bp = (const ull*)&Ws[kk][tc * 8];
                ull b0 = bp[0], b1 = bp[1], b2 = bp[2], b3 = bp[3];
                const float* ap = &Qs[kk][tr * 8];
#pragma unroll
                for (int i = 0; i < 8; i++) {
                    ull a2 = pack2(ap[i]);
                    ffma2(acc[i][0], a2, b0); ffma2(acc[i][1], a2, b1);
                    ffma2(acc[i][2], a2, b2); ffma2(acc[i][3], a2, b3);
                }
            }
            __syncthreads();
        }
#pragma unroll
        for (int i = 0; i < 8; i++) {
            float* Rp = R + (size_t)(tr * 8 + i) * C_SZ + tc * 8;
            float2 p0 = *(float2*)&acc[i][0], p1 = *(float2*)&acc[i][1];
            float2 p2 = *(float2*)&acc[i][2], p3 = *(float2*)&acc[i][3];
            *(float4*)(Rp)     = make_float4(p0.x, p0.y, p1.x, p1.y);
            *(float4*)(Rp + 4) = make_float4(p2.x, p2.y, p3.x, p3.y);
        }
    }
}

// ===========================================================================
extern "C" void kernel_launch(void* const* d_in, const int* in_sizes, int n_in,
                              void* d_out, int out_size)
{
    const float* x     = (const float*)d_in[0];
    const float* basis = (const float*)d_in[1];
    const float* qc    = (const float*)d_in[2];
    const float* kc    = (const float*)d_in[3];
    const float* vc    = (const float*)d_in[4];
    const float* oc    = (const float*)d_in[5];
    const float* dl    = (const float*)d_in[6];
    const float* os    = (const float*)d_in[7];
    float* out = (float*)d_out;

    float *pW, *pQKV, *pR;
    cudaGetSymbolAddress((void**)&pW,   g_W);
    cudaGetSymbolAddress((void**)&pQKV, g_QKV);
    cudaGetSymbolAddress((void**)&pR,   g_R);

    // 1. Weight build: W[z] = basis @ coeffs[z]^T   [1024,256]
    sgemm_nt<<<dim3(2, 8, 4), 256>>>(basis, qc, kc, vc, oc, pW,
                                     1024, 256, 256, (size_t)1024 * 256, nullptr);
    // 2. QKV projections: QKV[z] = x @ W[z]   [16384,256]
    sgemm_nn<<<dim3(2, 128, 3), 256>>>(x, pW, pQKV, 16384, 256, 1024,
                                       (size_t)1024 * 256, (size_t)16384 * 256);
    // 3. Per-chunk decayed KV sums
    chunk_kv_kernel<<<dim3(2, 2, B_SZ * NCH), 256>>>(dl);
    // 4. Backward state scan (in place)
    scan_kernel<<<dim3(256, B_SZ), 256>>>(dl);
    // 5. Per-chunk attention -> retrieved
    attn_kernel<<<dim3(NCH, B_SZ), 256>>>(dl);
    // 6. Output projection: out = R @ Wo^T * out_scale   [16384,1024]
    const float* Wo = pW + 3 * (size_t)1024 * 256;
    sgemm_nt<<<dim3(8, 128, 1), 256>>>(pR, Wo, Wo, Wo, Wo, out,
                                       16384, 1024, 256, 0, os);
}

// round 4
// speedup vs baseline: 1.5317x; 1.4530x over previous
#include <cuda_runtime.h>
#include <cuda_bf16.h>
#include <math.h>
#include <stdint.h>

// Problem constants
#define B_SZ 4
#define T_SZ 4096
#define V_SZ 1024
#define C_SZ 256
#define L_SZ 64                 // chunk length
#define NCH  64                 // chunks per batch (T/L)
#define BT   (B_SZ * T_SZ)      // 16384

typedef unsigned long long ull;

// ---------------- scratch (static __device__ arrays; no runtime alloc) -----
__device__ float g_Wt [3 * C_SZ * V_SZ];                    // Wt_q/k/v [256,1024] (K-major over V)
__device__ float g_Wo [V_SZ * C_SZ];                        // Wo [1024,256] (K-major over C)
__device__ float g_QKV[3 * BT * C_SZ];                      // 48 MB (Q,K,V)
__device__ float g_AS [B_SZ * NCH * C_SZ * C_SZ];           // 64 MB (A_c, then states in-place)
__device__ float g_R  [BT * C_SZ];                          // 16 MB (retrieved)
// bf16 split operands
__device__ __nv_bfloat16 g_xh [BT * V_SZ];
__device__ __nv_bfloat16 g_xl [BT * V_SZ];
__device__ __nv_bfloat16 g_Wth[3 * C_SZ * V_SZ];
__device__ __nv_bfloat16 g_Wtl[3 * C_SZ * V_SZ];
__device__ __nv_bfloat16 g_Woh[V_SZ * C_SZ];
__device__ __nv_bfloat16 g_Wol[V_SZ * C_SZ];
__device__ __nv_bfloat16 g_Rh [BT * C_SZ];
__device__ __nv_bfloat16 g_Rl [BT * C_SZ];

__device__ __forceinline__ float get_decay(const float* dl) {
    return 1.0f / (1.0f + expf(-dl[0]));
}

// ---- packed fp32x2 helpers (FFMA kernels) ---------------------------------
__device__ __forceinline__ ull pack2(float x) {
    ull r;
    asm("mov.b64 %0, {%1, %1};" : "=l"(r) : "f"(x));
    return r;
}
__device__ __forceinline__ void ffma2(ull& c, ull a, ull b) {
    asm("fma.rn.f32x2 %0, %1, %2, %0;" : "+l"(c) : "l"(a), "l"(b));
}

__device__ __forceinline__ uint32_t cvta_shared(const void* p) {
    uint32_t a;
    asm("{ .reg .u64 t; cvta.to.shared.u64 t, %1; cvt.u32.u64 %0, t; }"
        : "=r"(a) : "l"(p));
    return a;
}

// ---- mma.sync helpers (sm_80+, works on compute_103 target) ---------------
__device__ __forceinline__ void ldsm_x4(uint32_t a, uint32_t& r0, uint32_t& r1,
                                        uint32_t& r2, uint32_t& r3) {
    asm volatile("ldmatrix.sync.aligned.m8n8.x4.shared.b16 {%0,%1,%2,%3}, [%4];"
                 : "=r"(r0), "=r"(r1), "=r"(r2), "=r"(r3) : "r"(a));
}
__device__ __forceinline__ void mma_bf16(float* d, const uint32_t* a, const uint32_t* b) {
    asm volatile("mma.sync.aligned.m16n8k16.row.col.f32.bf16.bf16.f32 "
                 "{%0,%1,%2,%3}, {%4,%5,%6,%7}, {%8,%9}, {%0,%1,%2,%3};"
                 : "+f"(d[0]), "+f"(d[1]), "+f"(d[2]), "+f"(d[3])
                 : "r"(a[0]), "r"(a[1]), "r"(a[2]), "r"(a[3]),
                   "r"(b[0]), "r"(b[1]));
}

#define LDA 24   // smem row stride in bf16 (48 B) — conflict-free ldmatrix

// ===========================================================================
// Tensor-core split-bf16 GEMM: C[M,N] = (Ah+Al)[M,K] @ (Bh+Bl)[N,K]^T
// D = AhBh + AhBl + AlBh, fp32 accum. Block 128x128, 8 warps (32x64 each),
// K-step 16, register-prefetch pipeline. grid=(N/128, M/128, z).
// ===========================================================================
__global__ void __launch_bounds__(256) mma_gemm_nt(
    const __nv_bfloat16* __restrict__ Ahb, const __nv_bfloat16* __restrict__ Alb,
    const __nv_bfloat16* __restrict__ Bhb, const __nv_bfloat16* __restrict__ Blb,
    float* __restrict__ Cbase, int K, size_t sB, size_t sC, int ldC,
    const float* __restrict__ scale_ptr)
{
    __shared__ __align__(16) __nv_bfloat16 sm[4 * 128 * LDA];

    const int tid = threadIdx.x, lane = tid & 31, wid = tid >> 5;
    const int m0 = blockIdx.y * 128, n0 = blockIdx.x * 128;
    const __nv_bfloat16* Bh = Bhb + (size_t)blockIdx.z * sB;
    const __nv_bfloat16* Bl = Blb + (size_t)blockIdx.z * sB;
    float* C = Cbase + (size_t)blockIdx.z * sC;

    const int warp_m = wid >> 1;   // 0..3 (32 rows each)
    const int warp_n = wid & 1;    // 0..1 (64 cols each)

    // cooperative loaders: 2 threads per row, 8 bf16 (16 B) each
    const int lrow = tid >> 1, lcol = (tid & 1) * 8;
    const __nv_bfloat16* gAh = Ahb + (size_t)(m0 + lrow) * K + lcol;
    const __nv_bfloat16* gAl = Alb + (size_t)(m0 + lrow) * K + lcol;
    const __nv_bfloat16* gBh = Bh  + (size_t)(n0 + lrow) * K + lcol;
    const __nv_bfloat16* gBl = Bl  + (size_t)(n0 + lrow) * K + lcol;
    const int soff = lrow * LDA + lcol;

    __nv_bfloat16* sAh = sm;
    __nv_bfloat16* sAl = sm + 128 * LDA;
    __nv_bfloat16* sBh = sm + 2 * 128 * LDA;
    __nv_bfloat16* sBl = sm + 3 * 128 * LDA;

    // ldmatrix lane addressing
    const uint32_t sbase = cvta_shared(sm);
    const int r8 = lane & 7, midx = lane >> 3;
    // A x4: m0: rows+0 k0 | m1: rows+8 k0 | m2: rows+0 k8 | m3: rows+8 k8
    const uint32_t aoff = ((warp_m * 32 + (midx & 1) * 8 + r8) * LDA + (midx >> 1) * 8) * 2;
    // B x4: m0: n+0 k0 | m1: n+0 k8 | m2: n+8 k0 | m3: n+8 k8
    const uint32_t boff = ((warp_n * 64 + (midx >> 1) * 8 + r8) * LDA + (midx & 1) * 8) * 2;
    const uint32_t pAl_b = 128 * LDA * 2, pBh_b = 2 * 128 * LDA * 2, pBl_b = 3 * 128 * LDA * 2;

    float acc[2][8][4];
#pragma unroll
    for (int mt = 0; mt < 2; mt++)
#pragma unroll
        for (int nt = 0; nt < 8; nt++)
#pragma unroll
            for (int r = 0; r < 4; r++) acc[mt][nt][r] = 0.0f;

    const int NC = K >> 4;
    uint4 pA  = *(const uint4*)gAh;
    uint4 pAl = *(const uint4*)gAl;
    uint4 pB  = *(const uint4*)gBh;
    uint4 pBl = *(const uint4*)gBl;

    for (int i = 0; i < NC; i++) {
        *(uint4*)(sAh + soff) = pA;
        *(uint4*)(sAl + soff) = pAl;
        *(uint4*)(sBh + soff) = pB;
        *(uint4*)(sBl + soff) = pBl;
        __syncthreads();
        if (i + 1 < NC) {
            const int k = (i + 1) * 16;
            pA  = *(const uint4*)(gAh + k);
            pAl = *(const uint4*)(gAl + k);
            pB  = *(const uint4*)(gBh + k);
            pBl = *(const uint4*)(gBl + k);
        }
        uint32_t ah[2][4], al[2][4], bh[4][4], bl[4][4];
#pragma unroll
        for (int mt = 0; mt < 2; mt++) {
            const uint32_t d = aoff + mt * 16 * LDA * 2;
            ldsm_x4(sbase + d,         ah[mt][0], ah[mt][1], ah[mt][2], ah[mt][3]);
            ldsm_x4(sbase + pAl_b + d, al[mt][0], al[mt][1], al[mt][2], al[mt][3]);
        }
#pragma unroll
        for (int ng = 0; ng < 4; ng++) {
            const uint32_t d = boff + ng * 16 * LDA * 2;
            ldsm_x4(sbase + pBh_b + d, bh[ng][0], bh[ng][1], bh[ng][2], bh[ng][3]);
            ldsm_x4(sbase + pBl_b + d, bl[ng][0], bl[ng][1], bl[ng][2], bl[ng][3]);
        }
#pragma unroll
        for (int mt = 0; mt < 2; mt++)
#pragma unroll
            for (int nt = 0; nt < 8; nt++) {
                const uint32_t* bhp = &bh[nt >> 1][(nt & 1) * 2];
                const uint32_t* blp = &bl[nt >> 1][(nt & 1) * 2];
                mma_bf16(acc[mt][nt], ah[mt], bhp);
                mma_bf16(acc[mt][nt], ah[mt], blp);
                mma_bf16(acc[mt][nt], al[mt], bhp);
            }
        __syncthreads();
    }

    const float alpha = scale_ptr ? scale_ptr[0] : 1.0f;
    const int crow = lane >> 2, ccol = (lane & 3) * 2;
#pragma unroll
    for (int mt = 0; mt < 2; mt++)
#pragma unroll
        for (int nt = 0; nt < 8; nt++) {
            const int row = m0 + warp_m * 32 + mt * 16 + crow;
            const int col = n0 + warp_n * 64 + nt * 8 + ccol;
            float* p = C + (size_t)row * ldC + col;
            *(float2*)p = make_float2(acc[mt][nt][0] * alpha, acc[mt][nt][1] * alpha);
            *(float2*)(p + 8 * (size_t)ldC) =
                make_float2(acc[mt][nt][2] * alpha, acc[mt][nt][3] * alpha);
        }
}

// ===========================================================================
// fp32 -> (hi, lo) bf16 split, vectorized by 4
// ===========================================================================
__global__ void split_kernel(const float* __restrict__ s,
                             __nv_bfloat16* __restrict__ h,
                             __nv_bfloat16* __restrict__ l, int n4)
{
    int i = blockIdx.x * blockDim.x + threadIdx.x;
    if (i >= n4) return;
    float4 v = ((const float4*)s)[i];
    __nv_bfloat16 h0 = __float2bfloat16_rn(v.x), h1 = __float2bfloat16_rn(v.y);
    __nv_bfloat16 h2 = __float2bfloat16_rn(v.z), h3 = __float2bfloat16_rn(v.w);
    __nv_bfloat16 l0 = __float2bfloat16_rn(v.x - __bfloat162float(h0));
    __nv_bfloat16 l1 = __float2bfloat16_rn(v.y - __bfloat162float(h1));
    __nv_bfloat16 l2 = __float2bfloat16_rn(v.z - __bfloat162float(h2));
    __nv_bfloat16 l3 = __float2bfloat16_rn(v.w - __bfloat162float(h3));
    ((__nv_bfloat162*)h)[2 * i]     = __nv_bfloat162(h0, h1);
    ((__nv_bfloat162*)h)[2 * i + 1] = __nv_bfloat162(h2, h3);
    ((__nv_bfloat162*)l)[2 * i]     = __nv_bfloat162(l0, l1);
    ((__nv_bfloat162*)l)[2 * i + 1] = __nv_bfloat162(l2, l3);
}

// ===========================================================================
// 128x128x8 SGEMM, C = A[M,K] @ B[N,K]^T ("nt"), f32x2 core. Small weight
// builds only. blockIdx.z selects among 4 (A,B) pointer pairs.
// ===========================================================================
__global__ void __launch_bounds__(256) sgemm_nt(
    const float* __restrict__ A0, const float* __restrict__ A1,
    const float* __restrict__ A2, const float* __restrict__ A3,
    const float* __restrict__ B0, const float* __restrict__ B1,
    const float* __restrict__ B2, const float* __restrict__ B3,
    float* __restrict__ Cbase, int M, int N, int K, size_t sC)
{
    const float* A = (blockIdx.z == 0) ? A0 : (blockIdx.z == 1) ? A1
                   : (blockIdx.z == 2) ? A2 : A3;
    const float* B = (blockIdx.z == 0) ? B0 : (blockIdx.z == 1) ? B1
                   : (blockIdx.z == 2) ? B2 : B3;
    float* C = Cbase + (size_t)blockIdx.z * sC;
    __shared__ __align__(16) float As[8][128];
    __shared__ __align__(16) float Bs[8][128];
    const int tid = threadIdx.x;
    const int m0 = blockIdx.y * 128, n0 = blockIdx.x * 128;
    const int tr = tid >> 4, tc = tid & 15;
    const int ar = tid >> 1, ac = (tid & 1) * 4;
    ull acc[8][4] = {};
    const float* Aptr = A + (size_t)(m0 + ar) * K + ac;
    const float* Bptr = B + (size_t)(n0 + ar) * K + ac;
    for (int k0 = 0; k0 < K; k0 += 8) {
        float4 av = *(const float4*)(Aptr + k0);
        As[ac + 0][ar] = av.x; As[ac + 1][ar] = av.y;
        As[ac + 2][ar] = av.z; As[ac + 3][ar] = av.w;
        float4 bv = *(const float4*)(Bptr + k0);
        Bs[ac + 0][ar] = bv.x; Bs[ac + 1][ar] = bv.y;
        Bs[ac + 2][ar] = bv.z; Bs[ac + 3][ar] = bv.w;
        __syncthreads();
#pragma unroll
        for (int kk = 0; kk < 8; kk++) {
            const ull* bp = (const ull*)&Bs[kk][tc * 8];
            ull b0 = bp[0], b1 = bp[1], b2 = bp[2], b3 = bp[3];
            const float* ap = &As[kk][tr * 8];
#pragma unroll
            for (int i = 0; i < 8; i++) {
                ull a2 = pack2(ap[i]);
                ffma2(acc[i][0], a2, b0); ffma2(acc[i][1], a2, b1);
                ffma2(acc[i][2], a2, b2); ffma2(acc[i][3], a2, b3);
            }
        }
        __syncthreads();
    }
#pragma unroll
    for (int i = 0; i < 8; i++) {
        float* Cp = C + (size_t)(m0 + tr * 8 + i) * N + n0 + tc * 8;
        float2 p0 = *(float2*)&acc[i][0], p1 = *(float2*)&acc[i][1];
        float2 p2 = *(float2*)&acc[i][2], p3 = *(float2*)&acc[i][3];
        *(float4*)(Cp)     = make_float4(p0.x, p0.y, p1.x, p1.y);
        *(float4*)(Cp + 4) = make_float4(p2.x, p2.y, p3.x, p3.y);
    }
}

// ===========================================================================
// Per-chunk decayed KV outer-product sums (f32x2 core)
// ===========================================================================
__global__ void __launch_bounds__(256) chunk_kv_kernel(const float* __restrict__ dlp)
{
    const int z = blockIdx.z;
    const int b = z >> 6, c = z & 63;
    const size_t rowbase = ((size_t)b * T_SZ + (size_t)c * L_SZ) * C_SZ;
    const float* Kp = g_QKV + (size_t)BT * C_SZ + rowbase;
    const float* Vp = g_QKV + 2 * (size_t)BT * C_SZ + rowbase;
    float* Cp = g_AS + (size_t)z * C_SZ * C_SZ;
    const float decay = get_decay(dlp);
    const float lg2d = log2f(decay);

    __shared__ __align__(16) float As[8][128];
    __shared__ __align__(16) float Bs[8][128];
    const int tid = threadIdx.x;
    const int m0 = blockIdx.y * 128, n0 = blockIdx.x * 128;
    const int tr = tid >> 4, tc = tid & 15;
    const int lr = tid >> 5, lc = (tid & 31) * 4;
    ull acc[8][4] = {};
    for (int k0 = 0; k0 < L_SZ; k0 += 8) {
        const float sc = exp2f((float)(k0 + lr) * lg2d);
        float4 av = *(const float4*)&Kp[(size_t)(k0 + lr) * C_SZ + m0 + lc];
        av.x *= sc; av.y *= sc; av.z *= sc; av.w *= sc;
        *(float4*)&As[lr][lc] = av;
        *(float4*)&Bs[lr][lc] = *(const float4*)&Vp[(size_t)(k0 + lr) * C_SZ + n0 + lc];
        __syncthreads();
#pragma unroll
        for (int kk = 0; kk < 8; kk++) {
            const ull* bp = (const ull*)&Bs[kk][tc * 8];
            ull b0 = bp[0], b1 = bp[1], b2 = bp[2], b3 = bp[3];
            const float* ap = &As[kk][tr * 8];
#pragma unroll
            for (int i = 0; i < 8; i++) {
                ull a2 = pack2(ap[i]);
                ffma2(acc[i][0], a2, b0); ffma2(acc[i][1], a2, b1);
                ffma2(acc[i][2], a2, b2); ffma2(acc[i][3], a2, b3);
            }
        }
        __syncthreads();
    }
#pragma unroll
    for (int i = 0; i < 8; i++) {
        float* Op = Cp + (size_t)(m0 + tr * 8 + i) * C_SZ + n0 + tc * 8;
        float2 p0 = *(float2*)&acc[i][0], p1 = *(float2*)&acc[i][1];
        float2 p2 = *(float2*)&acc[i][2], p3 = *(float2*)&acc[i][3];
        *(float4*)(Op)     = make_float4(p0.x, p0.y, p1.x, p1.y);
        *(float4*)(Op + 4) = make_float4(p2.x, p2.y, p3.x, p3.y);
    }
}

// ===========================================================================
// Backward state scan over chunks (in-place on g_AS)
// ===========================================================================
__global__ void scan_kernel(const float* __restrict__ dlp)
{
    const int e = blockIdx.x * blockDim.x + threadIdx.x;
    const int b = blockIdx.y;
    const float decay = get_decay(dlp);
    const float dL = exp2f((float)L_SZ * log2f(decay));
    float run = 0.0f;
    float* base = g_AS + (size_t)b * NCH * (C_SZ * C_SZ) + e;
    for (int c = NCH - 1; c >= 0; c--) {
        float* p = base + (size_t)c * (C_SZ * C_SZ);
        float v = *p;
        *p = run;
        run = fmaf(dL, run, v);
    }
}

// ===========================================================================
// Per-chunk attention (f32x2 core)
// ===========================================================================
__global__ void __launch_bounds__(256) attn_kernel(const float* __restrict__ dlp)
{
    const int c = blockIdx.x, b = blockIdx.y;
    const size_t base = ((size_t)b * T_SZ + (size_t)c * L_SZ) * C_SZ;
    const float* Q  = g_QKV + base;
    const float* Kp = g_QKV + (size_t)BT * C_SZ + base;
    const float* Vp = g_QKV + 2 * (size_t)BT * C_SZ + base;
    const float* S  = g_AS + ((size_t)(b * NCH + c)) * (C_SZ * C_SZ);
    float* R = g_R + base;
    const float decay = get_decay(dlp);
    const float lg2d = log2f(decay);
    const int tid = threadIdx.x;

    __shared__ __align__(16) float P[64][66];
    __shared__ __align__(16) float Ta[16][64];
    __shared__ __align__(16) float Tb[16][64];
    __shared__ __align__(16) float Ws[8][256];
    __shared__ __align__(16) float Qs[8][64];

    // ---- Phase 1: P = mask-weighted Q K^T ----
    {
        const int tr = tid >> 4, tc = tid & 15;
        const int lrow = tid >> 2, lc4 = (tid & 3) * 4;
        ull acc[4][2] = {};
        for (int k0 = 0; k0 < C_SZ; k0 += 16) {
            float4 qv = *(const float4*)&Q [(size_t)lrow * C_SZ + k0 + lc4];
            Ta[lc4 + 0][lrow] = qv.x; Ta[lc4 + 1][lrow] = qv.y;
            Ta[lc4 + 2][lrow] = qv.z; Ta[lc4 + 3][lrow] = qv.w;
            float4 kv = *(const float4*)&Kp[(size_t)lrow * C_SZ + k0 + lc4];
            Tb[lc4 + 0][lrow] = kv.x; Tb[lc4 + 1][lrow] = kv.y;
            Tb[lc4 + 2][lrow] = kv.z; Tb[lc4 + 3][lrow] = kv.w;
            __syncthreads();
#pragma unroll
            for (int kk = 0; kk < 16; kk++) {
                const ull* bp = (const ull*)&Tb[kk][tc * 4];
                ull b0 = bp[0], b1 = bp[1];
                const float* ap = &Ta[kk][tr * 4];
#pragma unroll
                for (int i = 0; i < 4; i++) {
                    ull a2 = pack2(ap[i]);
                    ffma2(acc[i][0], a2, b0); ffma2(acc[i][1], a2, b1);
                }
            }
            __syncthreads();
        }
#pragma unroll
        for (int ii = 0; ii < 4; ii++) {
            const float2 q0 = *(float2*)&acc[ii][0];
            const float2 q1 = *(float2*)&acc[ii][1];
            float vv[4] = {q0.x, q0.y, q1.x, q1.y};
#pragma unroll
            for (int jj = 0; jj < 4; jj++) {
                int i = tr * 4 + ii, j = tc * 4 + jj;
                P[i][j] = (j > i) ? vv[jj] * exp2f((float)(j - i - 1) * lg2d) : 0.0f;
            }
        }
    }
    __syncthreads();

    // ---- Phase 2: R = P @ V + (Dq*Q) @ S ----
    {
        const int tr = tid >> 5, tc = tid & 31;
        const int lr = tid >> 5, lc8 = (tid & 31) * 8;
        ull acc[8][4] = {};
        for (int k0 = 0; k0 < L_SZ; k0 += 8) {
            *(float4*)&Ws[lr][lc8]     = *(const float4*)&Vp[(size_t)(k0 + lr) * C_SZ + lc8];
            *(float4*)&Ws[lr][lc8 + 4] = *(const float4*)&Vp[(size_t)(k0 + lr) * C_SZ + lc8 + 4];
            __syncthreads();
#pragma unroll
            for (int kk = 0; kk < 8; kk++) {
                const ull* bp = (const ull*)&Ws[kk][tc * 8];
                ull b0 = bp[0], b1 = bp[1], b2 = bp[2], b3 = bp[3];
#pragma unroll
                for (int i = 0; i < 8; i++) {
                    ull a2 = pack2(P[tr * 8 + i][k0 + kk]);
                    ffma2(acc[i][0], a2, b0); ffma2(acc[i][1], a2, b1);
                    ffma2(acc[i][2], a2, b2); ffma2(acc[i][3], a2, b3);
                }
            }
            __syncthreads();
        }
        for (int k0 = 0; k0 < C_SZ; k0 += 8) {
            if (tid < 128) {
                int row = tid >> 1, c4 = (tid & 1) * 4;
                float dq = exp2f((float)(63 - row) * lg2d);
                float4 qv = *(const float4*)&Q[(size_t)row * C_SZ + k0 + c4];
                Qs[c4 + 0][row] = qv.x * dq; Qs[c4 + 1][row] = qv.y * dq;
                Qs[c4 + 2][row] = qv.z * dq; Qs[c4 + 3][row] = qv.w * dq;
            }
            *(float4*)&Ws[lr][lc8]     = *(const float4*)&S[(size_t)(k0 + lr) * C_SZ + lc8];
            *(float4*)&Ws[lr][lc8 + 4] = *(const float4*)&S[(size_t)(k0 + lr) * C_SZ + lc8 + 4];
            __syncthreads();
#pragma unroll
            for (int kk = 0; kk < 8; kk++) {
                const ull* bp = (const ull*)&Ws[kk][tc * 8];
                ull b0 = bp[0], b1 = bp[1], b2 = bp[2], b3 = bp[3];
                const float* ap = &Qs[kk][tr * 8];
#pragma unroll
                for (int i = 0; i < 8; i++) {
                    ull a2 = pack2(ap[i]);
                    ffma2(acc[i][0], a2, b0); ffma2(acc[i][1], a2, b1);
                    ffma2(acc[i][2], a2, b2); ffma2(acc[i][3], a2, b3);
                }
            }
            __syncthreads();
        }
#pragma unroll
        for (int i = 0; i < 8; i++) {
            float* Rp = R + (size_t)(tr * 8 + i) * C_SZ + tc * 8;
            float2 p0 = *(float2*)&acc[i][0], p1 = *(float2*)&acc[i][1];
            float2 p2 = *(float2*)&acc[i][2], p3 = *(float2*)&acc[i][3];
            *(float4*)(Rp)     = make_float4(p0.x, p0.y, p1.x, p1.y);
            *(float4*)(Rp + 4) = make_float4(p2.x, p2.y, p3.x, p3.y);
        }
    }
}

// ===========================================================================
extern "C" void kernel_launch(void* const* d_in, const int* in_sizes, int n_in,
                              void* d_out, int out_size)
{
    const float* x     = (const float*)d_in[0];
    const float* basis = (const float*)d_in[1];
    const float* qc    = (const float*)d_in[2];
    const float* kc    = (const float*)d_in[3];
    const float* vc    = (const float*)d_in[4];
    const float* oc    = (const float*)d_in[5];
    const float* dl    = (const float*)d_in[6];
    const float* os    = (const float*)d_in[7];
    float* out = (float*)d_out;

    float *pWt, *pWo, *pR, *pQKV;
    __nv_bfloat16 *pxh, *pxl, *pWth, *pWtl, *pWoh, *pWol, *pRh, *pRl;
    cudaGetSymbolAddress((void**)&pWt,  g_Wt);
    cudaGetSymbolAddress((void**)&pWo,  g_Wo);
    cudaGetSymbolAddress((void**)&pR,   g_R);
    cudaGetSymbolAddress((void**)&pQKV, g_QKV);
    cudaGetSymbolAddress((void**)&pxh,  g_xh);
    cudaGetSymbolAddress((void**)&pxl,  g_xl);
    cudaGetSymbolAddress((void**)&pWth, g_Wth);
    cudaGetSymbolAddress((void**)&pWtl, g_Wtl);
    cudaGetSymbolAddress((void**)&pWoh, g_Woh);
    cudaGetSymbolAddress((void**)&pWol, g_Wol);
    cudaGetSymbolAddress((void**)&pRh,  g_Rh);
    cudaGetSymbolAddress((void**)&pRl,  g_Rl);

    // 1. Weight builds (fp32, small):
    //    Wt[z] = coeffs_z @ basis^T  [256,1024]  (K-major over V)
    sgemm_nt<<<dim3(8, 2, 3), 256>>>(qc, kc, vc, qc, basis, basis, basis, basis,
                                     pWt, 256, 1024, 256, (size_t)C_SZ * V_SZ);
    //    Wo = basis @ oc^T  [1024,256]  (K-major over C)
    sgemm_nt<<<dim3(2, 8, 1), 256>>>(basis, basis, basis, basis, oc, oc, oc, oc,
                                     pWo, 1024, 256, 256, 0);

    // 2. bf16 splits
    split_kernel<<<(BT * V_SZ / 4 + 255) / 256, 256>>>(x, pxh, pxl, BT * V_SZ / 4);
    split_kernel<<<(3 * C_SZ * V_SZ / 4 + 255) / 256, 256>>>(pWt, pWth, pWtl, 3 * C_SZ * V_SZ / 4);
    split_kernel<<<(V_SZ * C_SZ / 4 + 255) / 256, 256>>>(pWo, pWoh, pWol, V_SZ * C_SZ / 4);

    // 3. QKV projections on tensor cores: QKV[z] = x @ Wt[z]^T  [16384,256]
    mma_gemm_nt<<<dim3(2, 128, 3), 256>>>(
        pxh, pxl, pWth, pWtl, pQKV, V_SZ,
        (size_t)C_SZ * V_SZ, (size_t)BT * C_SZ, C_SZ, nullptr);

    // 4. Per-chunk decayed KV sums, state scan, per-chunk attention
    chunk_kv_kernel<<<dim3(2, 2, B_SZ * NCH), 256>>>(dl);
    scan_kernel<<<dim3(256, B_SZ), 256>>>(dl);
    attn_kernel<<<dim3(NCH, B_SZ), 256>>>(dl);

    // 5. Split retrieved, then output projection on tensor cores:
    //    out = R @ Wo^T * out_scale  [16384,1024]
    split_kernel<<<(BT * C_SZ / 4 + 255) / 256, 256>>>(pR, pRh, pRl, BT * C_SZ / 4);
    mma_gemm_nt<<<dim3(8, 128, 1), 256>>>(
        pRh, pRl, pWoh, pWol, out, C_SZ, 0, 0, V_SZ, os);
}

// round 6
// speedup vs baseline: 2.0089x; 1.3115x over previous
#include <cuda_runtime.h>
#include <cuda_fp16.h>
#include <math.h>
#include <stdint.h>

// Problem constants
#define B_SZ 4
#define T_SZ 4096
#define V_SZ 1024
#define C_SZ 256
#define L_SZ 64                 // chunk length
#define NCH  64                 // chunks per batch (T/V)
#define BT   (B_SZ * T_SZ)      // 16384

#define R_SCALE   0.00390625f   // 2^-8 pre-scale for R (fp16 range safety)
#define R_UNSCALE 256.0f

typedef unsigned long long ull;

// ---------------- scratch (static __device__ arrays; no runtime alloc) -----
__device__ float g_Wt [3 * C_SZ * V_SZ];                    // Wt_q/k/v [256,1024] (K-major over V)
__device__ float g_Wo [V_SZ * C_SZ];                        // Wo [1024,256] (K-major over C)
__device__ float g_QKV[3 * BT * C_SZ];                      // Q,K,V fp32
__device__ float g_AS [B_SZ * NCH * C_SZ * C_SZ];           // A_c, then states in-place
__device__ float g_R  [BT * C_SZ];                          // retrieved
// fp16 split operands (A gets hi+lo; B only hi — 2-term scheme)
__device__ __half g_xh [BT * V_SZ];
__device__ __half g_xl [BT * V_SZ];
__device__ __half g_Wth[3 * C_SZ * V_SZ];   // hi only (B operand)
__device__ __half g_Woh[V_SZ * C_SZ];       // hi only (B operand)
__device__ __half g_Rh [BT * C_SZ];
__device__ __half g_Rl [BT * C_SZ];
__device__ __half g_unused_l[3 * C_SZ * V_SZ];  // lo of Wt (written by shared split kernel)
__device__ __half g_unused_l2[V_SZ * C_SZ];     // lo of Wo

__device__ __forceinline__ float get_decay(const float* dl) {
    return 1.0f / (1.0f + expf(-dl[0]));
}

// ---- packed fp32x2 helpers (FFMA kernels) ---------------------------------
__device__ __forceinline__ ull pack2(float x) {
    ull r;
    asm("mov.b64 %0, {%1, %1};" : "=l"(r) : "f"(x));
    return r;
}
__device__ __forceinline__ void ffma2(ull& c, ull a, ull b) {
    asm("fma.rn.f32x2 %0, %1, %2, %0;" : "+l"(c) : "l"(a), "l"(b));
}

__device__ __forceinline__ uint32_t cvta_shared(const void* p) {
    uint32_t a;
    asm("{ .reg .u64 t; cvta.to.shared.u64 t, %1; cvt.u32.u64 %0, t; }"
        : "=r"(a) : "l"(p));
    return a;
}

// ---- mma.sync / ldmatrix / cp.async helpers (sm_80+ path) -----------------
__device__ __forceinline__ void ldsm_x4(uint32_t a, uint32_t* r) {
    asm volatile("ldmatrix.sync.aligned.m8n8.x4.shared.b16 {%0,%1,%2,%3}, [%4];"
                 : "=r"(r[0]), "=r"(r[1]), "=r"(r[2]), "=r"(r[3]) : "r"(a));
}
__device__ __forceinline__ void mma_f16(float* d, const uint32_t* a, const uint32_t* b) {
    asm volatile("mma.sync.aligned.m16n8k16.row.col.f32.f16.f16.f32 "
                 "{%0,%1,%2,%3}, {%4,%5,%6,%7}, {%8,%9}, {%0,%1,%2,%3};"
                 : "+f"(d[0]), "+f"(d[1]), "+f"(d[2]), "+f"(d[3])
                 : "r"(a[0]), "r"(a[1]), "r"(a[2]), "r"(a[3]),
                   "r"(b[0]), "r"(b[1]));
}
__device__ __forceinline__ void cp16(uint32_t dst, const void* src) {
    asm volatile("cp.async.cg.shared.global [%0], [%1], 16;" :: "r"(dst), "l"(src));
}

// smem geometry: rows padded to 80 B (40 halfs) — conflict-free ldmatrix
#define BK 32
#define ROWB 80
#define ARR_B (128 * ROWB)          // 10240 B per array
#define STAGE_B (3 * ARR_B)         // Ah | Al | Bh = 30720 B
#define SMEM_DYN (3 * STAGE_B)      // 3 stages = 92160 B

// ===========================================================================
// fp16 2-term tensor-core GEMM: C = (Ah+Al)[M,K] @ Bh[N,K]^T  (fp32 accum)
// Block 128x128, 8 warps (32x64 each), BK=32, 3-stage cp.async pipeline.
// grid = (N/128, M/128, z). alpha = (*scale_ptr) * alpha_mul.
// ===========================================================================
__global__ void __launch_bounds__(256) mma_gemm_nt(
    const __half* __restrict__ Ahb, const __half* __restrict__ Alb,
    const __half* __restrict__ Bhb,
    float* __restrict__ Cbase, int K, size_t sB, size_t sC, int ldC,
    const float* __restrict__ scale_ptr, float alpha_mul)
{
    extern __shared__ __align__(16) char dynsm[];
    const uint32_t sdyn = cvta_shared(dynsm);

    const int tid = threadIdx.x, lane = tid & 31, wid = tid >> 5;
    const int m0 = blockIdx.y * 128, n0 = blockIdx.x * 128;
    const __half* gAh = Ahb + (size_t)m0 * K;
    const __half* gAl = Alb + (size_t)m0 * K;
    const __half* gBh = Bhb + (size_t)blockIdx.z * sB + (size_t)n0 * K;
    float* C = Cbase + (size_t)blockIdx.z * sC;

    const int warp_m = wid >> 1;   // 0..3  (32 rows)
    const int warp_n = wid & 1;    // 0..1  (64 cols)
    const int r8 = lane & 7, midx = lane >> 3;
    const int NC = K / BK;

    // per-thread load mapping: rows tid>>2 and 64+(tid>>2), 16B col tid&3
    const int lr0 = tid >> 2, c4 = tid & 3;

    float acc[2][8][4];
#pragma unroll
    for (int mt = 0; mt < 2; mt++)
#pragma unroll
        for (int nt = 0; nt < 8; nt++)
#pragma unroll
            for (int r = 0; r < 4; r++) acc[mt][nt][r] = 0.0f;

    auto issue = [&](int s, int kc) {
        const int k0 = kc * BK;
        const uint32_t st = sdyn + s * STAGE_B;
#pragma unroll
        for (int h = 0; h < 2; h++) {
            const int r = lr0 + h * 64;
            const uint32_t d = st + r * ROWB + c4 * 16;
            const size_t g = (size_t)r * K + k0 + c4 * 8;
            cp16(d,             gAh + g);
            cp16(d + ARR_B,     gAl + g);
            cp16(d + 2 * ARR_B, gBh + g);
        }
        asm volatile("cp.async.commit_group;" ::: "memory");
    };

    issue(0, 0);
    issue(1, 1);

    for (int i = 0; i < NC; i++) {
        if (i < NC - 1) asm volatile("cp.async.wait_group 1;" ::: "memory");
        else            asm volatile("cp.async.wait_group 0;" ::: "memory");
        __syncthreads();
        if (i + 2 < NC) issue((i + 2) % 3, i + 2);

        const uint32_t stg = sdyn + (i % 3) * STAGE_B;
#pragma unroll
        for (int kh = 0; kh < 2; kh++) {
            uint32_t ah[2][4], al[2][4], bh4[4][4];
#pragma unroll
            for (int mt = 0; mt < 2; mt++) {
                const uint32_t ad = stg +
                    (warp_m * 32 + mt * 16 + (midx & 1) * 8 + r8) * ROWB +
                    (midx >> 1) * 16 + kh * 32;
                ldsm_x4(ad,         ah[mt]);
                ldsm_x4(ad + ARR_B, al[mt]);
            }
#pragma unroll
            for (int ng = 0; ng < 4; ng++) {
                const uint32_t bd = stg + 2 * ARR_B +
                    (warp_n * 64 + ng * 16 + (midx >> 1) * 8 + r8) * ROWB +
                    (midx & 1) * 16 + kh * 32;
                ldsm_x4(bd, bh4[ng]);
            }
#pragma unroll
            for (int mt = 0; mt < 2; mt++)
#pragma unroll
                for (int nt = 0; nt < 8; nt++) {
                    const uint32_t* bp = &bh4[nt >> 1][(nt & 1) * 2];
                    mma_f16(acc[mt][nt], ah[mt], bp);
                    mma_f16(acc[mt][nt], al[mt], bp);
                }
        }
    }

    const float alpha = (scale_ptr ? scale_ptr[0] : 1.0f) * alpha_mul;
    const int crow = lane >> 2, ccol = (lane & 3) * 2;
#pragma unroll
    for (int mt = 0; mt < 2; mt++)
#pragma unroll
        for (int nt = 0; nt < 8; nt++) {
            const int row = m0 + warp_m * 32 + mt * 16 + crow;
            const int col = n0 + warp_n * 64 + nt * 8 + ccol;
            float* p = C + (size_t)row * ldC + col;
            *(float2*)p = make_float2(acc[mt][nt][0] * alpha, acc[mt][nt][1] * alpha);
            *(float2*)(p + 8 * (size_t)ldC) =
                make_float2(acc[mt][nt][2] * alpha, acc[mt][nt][3] * alpha);
        }
}

// ===========================================================================
// fp32 -> (hi, lo) fp16 split with pre-scale, vectorized by 4
// ===========================================================================
__global__ void split_kernel(const float* __restrict__ s,
                             __half* __restrict__ h,
                             __half* __restrict__ l, int n4, float sc)
{
    int i = blockIdx.x * blockDim.x + threadIdx.x;
    if (i >= n4) return;
    float4 v = ((const float4*)s)[i];
    v.x *= sc; v.y *= sc; v.z *= sc; v.w *= sc;
    __half h0 = __float2half_rn(v.x), h1 = __float2half_rn(v.y);
    __half h2 = __float2half_rn(v.z), h3 = __float2half_rn(v.w);
    __half l0 = __float2half_rn(v.x - __half2float(h0));
    __half l1 = __float2half_rn(v.y - __half2float(h1));
    __half l2 = __float2half_rn(v.z - __half2float(h2));
    __half l3 = __float2half_rn(v.w - __half2float(h3));
    ((__half2*)h)[2 * i]     = __half2(h0, h1);
    ((__half2*)h)[2 * i + 1] = __half2(h2, h3);
    ((__half2*)l)[2 * i]     = __half2(l0, l1);
    ((__half2*)l)[2 * i + 1] = __half2(l2, l3);
}

// ===========================================================================
// 128x128x8 SGEMM, C = A[M,K] @ B[N,K]^T ("nt"), f32x2 core. Weight builds.
// ===========================================================================
__global__ void __launch_bounds__(256) sgemm_nt(
    const float* __restrict__ A0, const float* __restrict__ A1,
    const float* __restrict__ A2, const float* __restrict__ A3,
    const float* __restrict__ B0, const float* __restrict__ B1,
    const float* __restrict__ B2, const float* __restrict__ B3,
    float* __restrict__ Cbase, int M, int N, int K, size_t sC)
{
    const float* A = (blockIdx.z == 0) ? A0 : (blockIdx.z == 1) ? A1
                   : (blockIdx.z == 2) ? A2 : A3;
    const float* B = (blockIdx.z == 0) ? B0 : (blockIdx.z == 1) ? B1
                   : (blockIdx.z == 2) ? B2 : B3;
    float* C = Cbase + (size_t)blockIdx.z * sC;
    __shared__ __align__(16) float As[8][128];
    __shared__ __align__(16) float Bs[8][128];
    const int tid = threadIdx.x;
    const int m0 = blockIdx.y * 128, n0 = blockIdx.x * 128;
    const int tr = tid >> 4, tc = tid & 15;
    const int ar = tid >> 1, ac = (tid & 1) * 4;
    ull acc[8][4] = {};
    const float* Aptr = A + (size_t)(m0 + ar) * K + ac;
    const float* Bptr = B + (size_t)(n0 + ar) * K + ac;
    for (int k0 = 0; k0 < K; k0 += 8) {
        float4 av = *(const float4*)(Aptr + k0);
        As[ac + 0][ar] = av.x; As[ac + 1][ar] = av.y;
        As[ac + 2][ar] = av.z; As[ac + 3][ar] = av.w;
        float4 bv = *(const float4*)(Bptr + k0);
        Bs[ac + 0][ar] = bv.x; Bs[ac + 1][ar] = bv.y;
        Bs[ac + 2][ar] = bv.z; Bs[ac + 3][ar] = bv.w;
        __syncthreads();
#pragma unroll
        for (int kk = 0; kk < 8; kk++) {
            const ull* bp = (const ull*)&Bs[kk][tc * 8];
            ull b0 = bp[0], b1 = bp[1], b2 = bp[2], b3 = bp[3];
            const float* ap = &As[kk][tr * 8];
#pragma unroll
            for (int i = 0; i < 8; i++) {
                ull a2 = pack2(ap[i]);
                ffma2(acc[i][0], a2, b0); ffma2(acc[i][1], a2, b1);
                ffma2(acc[i][2], a2, b2); ffma2(acc[i][3], a2, b3);
            }
        }
        __syncthreads();
    }
#pragma unroll
    for (int i = 0; i < 8; i++) {
        float* Cp = C + (size_t)(m0 + tr * 8 + i) * N + n0 + tc * 8;
        float2 p0 = *(float2*)&acc[i][0], p1 = *(float2*)&acc[i][1];
        float2 p2 = *(float2*)&acc[i][2], p3 = *(float2*)&acc[i][3];
        *(float4*)(Cp)     = make_float4(p0.x, p0.y, p1.x, p1.y);
        *(float4*)(Cp + 4) = make_float4(p2.x, p2.y, p3.x, p3.y);
    }
}

// ===========================================================================
// Per-chunk decayed KV outer-product sums (f32x2 core)
// ===========================================================================
__global__ void __launch_bounds__(256) chunk_kv_kernel(const float* __restrict__ dlp)
{
    const int z = blockIdx.z;
    const int b = z >> 6, c = z & 63;
    const size_t rowbase = ((size_t)b * T_SZ + (size_t)c * L_SZ) * C_SZ;
    const float* Kp = g_QKV + (size_t)BT * C_SZ + rowbase;
    const float* Vp = g_QKV + 2 * (size_t)BT * C_SZ + rowbase;
    float* Cp = g_AS + (size_t)z * C_SZ * C_SZ;
    const float decay = get_decay(dlp);
    const float lg2d = log2f(decay);

    __shared__ __align__(16) float As[8][128];
    __shared__ __align__(16) float Bs[8][128];
    const int tid = threadIdx.x;
    const int m0 = blockIdx.y * 128, n0 = blockIdx.x * 128;
    const int tr = tid >> 4, tc = tid & 15;
    const int lr = tid >> 5, lc = (tid & 31) * 4;
    ull acc[8][4] = {};
    for (int k0 = 0; k0 < L_SZ; k0 += 8) {
        const float sc = exp2f((float)(k0 + lr) * lg2d);
        float4 av = *(const float4*)&Kp[(size_t)(k0 + lr) * C_SZ + m0 + lc];
        av.x *= sc; av.y *= sc; av.z *= sc; av.w *= sc;
        *(float4*)&As[lr][lc] = av;
        *(float4*)&Bs[lr][lc] = *(const float4*)&Vp[(size_t)(k0 + lr) * C_SZ + n0 + lc];
        __syncthreads();
#pragma unroll
        for (int kk = 0; kk < 8; kk++) {
            const ull* bp = (const ull*)&Bs[kk][tc * 8];
            ull b0 = bp[0], b1 = bp[1], b2 = bp[2], b3 = bp[3];
            const float* ap = &As[kk][tr * 8];
#pragma unroll
            for (int i = 0; i < 8; i++) {
                ull a2 = pack2(ap[i]);
                ffma2(acc[i][0], a2, b0); ffma2(acc[i][1], a2, b1);
                ffma2(acc[i][2], a2, b2); ffma2(acc[i][3], a2, b3);
            }
        }
        __syncthreads();
    }
#pragma unroll
    for (int i = 0; i < 8; i++) {
        float* Op = Cp + (size_t)(m0 + tr * 8 + i) * C_SZ + n0 + tc * 8;
        float2 p0 = *(float2*)&acc[i][0], p1 = *(float2*)&acc[i][1];
        float2 p2 = *(float2*)&acc[i][2], p3 = *(float2*)&acc[i][3];
        *(float4*)(Op)     = make_float4(p0.x, p0.y, p1.x, p1.y);
        *(float4*)(Op + 4) = make_float4(p2.x, p2.y, p3.x, p3.y);
    }
}

// ===========================================================================
// Backward state scan over chunks (in-place on g_AS)
// ===========================================================================
__global__ void scan_kernel(const float* __restrict__ dlp)
{
    const int e = blockIdx.x * blockDim.x + threadIdx.x;
    const int b = blockIdx.y;
    const float decay = get_decay(dlp);
    const float dL = exp2f((float)L_SZ * log2f(decay));
    float run = 0.0f;
    float* base = g_AS + (size_t)b * NCH * (C_SZ * C_SZ) + e;
    for (int c = NCH - 1; c >= 0; c--) {
        float* p = base + (size_t)c * (C_SZ * C_SZ);
        float v = *p;
        *p = run;
        run = fmaf(dL, run, v);
    }
}

// ===========================================================================
// Per-chunk attention (f32x2 core)
// ===========================================================================
__global__ void __launch_bounds__(256) attn_kernel(const float* __restrict__ dlp)
{
    const int c = blockIdx.x, b = blockIdx.y;
    const size_t base = ((size_t)b * T_SZ + (size_t)c * L_SZ) * C_SZ;
    const float* Q  = g_QKV + base;
    const float* Kp = g_QKV + (size_t)BT * C_SZ + base;
    const float* Vp = g_QKV + 2 * (size_t)BT * C_SZ + base;
    const float* S  = g_AS + ((size_t)(b * NCH + c)) * (C_SZ * C_SZ);
    float* R = g_R + base;
    const float decay = get_decay(dlp);
    const float lg2d = log2f(decay);
    const int tid = threadIdx.x;

    __shared__ __align__(16) float P[64][66];
    __shared__ __align__(16) float Ta[16][64];
    __shared__ __align__(16) float Tb[16][64];
    __shared__ __align__(16) float Ws[8][256];
    __shared__ __align__(16) float Qs[8][64];

    // ---- Phase 1: P = mask-weighted Q K^T ----
    {
        const int tr = tid >> 4, tc = tid & 15;
        const int lrow = tid >> 2, lc4 = (tid & 3) * 4;
        ull acc[4][2] = {};
        for (int k0 = 0; k0 < C_SZ; k0 += 16) {
            float4 qv = *(const float4*)&Q [(size_t)lrow * C_SZ + k0 + lc4];
            Ta[lc4 + 0][lrow] = qv.x; Ta[lc4 + 1][lrow] = qv.y;
            Ta[lc4 + 2][lrow] = qv.z; Ta[lc4 + 3][lrow] = qv.w;
            float4 kv = *(const float4*)&Kp[(size_t)lrow * C_SZ + k0 + lc4];
            Tb[lc4 + 0][lrow] = kv.x; Tb[lc4 + 1][lrow] = kv.y;
            Tb[lc4 + 2][lrow] = kv.z; Tb[lc4 + 3][lrow] = kv.w;
            __syncthreads();
#pragma unroll
            for (int kk = 0; kk < 16; kk++) {
                const ull* bp = (const ull*)&Tb[kk][tc * 4];
                ull b0 = bp[0], b1 = bp[1];
                const float* ap = &Ta[kk][tr * 4];
#pragma unroll
                for (int i = 0; i < 4; i++) {
                    ull a2 = pack2(ap[i]);
                    ffma2(acc[i][0], a2, b0); ffma2(acc[i][1], a2, b1);
                }
            }
            __syncthreads();
        }
#pragma unroll
        for (int ii = 0; ii < 4; ii++) {
            const float2 q0 = *(float2*)&acc[ii][0];
            const float2 q1 = *(float2*)&acc[ii][1];
            float vv[4] = {q0.x, q0.y, q1.x, q1.y};
#pragma unroll
            for (int jj = 0; jj < 4; jj++) {
                int i = tr * 4 + ii, j = tc * 4 + jj;
                P[i][j] = (j > i) ? vv[jj] * exp2f((float)(j - i - 1) * lg2d) : 0.0f;
            }
        }
    }
    __syncthreads();

    // ---- Phase 2: R = P @ V + (Dq*Q) @ S ----
    {
        const int tr = tid >> 5, tc = tid & 31;
        const int lr = tid >> 5, lc8 = (tid & 31) * 8;
        ull acc[8][4] = {};
        for (int k0 = 0; k0 < L_SZ; k0 += 8) {
            *(float4*)&Ws[lr][lc8]     = *(const float4*)&Vp[(size_t)(k0 + lr) * C_SZ + lc8];
            *(float4*)&Ws[lr][lc8 + 4] = *(const float4*)&Vp[(size_t)(k0 + lr) * C_SZ + lc8 + 4];
            __syncthreads();
#pragma unroll
            for (int kk = 0; kk < 8; kk++) {
                const ull* bp = (const ull*)&Ws[kk][tc * 8];
                ull b0 = bp[0], b1 = bp[1], b2 = bp[2], b3 = bp[3];
#pragma unroll
                for (int i = 0; i < 8; i++) {
                    ull a2 = pack2(P[tr * 8 + i][k0 + kk]);
                    ffma2(acc[i][0], a2, b0); ffma2(acc[i][1], a2, b1);
                    ffma2(acc[i][2], a2, b2); ffma2(acc[i][3], a2, b3);
                }
            }
            __syncthreads();
        }
        for (int k0 = 0; k0 < C_SZ; k0 += 8) {
            if (tid < 128) {
                int row = tid >> 1, c4 = (tid & 1) * 4;
                float dq = exp2f((float)(63 - row) * lg2d);
                float4 qv = *(const float4*)&Q[(size_t)row * C_SZ + k0 + c4];
                Qs[c4 + 0][row] = qv.x * dq; Qs[c4 + 1][row] = qv.y * dq;
                Qs[c4 + 2][row] = qv.z * dq; Qs[c4 + 3][row] = qv.w * dq;
            }
            *(float4*)&Ws[lr][lc8]     = *(const float4*)&S[(size_t)(k0 + lr) * C_SZ + lc8];
            *(float4*)&Ws[lr][lc8 + 4] = *(const float4*)&S[(size_t)(k0 + lr) * C_SZ + lc8 + 4];
            __syncthreads();
#pragma unroll
            for (int kk = 0; kk < 8; kk++) {
                const ull* bp = (const ull*)&Ws[kk][tc * 8];
                ull b0 = bp[0], b1 = bp[1], b2 = bp[2], b3 = bp[3];
                const float* ap = &Qs[kk][tr * 8];
#pragma unroll
                for (int i = 0; i < 8; i++) {
                    ull a2 = pack2(ap[i]);
                    ffma2(acc[i][0], a2, b0); ffma2(acc[i][1], a2, b1);
                    ffma2(acc[i][2], a2, b2); ffma2(acc[i][3], a2, b3);
                }
            }
            __syncthreads();
        }
#pragma unroll
        for (int i = 0; i < 8; i++) {
            float* Rp = R + (size_t)(tr * 8 + i) * C_SZ + tc * 8;
            float2 p0 = *(float2*)&acc[i][0], p1 = *(float2*)&acc[i][1];
            float2 p2 = *(float2*)&acc[i][2], p3 = *(float2*)&acc[i][3];
            *(float4*)(Rp)     = make_float4(p0.x, p0.y, p1.x, p1.y);
            *(float4*)(Rp + 4) = make_float4(p2.x, p2.y, p3.x, p3.y);
        }
    }
}

// ===========================================================================
extern "C" void kernel_launch(void* const* d_in, const int* in_sizes, int n_in,
                              void* d_out, int out_size)
{
    const float* x     = (const float*)d_in[0];
    const float* basis = (const float*)d_in[1];
    const float* qc    = (const float*)d_in[2];
    const float* kc    = (const float*)d_in[3];
    const float* vc    = (const float*)d_in[4];
    const float* oc    = (const float*)d_in[5];
    const float* dl    = (const float*)d_in[6];
    const float* os    = (const float*)d_in[7];
    float* out = (float*)d_out;

    float *pWt, *pWo, *pR, *pQKV;
    __half *pxh, *pxl, *pWth, *pWoh, *pRh, *pRl, *pWtl_d, *pWol_d;
    cudaGetSymbolAddress((void**)&pWt,    g_Wt);
    cudaGetSymbolAddress((void**)&pWo,    g_Wo);
    cudaGetSymbolAddress((void**)&pR,     g_R);
    cudaGetSymbolAddress((void**)&pQKV,   g_QKV);
    cudaGetSymbolAddress((void**)&pxh,    g_xh);
    cudaGetSymbolAddress((void**)&pxl,    g_xl);
    cudaGetSymbolAddress((void**)&pWth,   g_Wth);
    cudaGetSymbolAddress((void**)&pWoh,   g_Woh);
    cudaGetSymbolAddress((void**)&pRh,    g_Rh);
    cudaGetSymbolAddress((void**)&pRl,    g_Rl);
    cudaGetSymbolAddress((void**)&pWtl_d, g_unused_l);
    cudaGetSymbolAddress((void**)&pWol_d, g_unused_l2);

    cudaFuncSetAttribute(mma_gemm_nt, cudaFuncAttributeMaxDynamicSharedMemorySize, SMEM_DYN);

    // 1. Weight builds (fp32, small):
    sgemm_nt<<<dim3(8, 2, 3), 256>>>(qc, kc, vc, qc, basis, basis, basis, basis,
                                     pWt, 256, 1024, 256, (size_t)C_SZ * V_SZ);
    sgemm_nt<<<dim3(2, 8, 1), 256>>>(basis, basis, basis, basis, oc, oc, oc, oc,
                                     pWo, 1024, 256, 256, 0);

    // 2. fp16 splits (A operands get hi+lo; B operands hi used, lo discarded)
    split_kernel<<<(BT * V_SZ / 4 + 255) / 256, 256>>>(x, pxh, pxl, BT * V_SZ / 4, 1.0f);
    split_kernel<<<(3 * C_SZ * V_SZ / 4 + 255) / 256, 256>>>(pWt, pWth, pWtl_d,
                                                             3 * C_SZ * V_SZ / 4, 1.0f);
    split_kernel<<<(V_SZ * C_SZ / 4 + 255) / 256, 256>>>(pWo, pWoh, pWol_d,
                                                         V_SZ * C_SZ / 4, 1.0f);

    // 3. QKV projections: QKV[z] = x @ Wt[z]^T  [16384,256]
    mma_gemm_nt<<<dim3(2, 128, 3), 256, SMEM_DYN>>>(
        pxh, pxl, pWth, pQKV, V_SZ,
        (size_t)C_SZ * V_SZ, (size_t)BT * C_SZ, C_SZ, nullptr, 1.0f);

    // 4. Per-chunk decayed KV sums, state scan, per-chunk attention
    chunk_kv_kernel<<<dim3(2, 2, B_SZ * NCH), 256>>>(dl);
    scan_kernel<<<dim3(256, B_SZ), 256>>>(dl);
    attn_kernel<<<dim3(NCH, B_SZ), 256>>>(dl);

    // 5. Split retrieved (pre-scaled 2^-8 for fp16 range), then output proj:
    //    out = R @ Wo^T * out_scale   (alpha re-applies 2^8)
    split_kernel<<<(BT * C_SZ / 4 + 255) / 256, 256>>>(pR, pRh, pRl, BT * C_SZ / 4, R_SCALE);
    mma_gemm_nt<<<dim3(8, 128, 1), 256, SMEM_DYN>>>(
        pRh, pRl, pWoh, out, C_SZ, 0, 0, V_SZ, os, R_UNSCALE);
}

// round 7
// speedup vs baseline: 2.3113x; 1.1505x over previous
#include <cuda_runtime.h>
#include <cuda_fp16.h>
#include <math.h>
#include <stdint.h>

// Problem constants
#define B_SZ 4
#define T_SZ 4096
#define V_SZ 1024
#define C_SZ 256
#define L_SZ 64                 // chunk length
#define NCH  64                 // chunks per batch (T/L)
#define BT   (B_SZ * T_SZ)      // 16384

#define R_SCALE   0.00390625f   // 2^-8 pre-scale for R (fp16 range safety)
#define R_UNSCALE 256.0f

typedef unsigned long long ull;

// ---------------- scratch (static __device__ arrays; no runtime alloc) -----
__device__ float g_Wo [V_SZ * C_SZ];                        // Wo [1024,256] (K-major over C)
__device__ float g_xb [BT * C_SZ];                          // xb = x @ basis (fp32)
__device__ float g_QKV[3 * BT * C_SZ];                      // Q,K,V fp32
__device__ float g_AS [B_SZ * NCH * C_SZ * C_SZ];           // A_c, then states in-place
__device__ float g_R  [BT * C_SZ];                          // retrieved
// fp16 split operands
__device__ __half g_xh [BT * V_SZ];
__device__ __half g_xl [BT * V_SZ];
__device__ __half g_bTh[C_SZ * V_SZ];       // basis^T hi [256,1024]
__device__ __half g_bTl[C_SZ * V_SZ];       // basis^T lo (unused by 2-term; written anyway)
__device__ __half g_xbh[BT * C_SZ];
__device__ __half g_xbl[BT * C_SZ];
__device__ __half g_ch [3 * C_SZ * C_SZ];   // q/k/v coeffs hi
__device__ __half g_cl [3 * C_SZ * C_SZ];   // q/k/v coeffs lo
__device__ __half g_Woh[V_SZ * C_SZ];
__device__ __half g_Wol[V_SZ * C_SZ];       // unused (2-term), split target
__device__ __half g_Rh [BT * C_SZ];
__device__ __half g_Rl [BT * C_SZ];

__device__ __forceinline__ float get_decay(const float* dl) {
    return 1.0f / (1.0f + expf(-dl[0]));
}

// ---- packed fp32x2 helpers (FFMA kernels) ---------------------------------
__device__ __forceinline__ ull pack2(float x) {
    ull r;
    asm("mov.b64 %0, {%1, %1};" : "=l"(r) : "f"(x));
    return r;
}
__device__ __forceinline__ void ffma2(ull& c, ull a, ull b) {
    asm("fma.rn.f32x2 %0, %1, %2, %0;" : "+l"(c) : "l"(a), "l"(b));
}

__device__ __forceinline__ uint32_t cvta_shared(const void* p) {
    uint32_t a;
    asm("{ .reg .u64 t; cvta.to.shared.u64 t, %1; cvt.u32.u64 %0, t; }"
        : "=r"(a) : "l"(p));
    return a;
}

// ---- mma.sync / ldmatrix / cp.async helpers -------------------------------
__device__ __forceinline__ void ldsm_x4(uint32_t a, uint32_t* r) {
    asm volatile("ldmatrix.sync.aligned.m8n8.x4.shared.b16 {%0,%1,%2,%3}, [%4];"
                 : "=r"(r[0]), "=r"(r[1]), "=r"(r[2]), "=r"(r[3]) : "r"(a));
}
__device__ __forceinline__ void mma_f16(float* d, const uint32_t* a, const uint32_t* b) {
    asm volatile("mma.sync.aligned.m16n8k16.row.col.f32.f16.f16.f32 "
                 "{%0,%1,%2,%3}, {%4,%5,%6,%7}, {%8,%9}, {%0,%1,%2,%3};"
                 : "+f"(d[0]), "+f"(d[1]), "+f"(d[2]), "+f"(d[3])
                 : "r"(a[0]), "r"(a[1]), "r"(a[2]), "r"(a[3]),
                   "r"(b[0]), "r"(b[1]));
}
__device__ __forceinline__ void cp16(uint32_t dst, const void* src) {
    asm volatile("cp.async.cg.shared.global [%0], [%1], 16;" :: "r"(dst), "l"(src));
}

// smem geometry: rows padded to 80 B (40 halfs) — conflict-free ldmatrix
#define BK 32
#define ROWB 80
#define ARR_B (128 * ROWB)          // 10240 B per array

// ===========================================================================
// fp16 tensor-core GEMM, templated on number of smem arrays:
//   NARR=3: C = (Ah+Al) @ Bh^T            (2-term; Bl unused)
//   NARR=4: C = Ah@Bh + Ah@Bl + Al@Bh     (3-term; quasi-exact)
// Block 128x128, 8 warps (32x64 each), BK=32, 3-stage cp.async pipeline.
// grid = (N/128, M/128, z); z offsets B by sB and C by sC.
// ===========================================================================
template <int NARR>
__global__ void __launch_bounds__(256) mma_gemm(
    const __half* __restrict__ Ahb, const __half* __restrict__ Alb,
    const __half* __restrict__ Bhb, const __half* __restrict__ Blb,
    float* __restrict__ Cbase, int K, size_t sB, size_t sC, int ldC,
    const float* __restrict__ scale_ptr, float alpha_mul)
{
    extern __shared__ __align__(16) char dynsm[];
    const uint32_t sdyn = cvta_shared(dynsm);
    const uint32_t STAGE_B = NARR * ARR_B;

    const int tid = threadIdx.x, lane = tid & 31, wid = tid >> 5;
    const int m0 = blockIdx.y * 128, n0 = blockIdx.x * 128;
    const __half* gAh = Ahb + (size_t)m0 * K;
    const __half* gAl = Alb + (size_t)m0 * K;
    const __half* gBh = Bhb + (size_t)blockIdx.z * sB + (size_t)n0 * K;
    const __half* gBl = Blb + (size_t)blockIdx.z * sB + (size_t)n0 * K;
    float* C = Cbase + (size_t)blockIdx.z * sC;

    const int warp_m = wid >> 1;   // 0..3  (32 rows)
    const int warp_n = wid & 1;    // 0..1  (64 cols)
    const int r8 = lane & 7, midx = lane >> 3;
    const int NC = K / BK;
    const int lr0 = tid >> 2, c4 = tid & 3;

    float acc[2][8][4];
#pragma unroll
    for (int mt = 0; mt < 2; mt++)
#pragma unroll
        for (int nt = 0; nt < 8; nt++)
#pragma unroll
            for (int r = 0; r < 4; r++) acc[mt][nt][r] = 0.0f;

    auto issue = [&](int s, int kc) {
        const int k0 = kc * BK;
        const uint32_t st = sdyn + s * STAGE_B;
#pragma unroll
        for (int h = 0; h < 2; h++) {
            const int r = lr0 + h * 64;
            const uint32_t d = st + r * ROWB + c4 * 16;
            const size_t g = (size_t)r * K + k0 + c4 * 8;
            cp16(d,             gAh + g);
            cp16(d + ARR_B,     gAl + g);
            cp16(d + 2 * ARR_B, gBh + g);
            if (NARR == 4) cp16(d + 3 * ARR_B, gBl + g);
        }
        asm volatile("cp.async.commit_group;" ::: "memory");
    };

    issue(0, 0);
    issue(1, 1);

    for (int i = 0; i < NC; i++) {
        if (i < NC - 1) asm volatile("cp.async.wait_group 1;" ::: "memory");
        else            asm volatile("cp.async.wait_group 0;" ::: "memory");
        __syncthreads();
        if (i + 2 < NC) issue((i + 2) % 3, i + 2);

        const uint32_t stg = sdyn + (i % 3) * STAGE_B;
#pragma unroll
        for (int kh = 0; kh < 2; kh++) {
            uint32_t ah[2][4], al[2][4], bh4[4][4], bl4[4][4];
#pragma unroll
            for (int mt = 0; mt < 2; mt++) {
                const uint32_t ad = stg +
                    (warp_m * 32 + mt * 16 + (midx & 1) * 8 + r8) * ROWB +
                    (midx >> 1) * 16 + kh * 32;
                ldsm_x4(ad,         ah[mt]);
                ldsm_x4(ad + ARR_B, al[mt]);
            }
#pragma unroll
            for (int ng = 0; ng < 4; ng++) {
                const uint32_t bd = stg + 2 * ARR_B +
                    (warp_n * 64 + ng * 16 + (midx >> 1) * 8 + r8) * ROWB +
                    (midx & 1) * 16 + kh * 32;
                ldsm_x4(bd, bh4[ng]);
                if (NARR == 4) ldsm_x4(bd + ARR_B, bl4[ng]);
            }
#pragma unroll
            for (int mt = 0; mt < 2; mt++)
#pragma unroll
                for (int nt = 0; nt < 8; nt++) {
                    const uint32_t* bp = &bh4[nt >> 1][(nt & 1) * 2];
                    mma_f16(acc[mt][nt], ah[mt], bp);
                    mma_f16(acc[mt][nt], al[mt], bp);
                    if (NARR == 4) {
                        const uint32_t* blp = &bl4[nt >> 1][(nt & 1) * 2];
                        mma_f16(acc[mt][nt], ah[mt], blp);
                    }
                }
        }
    }

    const float alpha = (scale_ptr ? scale_ptr[0] : 1.0f) * alpha_mul;
    const int crow = lane >> 2, ccol = (lane & 3) * 2;
#pragma unroll
    for (int mt = 0; mt < 2; mt++)
#pragma unroll
        for (int nt = 0; nt < 8; nt++) {
            const int row = m0 + warp_m * 32 + mt * 16 + crow;
            const int col = n0 + warp_n * 64 + nt * 8 + ccol;
            float* p = C + (size_t)row * ldC + col;
            *(float2*)p = make_float2(acc[mt][nt][0] * alpha, acc[mt][nt][1] * alpha);
            *(float2*)(p + 8 * (size_t)ldC) =
                make_float2(acc[mt][nt][2] * alpha, acc[mt][nt][3] * alpha);
        }
}

// ===========================================================================
// fp32 -> (hi, lo) fp16 split with pre-scale, vectorized by 4
// ===========================================================================
__global__ void split_kernel(const float* __restrict__ s,
                             __half* __restrict__ h,
                             __half* __restrict__ l, int n4, float sc)
{
    int i = blockIdx.x * blockDim.x + threadIdx.x;
    if (i >= n4) return;
    float4 v = ((const float4*)s)[i];
    v.x *= sc; v.y *= sc; v.z *= sc; v.w *= sc;
    __half h0 = __float2half_rn(v.x), h1 = __float2half_rn(v.y);
    __half h2 = __float2half_rn(v.z), h3 = __float2half_rn(v.w);
    __half l0 = __float2half_rn(v.x - __half2float(h0));
    __half l1 = __float2half_rn(v.y - __half2float(h1));
    __half l2 = __float2half_rn(v.z - __half2float(h2));
    __half l3 = __float2half_rn(v.w - __half2float(h3));
    ((__half2*)h)[2 * i]     = __half2(h0, h1);
    ((__half2*)h)[2 * i + 1] = __half2(h2, h3);
    ((__half2*)l)[2 * i]     = __half2(l0, l1);
    ((__half2*)l)[2 * i + 1] = __half2(l2, l3);
}

// ===========================================================================
// basis [1024,256] fp32 -> basis^T [256,1024] split to fp16 hi/lo (tiled)
// grid (32, 8), block (32, 8)
// ===========================================================================
__global__ void transpose_split(const float* __restrict__ in,
                                __half* __restrict__ oh, __half* __restrict__ ol)
{
    __shared__ float t[32][33];
    const int v0 = blockIdx.x * 32, c0 = blockIdx.y * 32;
    const int tx = threadIdx.x, ty = threadIdx.y;
#pragma unroll
    for (int j = 0; j < 32; j += 8)
        t[ty + j][tx] = in[(size_t)(v0 + ty + j) * C_SZ + c0 + tx];
    __syncthreads();
#pragma unroll
    for (int j = 0; j < 32; j += 8) {
        float val = t[tx][ty + j];
        __half h = __float2half_rn(val);
        oh[(size_t)(c0 + ty + j) * V_SZ + v0 + tx] = h;
        ol[(size_t)(c0 + ty + j) * V_SZ + v0 + tx] =
            __float2half_rn(val - __half2float(h));
    }
}

// ===========================================================================
// 128x128x8 SGEMM, C = A[M,K] @ B[N,K]^T ("nt"), f32x2 core. Wo build only.
// ===========================================================================
__global__ void __launch_bounds__(256) sgemm_nt(
    const float* __restrict__ A, const float* __restrict__ B,
    float* __restrict__ C, int M, int N, int K)
{
    __shared__ __align__(16) float As[8][128];
    __shared__ __align__(16) float Bs[8][128];
    const int tid = threadIdx.x;
    const int m0 = blockIdx.y * 128, n0 = blockIdx.x * 128;
    const int tr = tid >> 4, tc = tid & 15;
    const int ar = tid >> 1, ac = (tid & 1) * 4;
    ull acc[8][4] = {};
    const float* Aptr = A + (size_t)(m0 + ar) * K + ac;
    const float* Bptr = B + (size_t)(n0 + ar) * K + ac;
    for (int k0 = 0; k0 < K; k0 += 8) {
        float4 av = *(const float4*)(Aptr + k0);
        As[ac + 0][ar] = av.x; As[ac + 1][ar] = av.y;
        As[ac + 2][ar] = av.z; As[ac + 3][ar] = av.w;
        float4 bv = *(const float4*)(Bptr + k0);
        Bs[ac + 0][ar] = bv.x; Bs[ac + 1][ar] = bv.y;
        Bs[ac + 2][ar] = bv.z; Bs[ac + 3][ar] = bv.w;
        __syncthreads();
#pragma unroll
        for (int kk = 0; kk < 8; kk++) {
            const ull* bp = (const ull*)&Bs[kk][tc * 8];
            ull b0 = bp[0], b1 = bp[1], b2 = bp[2], b3 = bp[3];
            const float* ap = &As[kk][tr * 8];
#pragma unroll
            for (int i = 0; i < 8; i++) {
                ull a2 = pack2(ap[i]);
                ffma2(acc[i][0], a2, b0); ffma2(acc[i][1], a2, b1);
                ffma2(acc[i][2], a2, b2); ffma2(acc[i][3], a2, b3);
            }
        }
        __syncthreads();
    }
#pragma unroll
    for (int i = 0; i < 8; i++) {
        float* Cp = C + (size_t)(m0 + tr * 8 + i) * N + n0 + tc * 8;
        float2 p0 = *(float2*)&acc[i][0], p1 = *(float2*)&acc[i][1];
        float2 p2 = *(float2*)&acc[i][2], p3 = *(float2*)&acc[i][3];
        *(float4*)(Cp)     = make_float4(p0.x, p0.y, p1.x, p1.y);
        *(float4*)(Cp + 4) = make_float4(p2.x, p2.y, p3.x, p3.y);
    }
}

// ===========================================================================
// Per-chunk decayed KV outer-product sums (f32x2 core)
// ===========================================================================
__global__ void __launch_bounds__(256) chunk_kv_kernel(const float* __restrict__ dlp)
{
    const int z = blockIdx.z;
    const int b = z >> 6, c = z & 63;
    const size_t rowbase = ((size_t)b * T_SZ + (size_t)c * L_SZ) * C_SZ;
    const float* Kp = g_QKV + (size_t)BT * C_SZ + rowbase;
    const float* Vp = g_QKV + 2 * (size_t)BT * C_SZ + rowbase;
    float* Cp = g_AS + (size_t)z * C_SZ * C_SZ;
    const float decay = get_decay(dlp);
    const float lg2d = log2f(decay);

    __shared__ __align__(16) float As[8][128];
    __shared__ __align__(16) float Bs[8][128];
    const int tid = threadIdx.x;
    const int m0 = blockIdx.y * 128, n0 = blockIdx.x * 128;
    const int tr = tid >> 4, tc = tid & 15;
    const int lr = tid >> 5, lc = (tid & 31) * 4;
    ull acc[8][4] = {};
    for (int k0 = 0; k0 < L_SZ; k0 += 8) {
        const float sc = exp2f((float)(k0 + lr) * lg2d);
        float4 av = *(const float4*)&Kp[(size_t)(k0 + lr) * C_SZ + m0 + lc];
        av.x *= sc; av.y *= sc; av.z *= sc; av.w *= sc;
        *(float4*)&As[lr][lc] = av;
        *(float4*)&Bs[lr][lc] = *(const float4*)&Vp[(size_t)(k0 + lr) * C_SZ + n0 + lc];
        __syncthreads();
#pragma unroll
        for (int kk = 0; kk < 8; kk++) {
            const ull* bp = (const ull*)&Bs[kk][tc * 8];
            ull b0 = bp[0], b1 = bp[1], b2 = bp[2], b3 = bp[3];
            const float* ap = &As[kk][tr * 8];
#pragma unroll
            for (int i = 0; i < 8; i++) {
                ull a2 = pack2(ap[i]);
                ffma2(acc[i][0], a2, b0); ffma2(acc[i][1], a2, b1);
                ffma2(acc[i][2], a2, b2); ffma2(acc[i][3], a2, b3);
            }
        }
        __syncthreads();
    }
#pragma unroll
    for (int i = 0; i < 8; i++) {
        float* Op = Cp + (size_t)(m0 + tr * 8 + i) * C_SZ + n0 + tc * 8;
        float2 p0 = *(float2*)&acc[i][0], p1 = *(float2*)&acc[i][1];
        float2 p2 = *(float2*)&acc[i][2], p3 = *(float2*)&acc[i][3];
        *(float4*)(Op)     = make_float4(p0.x, p0.y, p1.x, p1.y);
        *(float4*)(Op + 4) = make_float4(p2.x, p2.y, p3.x, p3.y);
    }
}

// ===========================================================================
// Backward state scan over chunks (in-place on g_AS)
// ===========================================================================
__global__ void scan_kernel(const float* __restrict__ dlp)
{
    const int e = blockIdx.x * blockDim.x + threadIdx.x;
    const int b = blockIdx.y;
    const float decay = get_decay(dlp);
    const float dL = exp2f((float)L_SZ * log2f(decay));
    float run = 0.0f;
    float* base = g_AS + (size_t)b * NCH * (C_SZ * C_SZ) + e;
    for (int c = NCH - 1; c >= 0; c--) {
        float* p = base + (size_t)c * (C_SZ * C_SZ);
        float v = *p;
        *p = run;
        run = fmaf(dL, run, v);
    }
}

// ===========================================================================
// Per-chunk attention (f32x2 core)
// ===========================================================================
__global__ void __launch_bounds__(256) attn_kernel(const float* __restrict__ dlp)
{
    const int c = blockIdx.x, b = blockIdx.y;
    const size_t base = ((size_t)b * T_SZ + (size_t)c * L_SZ) * C_SZ;
    const float* Q  = g_QKV + base;
    const float* Kp = g_QKV + (size_t)BT * C_SZ + base;
    const float* Vp = g_QKV + 2 * (size_t)BT * C_SZ + base;
    const float* S  = g_AS + ((size_t)(b * NCH + c)) * (C_SZ * C_SZ);
    float* R = g_R + base;
    const float decay = get_decay(dlp);
    const float lg2d = log2f(decay);
    const int tid = threadIdx.x;

    __shared__ __align__(16) float P[64][66];
    __shared__ __align__(16) float Ta[16][64];
    __shared__ __align__(16) float Tb[16][64];
    __shared__ __align__(16) float Ws[8][256];
    __shared__ __align__(16) float Qs[8][64];

    // ---- Phase 1: P = mask-weighted Q K^T ----
    {
        const int tr = tid >> 4, tc = tid & 15;
        const int lrow = tid >> 2, lc4 = (tid & 3) * 4;
        ull acc[4][2] = {};
        for (int k0 = 0; k0 < C_SZ; k0 += 16) {
            float4 qv = *(const float4*)&Q [(size_t)lrow * C_SZ + k0 + lc4];
            Ta[lc4 + 0][lrow] = qv.x; Ta[lc4 + 1][lrow] = qv.y;
            Ta[lc4 + 2][lrow] = qv.z; Ta[lc4 + 3][lrow] = qv.w;
            float4 kv = *(const float4*)&Kp[(size_t)lrow * C_SZ + k0 + lc4];
            Tb[lc4 + 0][lrow] = kv.x; Tb[lc4 + 1][lrow] = kv.y;
            Tb[lc4 + 2][lrow] = kv.z; Tb[lc4 + 3][lrow] = kv.w;
            __syncthreads();
#pragma unroll
            for (int kk = 0; kk < 16; kk++) {
                const ull* bp = (const ull*)&Tb[kk][tc * 4];
                ull b0 = bp[0], b1 = bp[1];
                const float* ap = &Ta[kk][tr * 4];
#pragma unroll
                for (int i = 0; i < 4; i++) {
                    ull a2 = pack2(ap[i]);
                    ffma2(acc[i][0], a2, b0); ffma2(acc[i][1], a2, b1);
                }
            }
            __syncthreads();
        }
#pragma unroll
        for (int ii = 0; ii < 4; ii++) {
            const float2 q0 = *(float2*)&acc[ii][0];
            const float2 q1 = *(float2*)&acc[ii][1];
            float vv[4] = {q0.x, q0.y, q1.x, q1.y};
#pragma unroll
            for (int jj = 0; jj < 4; jj++) {
                int i = tr * 4 + ii, j = tc * 4 + jj;
                P[i][j] = (j > i) ? vv[jj] * exp2f((float)(j - i - 1) * lg2d) : 0.0f;
            }
        }
    }
    __syncthreads();

    // ---- Phase 2: R = P @ V + (Dq*Q) @ S ----
    {
        const int tr = tid >> 5, tc = tid & 31;
        const int lr = tid >> 5, lc8 = (tid & 31) * 8;
        ull acc[8][4] = {};
        for (int k0 = 0; k0 < L_SZ; k0 += 8) {
            *(float4*)&Ws[lr][lc8]     = *(const float4*)&Vp[(size_t)(k0 + lr) * C_SZ + lc8];
            *(float4*)&Ws[lr][lc8 + 4] = *(const float4*)&Vp[(size_t)(k0 + lr) * C_SZ + lc8 + 4];
            __syncthreads();
#pragma unroll
            for (int kk = 0; kk < 8; kk++) {
                const ull* bp = (const ull*)&Ws[kk][tc * 8];
                ull b0 = bp[0], b1 = bp[1], b2 = bp[2], b3 = bp[3];
#pragma unroll
                for (int i = 0; i < 8; i++) {
                    ull a2 = pack2(P[tr * 8 + i][k0 + kk]);
                    ffma2(acc[i][0], a2, b0); ffma2(acc[i][1], a2, b1);
                    ffma2(acc[i][2], a2, b2); ffma2(acc[i][3], a2, b3);
                }
            }
            __syncthreads();
        }
        for (int k0 = 0; k0 < C_SZ; k0 += 8) {
            if (tid < 128) {
                int row = tid >> 1, c4 = (tid & 1) * 4;
                float dq = exp2f((float)(63 - row) * lg2d);
                float4 qv = *(const float4*)&Q[(size_t)row * C_SZ + k0 + c4];
                Qs[c4 + 0][row] = qv.x * dq; Qs[c4 + 1][row] = qv.y * dq;
                Qs[c4 + 2][row] = qv.z * dq; Qs[c4 + 3][row] = qv.w * dq;
            }
            *(float4*)&Ws[lr][lc8]     = *(const float4*)&S[(size_t)(k0 + lr) * C_SZ + lc8];
            *(float4*)&Ws[lr][lc8 + 4] = *(const float4*)&S[(size_t)(k0 + lr) * C_SZ + lc8 + 4];
            __syncthreads();
#pragma unroll
            for (int kk = 0; kk < 8; kk++) {
                const ull* bp = (const ull*)&Ws[kk][tc * 8];
                ull b0 = bp[0], b1 = bp[1], b2 = bp[2], b3 = bp[3];
                const float* ap = &Qs[kk][tr * 8];
#pragma unroll
                for (int i = 0; i < 8; i++) {
                    ull a2 = pack2(ap[i]);
                    ffma2(acc[i][0], a2, b0); ffma2(acc[i][1], a2, b1);
                    ffma2(acc[i][2], a2, b2); ffma2(acc[i][3], a2, b3);
                }
            }
            __syncthreads();
        }
#pragma unroll
        for (int i = 0; i < 8; i++) {
            float* Rp = R + (size_t)(tr * 8 + i) * C_SZ + tc * 8;
            float2 p0 = *(float2*)&acc[i][0], p1 = *(float2*)&acc[i][1];
            float2 p2 = *(float2*)&acc[i][2], p3 = *(float2*)&acc[i][3];
            *(float4*)(Rp)     = make_float4(p0.x, p0.y, p1.x, p1.y);
            *(float4*)(Rp + 4) = make_float4(p2.x, p2.y, p3.x, p3.y);
        }
    }
}

// ===========================================================================
extern "C" void kernel_launch(void* const* d_in, const int* in_sizes, int n_in,
                              void* d_out, int out_size)
{
    const float* x     = (const float*)d_in[0];
    const float* basis = (const float*)d_in[1];
    const float* qc    = (const float*)d_in[2];
    const float* kc    = (const float*)d_in[3];
    const float* vc    = (const float*)d_in[4];
    const float* oc    = (const float*)d_in[5];
    const float* dl    = (const float*)d_in[6];
    const float* os    = (const float*)d_in[7];
    float* out = (float*)d_out;

    float *pWo, *pxb, *pR, *pQKV;
    __half *pxh, *pxl, *pbTh, *pbTl, *pxbh, *pxbl, *pch, *pcl, *pWoh, *pWol, *pRh, *pRl;
    cudaGetSymbolAddress((void**)&pWo,  g_Wo);
    cudaGetSymbolAddress((void**)&pxb,  g_xb);
    cudaGetSymbolAddress((void**)&pR,   g_R);
    cudaGetSymbolAddress((void**)&pQKV, g_QKV);
    cudaGetSymbolAddress((void**)&pxh,  g_xh);
    cudaGetSymbolAddress((void**)&pxl,  g_xl);
    cudaGetSymbolAddress((void**)&pbTh, g_bTh);
    cudaGetSymbolAddress((void**)&pbTl, g_bTl);
    cudaGetSymbolAddress((void**)&pxbh, g_xbh);
    cudaGetSymbolAddress((void**)&pxbl, g_xbl);
    cudaGetSymbolAddress((void**)&pch,  g_ch);
    cudaGetSymbolAddress((void**)&pcl,  g_cl);
    cudaGetSymbolAddress((void**)&pWoh, g_Woh);
    cudaGetSymbolAddress((void**)&pWol, g_Wol);
    cudaGetSymbolAddress((void**)&pRh,  g_Rh);
    cudaGetSymbolAddress((void**)&pRl,  g_Rl);

    const int SMEM2 = 3 * 3 * ARR_B;   // 92160
    const int SMEM3 = 3 * 4 * ARR_B;   // 122880
    cudaFuncSetAttribute(mma_gemm<3>, cudaFuncAttributeMaxDynamicSharedMemorySize, SMEM2);
    cudaFuncSetAttribute(mma_gemm<4>, cudaFuncAttributeMaxDynamicSharedMemorySize, SMEM3);

    // 1. basis^T split (fp16), x split, coeff splits, Wo build + split
    transpose_split<<<dim3(32, 8), dim3(32, 8)>>>(basis, pbTh, pbTl);
    split_kernel<<<(BT * V_SZ / 4 + 255) / 256, 256>>>(x, pxh, pxl, BT * V_SZ / 4, 1.0f);
    split_kernel<<<(C_SZ * C_SZ / 4 + 255) / 256, 256>>>(qc, pch, pcl, C_SZ * C_SZ / 4, 1.0f);
    split_kernel<<<(C_SZ * C_SZ / 4 + 255) / 256, 256>>>(kc, pch + C_SZ * C_SZ,
                                                         pcl + C_SZ * C_SZ, C_SZ * C_SZ / 4, 1.0f);
    split_kernel<<<(C_SZ * C_SZ / 4 + 255) / 256, 256>>>(vc, pch + 2 * C_SZ * C_SZ,
                                                         pcl + 2 * C_SZ * C_SZ, C_SZ * C_SZ / 4, 1.0f);
    sgemm_nt<<<dim3(2, 8), 256>>>(basis, oc, pWo, 1024, 256, 256);
    split_kernel<<<(V_SZ * C_SZ / 4 + 255) / 256, 256>>>(pWo, pWoh, pWol, V_SZ * C_SZ / 4, 1.0f);

    // 2. xb = x @ basis  [16384,256]  (2-term fp16, lossy stage #1)
    mma_gemm<3><<<dim3(2, 128, 1), 256, SMEM2>>>(
        pxh, pxl, pbTh, pbTh, pxb, V_SZ, 0, 0, C_SZ, nullptr, 1.0f);

    // 3. split xb, then QKV[z] = xb @ coeffs_z^T (3-term fp16, quasi-exact)
    split_kernel<<<(BT * C_SZ / 4 + 255) / 256, 256>>>(pxb, pxbh, pxbl, BT * C_SZ / 4, 1.0f);
    mma_gemm<4><<<dim3(2, 128, 3), 256, SMEM3>>>(
        pxbh, pxbl, pch, pcl, pQKV, C_SZ,
        (size_t)C_SZ * C_SZ, (size_t)BT * C_SZ, C_SZ, nullptr, 1.0f);

    // 4. Per-chunk decayed KV sums, state scan, per-chunk attention
    chunk_kv_kernel<<<dim3(2, 2, B_SZ * NCH), 256>>>(dl);
    scan_kernel<<<dim3(256, B_SZ), 256>>>(dl);
    attn_kernel<<<dim3(NCH, B_SZ), 256>>>(dl);

    // 5. Split retrieved (2^-8 pre-scale), output proj (2-term, lossy stage #2)
    split_kernel<<<(BT * C_SZ / 4 + 255) / 256, 256>>>(pR, pRh, pRl, BT * C_SZ / 4, R_SCALE);
    mma_gemm<3><<<dim3(8, 128, 1), 256, SMEM2>>>(
        pRh, pRl, pWoh, pWoh, out, C_SZ, 0, 0, V_SZ, os, R_UNSCALE);
}

// round 8
// speedup vs baseline: 2.7781x; 1.2019x over previous
#include <cuda_runtime.h>
#include <cuda_fp16.h>
#include <math.h>
#include <stdint.h>

// Problem constants
#define B_SZ 4
#define T_SZ 4096
#define V_SZ 1024
#define C_SZ 256
#define L_SZ 64                 // chunk length
#define NCH  64                 // chunks per batch (T/L)
#define BT   (B_SZ * T_SZ)      // 16384

#define R_SCALE   0.00390625f   // 2^-8 pre-scale for R (fp16 range safety)
#define R_UNSCALE 256.0f

typedef unsigned long long ull;

// ---------------- scratch (static __device__ arrays; no runtime alloc) -----
__device__ float g_Wo [V_SZ * C_SZ];
__device__ float g_xb [BT * C_SZ];
__device__ float g_QKV[3 * BT * C_SZ];
__device__ float g_AS [B_SZ * NCH * C_SZ * C_SZ];           // A^T per chunk (fp32)
__device__ float g_R  [BT * C_SZ];
// fp16 split operands
__device__ __half g_xh [BT * V_SZ];
__device__ __half g_xl [BT * V_SZ];
__device__ __half g_bTh[C_SZ * V_SZ];
__device__ __half g_bTl[C_SZ * V_SZ];
__device__ __half g_xbh[BT * C_SZ];
__device__ __half g_xbl[BT * C_SZ];
__device__ __half g_ch [3 * C_SZ * C_SZ];
__device__ __half g_cl [3 * C_SZ * C_SZ];
__device__ __half g_Woh[V_SZ * C_SZ];
__device__ __half g_Wol[V_SZ * C_SZ];
__device__ __half g_Rh [BT * C_SZ];
__device__ __half g_Rl [BT * C_SZ];
// attn fp16 operands
__device__ __half g_Qh [BT * C_SZ];
__device__ __half g_Ql [BT * C_SZ];
__device__ __half g_Kh [BT * C_SZ];
__device__ __half g_Kl [BT * C_SZ];
__device__ __half g_Vth[BT * C_SZ];          // V^T per batch: [B][C][T]
__device__ __half g_Vtl[BT * C_SZ];
__device__ __half g_Sth[B_SZ * NCH * C_SZ * C_SZ];   // S^T states hi
__device__ __half g_Stl[B_SZ * NCH * C_SZ * C_SZ];   // S^T states lo

__device__ __forceinline__ float get_decay(const float* dl) {
    return 1.0f / (1.0f + expf(-dl[0]));
}

// ---- packed fp32x2 helpers (FFMA kernels) ---------------------------------
__device__ __forceinline__ ull pack2(float x) {
    ull r;
    asm("mov.b64 %0, {%1, %1};" : "=l"(r) : "f"(x));
    return r;
}
__device__ __forceinline__ void ffma2(ull& c, ull a, ull b) {
    asm("fma.rn.f32x2 %0, %1, %2, %0;" : "+l"(c) : "l"(a), "l"(b));
}

__device__ __forceinline__ uint32_t cvta_shared(const void* p) {
    uint32_t a;
    asm("{ .reg .u64 t; cvta.to.shared.u64 t, %1; cvt.u32.u64 %0, t; }"
        : "=r"(a) : "l"(p));
    return a;
}

// ---- mma.sync / ldmatrix / cp.async helpers -------------------------------
__device__ __forceinline__ void ldsm_x4(uint32_t a, uint32_t* r) {
    asm volatile("ldmatrix.sync.aligned.m8n8.x4.shared.b16 {%0,%1,%2,%3}, [%4];"
                 : "=r"(r[0]), "=r"(r[1]), "=r"(r[2]), "=r"(r[3]) : "r"(a));
}
__device__ __forceinline__ void mma_f16(float* d, const uint32_t* a, const uint32_t* b) {
    asm volatile("mma.sync.aligned.m16n8k16.row.col.f32.f16.f16.f32 "
                 "{%0,%1,%2,%3}, {%4,%5,%6,%7}, {%8,%9}, {%0,%1,%2,%3};"
                 : "+f"(d[0]), "+f"(d[1]), "+f"(d[2]), "+f"(d[3])
                 : "r"(a[0]), "r"(a[1]), "r"(a[2]), "r"(a[3]),
                   "r"(b[0]), "r"(b[1]));
}
__device__ __forceinline__ void cp16(uint32_t dst, const void* src) {
    asm volatile("cp.async.cg.shared.global [%0], [%1], 16;" :: "r"(dst), "l"(src));
}
#define CP_COMMIT() asm volatile("cp.async.commit_group;" ::: "memory")
#define CP_WAIT1()  asm volatile("cp.async.wait_group 1;" ::: "memory")
#define CP_WAIT0()  asm volatile("cp.async.wait_group 0;" ::: "memory")

// smem geometry for mma_gemm: rows padded to 80 B
#define BK 32
#define ROWB 80
#define ARR_B (128 * ROWB)

// ===========================================================================
// fp16 tensor-core GEMM (NARR=3: 2-term, NARR=4: 3-term). As in R6.
// ===========================================================================
template <int NARR>
__global__ void __launch_bounds__(256) mma_gemm(
    const __half* __restrict__ Ahb, const __half* __restrict__ Alb,
    const __half* __restrict__ Bhb, const __half* __restrict__ Blb,
    float* __restrict__ Cbase, int K, size_t sB, size_t sC, int ldC,
    const float* __restrict__ scale_ptr, float alpha_mul)
{
    extern __shared__ __align__(16) char dynsm[];
    const uint32_t sdyn = cvta_shared(dynsm);
    const uint32_t STAGE_B = NARR * ARR_B;

    const int tid = threadIdx.x, lane = tid & 31, wid = tid >> 5;
    const int m0 = blockIdx.y * 128, n0 = blockIdx.x * 128;
    const __half* gAh = Ahb + (size_t)m0 * K;
    const __half* gAl = Alb + (size_t)m0 * K;
    const __half* gBh = Bhb + (size_t)blockIdx.z * sB + (size_t)n0 * K;
    const __half* gBl = Blb + (size_t)blockIdx.z * sB + (size_t)n0 * K;
    float* C = Cbase + (size_t)blockIdx.z * sC;

    const int warp_m = wid >> 1, warp_n = wid & 1;
    const int r8 = lane & 7, midx = lane >> 3;
    const int NC = K / BK;
    const int lr0 = tid >> 2, c4 = tid & 3;

    float acc[2][8][4];
#pragma unroll
    for (int mt = 0; mt < 2; mt++)
#pragma unroll
        for (int nt = 0; nt < 8; nt++)
#pragma unroll
            for (int r = 0; r < 4; r++) acc[mt][nt][r] = 0.0f;

    auto issue = [&](int s, int kc) {
        const int k0 = kc * BK;
        const uint32_t st = sdyn + s * STAGE_B;
#pragma unroll
        for (int h = 0; h < 2; h++) {
            const int r = lr0 + h * 64;
            const uint32_t d = st + r * ROWB + c4 * 16;
            const size_t g = (size_t)r * K + k0 + c4 * 8;
            cp16(d,             gAh + g);
            cp16(d + ARR_B,     gAl + g);
            cp16(d + 2 * ARR_B, gBh + g);
            if (NARR == 4) cp16(d + 3 * ARR_B, gBl + g);
        }
        CP_COMMIT();
    };

    issue(0, 0);
    issue(1, 1);

    for (int i = 0; i < NC; i++) {
        if (i < NC - 1) CP_WAIT1(); else CP_WAIT0();
        __syncthreads();
        if (i + 2 < NC) issue((i + 2) % 3, i + 2);

        const uint32_t stg = sdyn + (i % 3) * STAGE_B;
#pragma unroll
        for (int kh = 0; kh < 2; kh++) {
            uint32_t ah[2][4], al[2][4], bh4[4][4], bl4[4][4];
#pragma unroll
            for (int mt = 0; mt < 2; mt++) {
                const uint32_t ad = stg +
                    (warp_m * 32 + mt * 16 + (midx & 1) * 8 + r8) * ROWB +
                    (midx >> 1) * 16 + kh * 32;
                ldsm_x4(ad,         ah[mt]);
                ldsm_x4(ad + ARR_B, al[mt]);
            }
#pragma unroll
            for (int ng = 0; ng < 4; ng++) {
                const uint32_t bd = stg + 2 * ARR_B +
                    (warp_n * 64 + ng * 16 + (midx >> 1) * 8 + r8) * ROWB +
                    (midx & 1) * 16 + kh * 32;
                ldsm_x4(bd, bh4[ng]);
                if (NARR == 4) ldsm_x4(bd + ARR_B, bl4[ng]);
            }
#pragma unroll
            for (int mt = 0; mt < 2; mt++)
#pragma unroll
                for (int nt = 0; nt < 8; nt++) {
                    const uint32_t* bp = &bh4[nt >> 1][(nt & 1) * 2];
                    mma_f16(acc[mt][nt], ah[mt], bp);
                    mma_f16(acc[mt][nt], al[mt], bp);
                    if (NARR == 4) {
                        const uint32_t* blp = &bl4[nt >> 1][(nt & 1) * 2];
                        mma_f16(acc[mt][nt], ah[mt], blp);
                    }
                }
        }
    }

    const float alpha = (scale_ptr ? scale_ptr[0] : 1.0f) * alpha_mul;
    const int crow = lane >> 2, ccol = (lane & 3) * 2;
#pragma unroll
    for (int mt = 0; mt < 2; mt++)
#pragma unroll
        for (int nt = 0; nt < 8; nt++) {
            const int row = m0 + warp_m * 32 + mt * 16 + crow;
            const int col = n0 + warp_n * 64 + nt * 8 + ccol;
            float* p = C + (size_t)row * ldC + col;
            *(float2*)p = make_float2(acc[mt][nt][0] * alpha, acc[mt][nt][1] * alpha);
            *(float2*)(p + 8 * (size_t)ldC) =
                make_float2(acc[mt][nt][2] * alpha, acc[mt][nt][3] * alpha);
        }
}

// ===========================================================================
// attn via fp16 mma (3-term, quasi-exact). One block per chunk, 256 threads.
//   P = mask(Q K^T); acc = Q@St; acc *= d^(63-i); acc += P@Vt; R = acc
// Unified 18-tile cp.async pipeline: 8 K-tiles, 8 St-tiles, 2 Vt-tiles (BK=32)
// ===========================================================================
#define AQ_STR 528                 // sQ row stride bytes (264 halfs)
#define AP_STR 144                 // sP row stride bytes (72 halfs)
#define AB_STR 80                  // buf row stride bytes (40 halfs)
#define A_SQH  0
#define A_SQL  33792
#define A_SPH  67584
#define A_SPL  76800
#define A_BUF  86016               // 3 stages x (hi 20480 | lo 20480)
#define A_STG  40960
#define A_SMEM 208896

__global__ void __launch_bounds__(256) attn_mma(const float* __restrict__ dlp)
{
    extern __shared__ __align__(16) char asmm[];
    const uint32_t s0 = cvta_shared(asmm);
    const int c = blockIdx.x, b = blockIdx.y;
    const int tid = threadIdx.x, lane = tid & 31, wid = tid >> 5;
    const float lg2d = log2f(get_decay(dlp));

    const size_t nat = ((size_t)b * T_SZ + (size_t)c * L_SZ) * C_SZ;
    const __half* gQh = g_Qh + nat;
    const __half* gQl = g_Ql + nat;
    const __half* gKh = g_Kh + nat;
    const __half* gKl = g_Kl + nat;
    const size_t vt = (size_t)b * C_SZ * T_SZ + (size_t)c * L_SZ;
    const size_t st = ((size_t)(b * NCH + c)) * C_SZ * C_SZ;

    const int r8 = lane & 7, midx = lane >> 3;

    // ---- load full Q (64x256 hi/lo) ----
    {
        const int row = tid >> 2, q4 = tid & 3;
#pragma unroll
        for (int it = 0; it < 8; it++) {
            const int c16 = q4 + it * 4;
            cp16(s0 + A_SQH + row * AQ_STR + c16 * 16, gQh + row * C_SZ + c16 * 8);
            cp16(s0 + A_SQL + row * AQ_STR + c16 * 16, gQl + row * C_SZ + c16 * 8);
        }
        CP_COMMIT();
    }

    auto issue = [&](int q) {
        const uint32_t bh = s0 + A_BUF + (q % 3) * A_STG;
        const uint32_t bl = bh + 20480;
        if (q < 8) {                       // K tile: 64 rows x 32k
            const int row = tid >> 2, c16 = tid & 3;
            cp16(bh + row * AB_STR + c16 * 16, gKh + row * C_SZ + q * 32 + c16 * 8);
            cp16(bl + row * AB_STR + c16 * 16, gKl + row * C_SZ + q * 32 + c16 * 8);
        } else if (q < 16) {               // St tile: 256 rows x 32k
            const int ct = q - 8;
            const size_t src = st + (size_t)tid * C_SZ + ct * 32;
#pragma unroll
            for (int it = 0; it < 4; it++) {
                cp16(bh + tid * AB_STR + it * 16, g_Sth + src + it * 8);
                cp16(bl + tid * AB_STR + it * 16, g_Stl + src + it * 8);
            }
        } else {                           // Vt tile: 256 rows x 32t
            const int ct = q - 16;
            const size_t src = vt + (size_t)tid * T_SZ + ct * 32;
#pragma unroll
            for (int it = 0; it < 4; it++) {
                cp16(bh + tid * AB_STR + it * 16, g_Vth + src + it * 8);
                cp16(bl + tid * AB_STR + it * 16, g_Vtl + src + it * 8);
            }
        }
        CP_COMMIT();
    };

    // P-phase warp layout: 16 rows x 32 cols per warp
    const int pwm = wid & 3, pwn = wid >> 2;
    // inter/intra warp layout: 32 rows x 64 cols per warp
    const int wm = wid & 1, wn = wid >> 1;

    float accp[4][4];
#pragma unroll
    for (int a = 0; a < 4; a++)
#pragma unroll
        for (int e = 0; e < 4; e++) accp[a][e] = 0.0f;
    float acc[2][8][4];
#pragma unroll
    for (int mt = 0; mt < 2; mt++)
#pragma unroll
        for (int nt = 0; nt < 8; nt++)
#pragma unroll
            for (int e = 0; e < 4; e++) acc[mt][nt][e] = 0.0f;

    issue(0);
    issue(1);

    for (int q = 0; q < 18; q++) {
        if (q < 17) CP_WAIT1(); else CP_WAIT0();
        __syncthreads();
        if (q + 2 < 18) issue(q + 2);

        const uint32_t bh = s0 + A_BUF + (q % 3) * A_STG;
        const uint32_t bl = bh + 20480;

        if (q < 8) {
            // ---- P phase: A = Q[16 rows], B = K tile ----
#pragma unroll
            for (int ks = 0; ks < 2; ks++) {
                uint32_t ah[4], al[4];
                const uint32_t ad = s0 + A_SQH +
                    (pwm * 16 + (midx & 1) * 8 + r8) * AQ_STR +
                    (q * 32 + ks * 16 + (midx >> 1) * 8) * 2;
                ldsm_x4(ad, ah);
                ldsm_x4(ad + (A_SQL - A_SQH), al);
#pragma unroll
                for (int ng = 0; ng < 2; ng++) {
                    uint32_t bhf[4], blf[4];
                    const uint32_t bd = bh +
                        (pwn * 32 + ng * 16 + (midx >> 1) * 8 + r8) * AB_STR +
                        (ks * 16 + (midx & 1) * 8) * 2;
                    ldsm_x4(bd, bhf);
                    ldsm_x4(bd + 20480, blf);
#pragma unroll
                    for (int sub = 0; sub < 2; sub++) {
                        float* A = accp[ng * 2 + sub];
                        mma_f16(A, ah, &bhf[sub * 2]);
                        mma_f16(A, al, &bhf[sub * 2]);
                        mma_f16(A, ah, &blf[sub * 2]);
                    }
                }
            }
            if (q == 7) {
                // P epilogue: mask + decay, split to sP hi/lo
                const int prow = pwm * 16 + (lane >> 2);
#pragma unroll
                for (int nt = 0; nt < 4; nt++)
#pragma unroll
                    for (int e = 0; e < 4; e++) {
                        const int i = prow + (e >> 1) * 8;
                        const int j = pwn * 32 + nt * 8 + (lane & 3) * 2 + (e & 1);
                        float v = (j > i)
                            ? accp[nt][e] * exp2f((float)(j - i - 1) * lg2d) : 0.0f;
                        __half h = __float2half_rn(v);
                        *(__half*)(asmm + A_SPH + i * AP_STR + j * 2) = h;
                        *(__half*)(asmm + A_SPL + i * AP_STR + j * 2) =
                            __float2half_rn(v - __half2float(h));
                    }
            }
        } else if (q < 16) {
            // ---- inter: acc += Q @ St-tile ----
            const int ct = q - 8;
#pragma unroll
            for (int ks = 0; ks < 2; ks++) {
                uint32_t ah[2][4], al[2][4], bh4[4][4], bl4[4][4];
#pragma unroll
                for (int mt = 0; mt < 2; mt++) {
                    const uint32_t ad = s0 + A_SQH +
                        (wm * 32 + mt * 16 + (midx & 1) * 8 + r8) * AQ_STR +
                        (ct * 32 + ks * 16 + (midx >> 1) * 8) * 2;
                    ldsm_x4(ad, ah[mt]);
                    ldsm_x4(ad + (A_SQL - A_SQH), al[mt]);
                }
#pragma unroll
                for (int ng = 0; ng < 4; ng++) {
                    const uint32_t bd = bh +
                        (wn * 64 + ng * 16 + (midx >> 1) * 8 + r8) * AB_STR +
                        (ks * 16 + (midx & 1) * 8) * 2;
                    ldsm_x4(bd, bh4[ng]);
                    ldsm_x4(bd + 20480, bl4[ng]);
                }
#pragma unroll
                for (int mt = 0; mt < 2; mt++)
#pragma unroll
                    for (int nt = 0; nt < 8; nt++) {
                        const uint32_t* bp  = &bh4[nt >> 1][(nt & 1) * 2];
                        const uint32_t* blp = &bl4[nt >> 1][(nt & 1) * 2];
                        mma_f16(acc[mt][nt], ah[mt], bp);
                        mma_f16(acc[mt][nt], al[mt], bp);
                        mma_f16(acc[mt][nt], ah[mt], blp);
                    }
            }
            if (q == 15) {
                // scale inter contribution by d^(63-i) (fp32, exact)
#pragma unroll
                for (int mt = 0; mt < 2; mt++) {
                    const int i0 = wm * 32 + mt * 16 + (lane >> 2);
                    const float sA = exp2f((float)(63 - i0) * lg2d);
                    const float sB = exp2f((float)(55 - i0) * lg2d);  // 63-(i0+8)
#pragma unroll
                    for (int nt = 0; nt < 8; nt++) {
                        acc[mt][nt][0] *= sA; acc[mt][nt][1] *= sA;
                        acc[mt][nt][2] *= sB; acc[mt][nt][3] *= sB;
                    }
                }
            }
        } else {
            // ---- intra: acc += P @ Vt-tile ----
            const int ct = q - 16;
#pragma unroll
            for (int ks = 0; ks < 2; ks++) {
                uint32_t ah[2][4], al[2][4], bh4[4][4], bl4[4][4];
#pragma unroll
                for (int mt = 0; mt < 2; mt++) {
                    const uint32_t ad = s0 + A_SPH +
                        (wm * 32 + mt * 16 + (midx & 1) * 8 + r8) * AP_STR +
                        (ct * 32 + ks * 16 + (midx >> 1) * 8) * 2;
                    ldsm_x4(ad, ah[mt]);
                    ldsm_x4(ad + (A_SPL - A_SPH), al[mt]);
                }
#pragma unroll
                for (int ng = 0; ng < 4; ng++) {
                    const uint32_t bd = bh +
                        (wn * 64 + ng * 16 + (midx >> 1) * 8 + r8) * AB_STR +
                        (ks * 16 + (midx & 1) * 8) * 2;
                    ldsm_x4(bd, bh4[ng]);
                    ldsm_x4(bd + 20480, bl4[ng]);
                }
#pragma unroll
                for (int mt = 0; mt < 2; mt++)
#pragma unroll
                    for (int nt = 0; nt < 8; nt++) {
                        const uint32_t* bp  = &bh4[nt >> 1][(nt & 1) * 2];
                        const uint32_t* blp = &bl4[nt >> 1][(nt & 1) * 2];
                        mma_f16(acc[mt][nt], ah[mt], bp);
                        mma_f16(acc[mt][nt], al[mt], bp);
                        mma_f16(acc[mt][nt], ah[mt], blp);
                    }
            }
        }
    }

    // ---- write R ----
    float* R = g_R + nat;
#pragma unroll
    for (int mt = 0; mt < 2; mt++)
#pragma unroll
        for (int nt = 0; nt < 8; nt++) {
            const int row = wm * 32 + mt * 16 + (lane >> 2);
            const int col = wn * 64 + nt * 8 + (lane & 3) * 2;
            *(float2*)(R + (size_t)row * C_SZ + col) =
                make_float2(acc[mt][nt][0], acc[mt][nt][1]);
            *(float2*)(R + (size_t)(row + 8) * C_SZ + col) =
                make_float2(acc[mt][nt][2], acc[mt][nt][3]);
        }
}

// ===========================================================================
// fp32 -> (hi, lo) fp16 split with pre-scale, vectorized by 4
// ===========================================================================
__global__ void split_kernel(const float* __restrict__ s,
                             __half* __restrict__ h,
                             __half* __restrict__ l, int n4, float sc)
{
    int i = blockIdx.x * blockDim.x + threadIdx.x;
    if (i >= n4) return;
    float4 v = ((const float4*)s)[i];
    v.x *= sc; v.y *= sc; v.z *= sc; v.w *= sc;
    __half h0 = __float2half_rn(v.x), h1 = __float2half_rn(v.y);
    __half h2 = __float2half_rn(v.z), h3 = __float2half_rn(v.w);
    __half l0 = __float2half_rn(v.x - __half2float(h0));
    __half l1 = __float2half_rn(v.y - __half2float(h1));
    __half l2 = __float2half_rn(v.z - __half2float(h2));
    __half l3 = __float2half_rn(v.w - __half2float(h3));
    ((__half2*)h)[2 * i]     = __half2(h0, h1);
    ((__half2*)h)[2 * i + 1] = __half2(h2, h3);
    ((__half2*)l)[2 * i]     = __half2(l0, l1);
    ((__half2*)l)[2 * i + 1] = __half2(l2, l3);
}

// ===========================================================================
// basis [1024,256] -> basis^T fp16 hi/lo
// ===========================================================================
__global__ void transpose_split(const float* __restrict__ in,
                                __half* __restrict__ oh, __half* __restrict__ ol)
{
    __shared__ float t[32][33];
    const int v0 = blockIdx.x * 32, c0 = blockIdx.y * 32;
    const int tx = threadIdx.x, ty = threadIdx.y;
#pragma unroll
    for (int j = 0; j < 32; j += 8)
        t[ty + j][tx] = in[(size_t)(v0 + ty + j) * C_SZ + c0 + tx];
    __syncthreads();
#pragma unroll
    for (int j = 0; j < 32; j += 8) {
        float val = t[tx][ty + j];
        __half h = __float2half_rn(val);
        oh[(size_t)(c0 + ty + j) * V_SZ + v0 + tx] = h;
        ol[(size_t)(c0 + ty + j) * V_SZ + v0 + tx] =
            __float2half_rn(val - __half2float(h));
    }
}

// ===========================================================================
// V [B*T, C] fp32 -> V^T [B][C][T] fp16 hi/lo.  grid (T/32, C/32, B)
// ===========================================================================
__global__ void transpose_split_v(const float* __restrict__ in,
                                  __half* __restrict__ oh, __half* __restrict__ ol)
{
    __shared__ float t[32][33];
    const int b = blockIdx.z;
    const int t0 = blockIdx.x * 32, c0 = blockIdx.y * 32;
    const int tx = threadIdx.x, ty = threadIdx.y;
#pragma unroll
    for (int j = 0; j < 32; j += 8)
        t[ty + j][tx] = in[((size_t)b * T_SZ + t0 + ty + j) * C_SZ + c0 + tx];
    __syncthreads();
#pragma unroll
    for (int j = 0; j < 32; j += 8) {
        float val = t[tx][ty + j];
        __half h = __float2half_rn(val);
        const size_t o = (size_t)b * C_SZ * T_SZ + (size_t)(c0 + ty + j) * T_SZ + t0 + tx;
        oh[o] = h;
        ol[o] = __float2half_rn(val - __half2float(h));
    }
}

// ===========================================================================
// 128x128x8 SGEMM nt (f32x2). Wo build only.
// ===========================================================================
__global__ void __launch_bounds__(256) sgemm_nt(
    const float* __restrict__ A, const float* __restrict__ B,
    float* __restrict__ C, int M, int N, int K)
{
    __shared__ __align__(16) float As[8][128];
    __shared__ __align__(16) float Bs[8][128];
    const int tid = threadIdx.x;
    const int m0 = blockIdx.y * 128, n0 = blockIdx.x * 128;
    const int tr = tid >> 4, tc = tid & 15;
    const int ar = tid >> 1, ac = (tid & 1) * 4;
    ull acc[8][4] = {};
    const float* Aptr = A + (size_t)(m0 + ar) * K + ac;
    const float* Bptr = B + (size_t)(n0 + ar) * K + ac;
    for (int k0 = 0; k0 < K; k0 += 8) {
        float4 av = *(const float4*)(Aptr + k0);
        As[ac + 0][ar] = av.x; As[ac + 1][ar] = av.y;
        As[ac + 2][ar] = av.z; As[ac + 3][ar] = av.w;
        float4 bv = *(const float4*)(Bptr + k0);
        Bs[ac + 0][ar] = bv.x; Bs[ac + 1][ar] = bv.y;
        Bs[ac + 2][ar] = bv.z; Bs[ac + 3][ar] = bv.w;
        __syncthreads();
#pragma unroll
        for (int kk = 0; kk < 8; kk++) {
            const ull* bp = (const ull*)&Bs[kk][tc * 8];
            ull b0 = bp[0], b1 = bp[1], b2 = bp[2], b3 = bp[3];
            const float* ap = &As[kk][tr * 8];
#pragma unroll
            for (int i = 0; i < 8; i++) {
                ull a2 = pack2(ap[i]);
                ffma2(acc[i][0], a2, b0); ffma2(acc[i][1], a2, b1);
                ffma2(acc[i][2], a2, b2); ffma2(acc[i][3], a2, b3);
            }
        }
        __syncthreads();
    }
#pragma unroll
    for (int i = 0; i < 8; i++) {
        float* Cp = C + (size_t)(m0 + tr * 8 + i) * N + n0 + tc * 8;
        float2 p0 = *(float2*)&acc[i][0], p1 = *(float2*)&acc[i][1];
        float2 p2 = *(float2*)&acc[i][2], p3 = *(float2*)&acc[i][3];
        *(float4*)(Cp)     = make_float4(p0.x, p0.y, p1.x, p1.y);
        *(float4*)(Cp + 4) = make_float4(p2.x, p2.y, p3.x, p3.y);
    }
}

// ===========================================================================
// Per-chunk decayed KV sums, emitting A^T: out[c2][c1] = sum_r d^r V[r,c2] K[r,c1]
// ===========================================================================
__global__ void __launch_bounds__(256) chunk_kv_kernel(const float* __restrict__ dlp)
{
    const int z = blockIdx.z;
    const int b = z >> 6, c = z & 63;
    const size_t rowbase = ((size_t)b * T_SZ + (size_t)c * L_SZ) * C_SZ;
    const float* Ap = g_QKV + 2 * (size_t)BT * C_SZ + rowbase;   // V (decayed, m=c2)
    const float* Bp = g_QKV + (size_t)BT * C_SZ + rowbase;       // K (n=c1)
    float* Cp = g_AS + (size_t)z * C_SZ * C_SZ;
    const float decay = get_decay(dlp);
    const float lg2d = log2f(decay);

    __shared__ __align__(16) float As[8][128];
    __shared__ __align__(16) float Bs[8][128];
    const int tid = threadIdx.x;
    const int m0 = blockIdx.y * 128, n0 = blockIdx.x * 128;
    const int tr = tid >> 4, tc = tid & 15;
    const int lr = tid >> 5, lc = (tid & 31) * 4;
    ull acc[8][4] = {};
    for (int k0 = 0; k0 < L_SZ; k0 += 8) {
        const float sc = exp2f((float)(k0 + lr) * lg2d);
        float4 av = *(const float4*)&Ap[(size_t)(k0 + lr) * C_SZ + m0 + lc];
        av.x *= sc; av.y *= sc; av.z *= sc; av.w *= sc;
        *(float4*)&As[lr][lc] = av;
        *(float4*)&Bs[lr][lc] = *(const float4*)&Bp[(size_t)(k0 + lr) * C_SZ + n0 + lc];
        __syncthreads();
#pragma unroll
        for (int kk = 0; kk < 8; kk++) {
            const ull* bp = (const ull*)&Bs[kk][tc * 8];
            ull b0 = bp[0], b1 = bp[1], b2 = bp[2], b3 = bp[3];
            const float* ap = &As[kk][tr * 8];
#pragma unroll
            for (int i = 0; i < 8; i++) {
                ull a2 = pack2(ap[i]);
                ffma2(acc[i][0], a2, b0); ffma2(acc[i][1], a2, b1);
                ffma2(acc[i][2], a2, b2); ffma2(acc[i][3], a2, b3);
            }
        }
        __syncthreads();
    }
#pragma unroll
    for (int i = 0; i < 8; i++) {
        float* Op = Cp + (size_t)(m0 + tr * 8 + i) * C_SZ + n0 + tc * 8;
        float2 p0 = *(float2*)&acc[i][0], p1 = *(float2*)&acc[i][1];
        float2 p2 = *(float2*)&acc[i][2], p3 = *(float2*)&acc[i][3];
        *(float4*)(Op)     = make_float4(p0.x, p0.y, p1.x, p1.y);
        *(float4*)(Op + 4) = make_float4(p2.x, p2.y, p3.x, p3.y);
    }
}

// ===========================================================================
// Backward state scan: writes S^T states as fp16 hi/lo
// ===========================================================================
__global__ void scan_kernel(const float* __restrict__ dlp)
{
    const int e = blockIdx.x * blockDim.x + threadIdx.x;
    const int b = blockIdx.y;
    const float decay = get_decay(dlp);
    const float dL = exp2f((float)L_SZ * log2f(decay));
    float run = 0.0f;
    const size_t base = (size_t)b * NCH * (C_SZ * C_SZ) + e;
    for (int c = NCH - 1; c >= 0; c--) {
        const size_t pos = base + (size_t)c * (C_SZ * C_SZ);
        __half h = __float2half_rn(run);
        g_Sth[pos] = h;
        g_Stl[pos] = __float2half_rn(run - __half2float(h));
        run = fmaf(dL, run, g_AS[pos]);
    }
}

// ===========================================================================
extern "C" void kernel_launch(void* const* d_in, const int* in_sizes, int n_in,
                              void* d_out, int out_size)
{
    const float* x     = (const float*)d_in[0];
    const float* basis = (const float*)d_in[1];
    const float* qc    = (const float*)d_in[2];
    const float* kc    = (const float*)d_in[3];
    const float* vc    = (const float*)d_in[4];
    const float* oc    = (const float*)d_in[5];
    const float* dl    = (const float*)d_in[6];
    const float* os    = (const float*)d_in[7];
    float* out = (float*)d_out;

    float *pWo, *pxb, *pR, *pQKV;
    __half *pxh, *pxl, *pbTh, *pbTl, *pxbh, *pxbl, *pch, *pcl, *pWoh, *pWol, *pRh, *pRl;
    __half *pQh, *pQl, *pKh, *pKl, *pVth, *pVtl;
    cudaGetSymbolAddress((void**)&pWo,  g_Wo);
    cudaGetSymbolAddress((void**)&pxb,  g_xb);
    cudaGetSymbolAddress((void**)&pR,   g_R);
    cudaGetSymbolAddress((void**)&pQKV, g_QKV);
    cudaGetSymbolAddress((void**)&pxh,  g_xh);
    cudaGetSymbolAddress((void**)&pxl,  g_xl);
    cudaGetSymbolAddress((void**)&pbTh, g_bTh);
    cudaGetSymbolAddress((void**)&pbTl, g_bTl);
    cudaGetSymbolAddress((void**)&pxbh, g_xbh);
    cudaGetSymbolAddress((void**)&pxbl, g_xbl);
    cudaGetSymbolAddress((void**)&pch,  g_ch);
    cudaGetSymbolAddress((void**)&pcl,  g_cl);
    cudaGetSymbolAddress((void**)&pWoh, g_Woh);
    cudaGetSymbolAddress((void**)&pWol, g_Wol);
    cudaGetSymbolAddress((void**)&pRh,  g_Rh);
    cudaGetSymbolAddress((void**)&pRl,  g_Rl);
    cudaGetSymbolAddress((void**)&pQh,  g_Qh);
    cudaGetSymbolAddress((void**)&pQl,  g_Ql);
    cudaGetSymbolAddress((void**)&pKh,  g_Kh);
    cudaGetSymbolAddress((void**)&pKl,  g_Kl);
    cudaGetSymbolAddress((void**)&pVth, g_Vth);
    cudaGetSymbolAddress((void**)&pVtl, g_Vtl);

    const int SMEM2 = 3 * 3 * ARR_B;
    cudaFuncSetAttribute(mma_gemm<3>, cudaFuncAttributeMaxDynamicSharedMemorySize, SMEM2);
    cudaFuncSetAttribute(attn_mma, cudaFuncAttributeMaxDynamicSharedMemorySize, A_SMEM);

    // 1. prep: basis^T split, x split, coeff splits, Wo build + split
    transpose_split<<<dim3(32, 8), dim3(32, 8)>>>(basis, pbTh, pbTl);
    split_kernel<<<(BT * V_SZ / 4 + 255) / 256, 256>>>(x, pxh, pxl, BT * V_SZ / 4, 1.0f);
    split_kernel<<<(C_SZ * C_SZ / 4 + 255) / 256, 256>>>(qc, pch, pcl, C_SZ * C_SZ / 4, 1.0f);
    split_kernel<<<(C_SZ * C_SZ / 4 + 255) / 256, 256>>>(kc, pch + C_SZ * C_SZ,
                                                         pcl + C_SZ * C_SZ, C_SZ * C_SZ / 4, 1.0f);
    split_kernel<<<(C_SZ * C_SZ / 4 + 255) / 256, 256>>>(vc, pch + 2 * C_SZ * C_SZ,
                                                         pcl + 2 * C_SZ * C_SZ, C_SZ * C_SZ / 4, 1.0f);
    sgemm_nt<<<dim3(2, 8), 256>>>(basis, oc, pWo, 1024, 256, 256);
    split_kernel<<<(V_SZ * C_SZ / 4 + 255) / 256, 256>>>(pWo, pWoh, pWol, V_SZ * C_SZ / 4, 1.0f);

    // 2. xb = x @ basis (2-term, lossy stage #1)
    mma_gemm<3><<<dim3(2, 128, 1), 256, SMEM2>>>(
        pxh, pxl, pbTh, pbTh, pxb, V_SZ, 0, 0, C_SZ, nullptr, 1.0f);

    // 3. QKV = xb @ coeffs^T (2-term, lossy stage #2)
    split_kernel<<<(BT * C_SZ / 4 + 255) / 256, 256>>>(pxb, pxbh, pxbl, BT * C_SZ / 4, 1.0f);
    mma_gemm<3><<<dim3(2, 128, 3), 256, SMEM2>>>(
        pxbh, pxbl, pch, pch, pQKV, C_SZ,
        (size_t)C_SZ * C_SZ, (size_t)BT * C_SZ, C_SZ, nullptr, 1.0f);

    // 4. attn operand prep: Q/K natural splits, V^T split
    split_kernel<<<(BT * C_SZ / 4 + 255) / 256, 256>>>(pQKV, pQh, pQl, BT * C_SZ / 4, 1.0f);
    split_kernel<<<(BT * C_SZ / 4 + 255) / 256, 256>>>(pQKV + (size_t)BT * C_SZ,
                                                       pKh, pKl, BT * C_SZ / 4, 1.0f);
    transpose_split_v<<<dim3(128, 8, B_SZ), dim3(32, 8)>>>(
        pQKV + 2 * (size_t)BT * C_SZ, pVth, pVtl);

    // 5. chunk KV sums (A^T), scan -> fp16 states, attn on tensor cores
    chunk_kv_kernel<<<dim3(2, 2, B_SZ * NCH), 256>>>(dl);
    scan_kernel<<<dim3(256, B_SZ), 256>>>(dl);
    attn_mma<<<dim3(NCH, B_SZ), 256, A_SMEM>>>(dl);

    // 6. output projection (2-term, lossy stage #3 shares Wo rounding)
    split_kernel<<<(BT * C_SZ / 4 + 255) / 256, 256>>>(pR, pRh, pRl, BT * C_SZ / 4, R_SCALE);
    mma_gemm<3><<<dim3(8, 128, 1), 256, SMEM2>>>(
        pRh, pRl, pWoh, pWoh, out, C_SZ, 0, 0, V_SZ, os, R_UNSCALE);
}

// round 9
// speedup vs baseline: 3.2372x; 1.1653x over previous
#include <cuda_runtime.h>
#include <cuda_fp16.h>
#include <math.h>
#include <stdint.h>

// Problem constants
#define B_SZ 4
#define T_SZ 4096
#define V_SZ 1024
#define C_SZ 256
#define L_SZ 64
#define NCH  64
#define BT   (B_SZ * T_SZ)

#define R_SCALE   0.00390625f
#define R_UNSCALE 256.0f

typedef unsigned long long ull;

// ---------------- scratch ---------------------------------------------------
__device__ float g_Wo [V_SZ * C_SZ];
__device__ float g_QKV[3 * BT * C_SZ];       // only V slab (z=2) written fp32
__device__ float g_AS [B_SZ * NCH * C_SZ * C_SZ];   // A^T per chunk (fp32)
__device__ __half g_xh [BT * V_SZ];
__device__ __half g_xl [BT * V_SZ];
__device__ __half g_bTh[C_SZ * V_SZ];
__device__ __half g_bTl[C_SZ * V_SZ];
__device__ __half g_xbh[BT * C_SZ];
__device__ __half g_xbl[BT * C_SZ];
__device__ __half g_ch [3 * C_SZ * C_SZ];
__device__ __half g_cl [3 * C_SZ * C_SZ];    // written by split, unused (2-term)
__device__ __half g_Woh[V_SZ * C_SZ];
__device__ __half g_Wol[V_SZ * C_SZ];        // dump
__device__ __half g_QKh[2 * BT * C_SZ];      // Q,K hi (from QKV epilogue)
__device__ __half g_QKl[2 * BT * C_SZ];
__device__ __half g_Vdth[BT * C_SZ];         // decayed V^T [B][C][T] hi
__device__ __half g_Vdtl[BT * C_SZ];
__device__ __half g_Kth[BT * C_SZ];          // K^T [B][C][T] hi
__device__ __half g_Sth[B_SZ * NCH * C_SZ * C_SZ];  // d^64 * S^T states, hi
__device__ __half g_Rh [BT * C_SZ];
__device__ __half g_Rl [BT * C_SZ];

__device__ __forceinline__ float get_decay(const float* dl) {
    return 1.0f / (1.0f + expf(-dl[0]));
}

// ---- packed fp32x2 (Wo build only) ----------------------------------------
__device__ __forceinline__ ull pack2(float x) {
    ull r; asm("mov.b64 %0, {%1, %1};" : "=l"(r) : "f"(x)); return r;
}
__device__ __forceinline__ void ffma2(ull& c, ull a, ull b) {
    asm("fma.rn.f32x2 %0, %1, %2, %0;" : "+l"(c) : "l"(a), "l"(b));
}
__device__ __forceinline__ uint32_t cvta_shared(const void* p) {
    uint32_t a;
    asm("{ .reg .u64 t; cvta.to.shared.u64 t, %1; cvt.u32.u64 %0, t; }"
        : "=r"(a) : "l"(p));
    return a;
}

// ---- mma.sync / ldmatrix / cp.async ---------------------------------------
__device__ __forceinline__ void ldsm_x4(uint32_t a, uint32_t* r) {
    asm volatile("ldmatrix.sync.aligned.m8n8.x4.shared.b16 {%0,%1,%2,%3}, [%4];"
                 : "=r"(r[0]), "=r"(r[1]), "=r"(r[2]), "=r"(r[3]) : "r"(a));
}
__device__ __forceinline__ void mma_f16(float* d, const uint32_t* a, const uint32_t* b) {
    asm volatile("mma.sync.aligned.m16n8k16.row.col.f32.f16.f16.f32 "
                 "{%0,%1,%2,%3}, {%4,%5,%6,%7}, {%8,%9}, {%0,%1,%2,%3};"
                 : "+f"(d[0]), "+f"(d[1]), "+f"(d[2]), "+f"(d[3])
                 : "r"(a[0]), "r"(a[1]), "r"(a[2]), "r"(a[3]),
                   "r"(b[0]), "r"(b[1]));
}
__device__ __forceinline__ void cp16(uint32_t dst, const void* src) {
    asm volatile("cp.async.cg.shared.global [%0], [%1], 16;" :: "r"(dst), "l"(src));
}
#define CP_COMMIT() asm volatile("cp.async.commit_group;" ::: "memory")
#define CP_WAIT1()  asm volatile("cp.async.wait_group 1;" ::: "memory")
#define CP_WAIT0()  asm volatile("cp.async.wait_group 0;" ::: "memory")

__device__ __forceinline__ void split_store2(__half* H, __half* L, float v0, float v1) {
    __half h0 = __float2half_rn(v0), h1 = __float2half_rn(v1);
    *(__half2*)H = __half2(h0, h1);
    *(__half2*)L = __half2(__float2half_rn(v0 - __half2float(h0)),
                           __float2half_rn(v1 - __half2float(h1)));
}

// smem geometry for mma_gemm
#define BK 32
#define ROWB 80
#define ARR_B (128 * ROWB)

// ===========================================================================
// fp16 2-term tensor-core GEMM: C = (Ah+Al) @ Bh^T, fp32 accum.
// Epilogue: z < nhz -> write fp16 hi/lo split (Hout/Lout + z*sH),
//           else fp32 (Cbase + z*sC), scaled by (*scale_ptr)*alpha_mul.
// ===========================================================================
__global__ void __launch_bounds__(256) mma_gemm(
    const __half* __restrict__ Ahb, const __half* __restrict__ Alb,
    const __half* __restrict__ Bhb,
    float* __restrict__ Cbase, __half* __restrict__ Hout, __half* __restrict__ Lout,
    int nhz, size_t sH, int K, size_t sB, size_t sC, int ldC,
    const float* __restrict__ scale_ptr, float alpha_mul)
{
    extern __shared__ __align__(16) char dynsm[];
    const uint32_t sdyn = cvta_shared(dynsm);
    const uint32_t STAGE_B = 3 * ARR_B;

    const int tid = threadIdx.x, lane = tid & 31, wid = tid >> 5;
    const int m0 = blockIdx.y * 128, n0 = blockIdx.x * 128;
    const int z = blockIdx.z;
    const __half* gAh = Ahb + (size_t)m0 * K;
    const __half* gAl = Alb + (size_t)m0 * K;
    const __half* gBh = Bhb + (size_t)z * sB + (size_t)n0 * K;

    const int warp_m = wid >> 1, warp_n = wid & 1;
    const int r8 = lane & 7, midx = lane >> 3;
    const int NC = K / BK;
    const int lr0 = tid >> 2, c4 = tid & 3;

    float acc[2][8][4];
#pragma unroll
    for (int mt = 0; mt < 2; mt++)
#pragma unroll
        for (int nt = 0; nt < 8; nt++)
#pragma unroll
            for (int r = 0; r < 4; r++) acc[mt][nt][r] = 0.0f;

    auto issue = [&](int s, int kc) {
        const int k0 = kc * BK;
        const uint32_t st = sdyn + s * STAGE_B;
#pragma unroll
        for (int h = 0; h < 2; h++) {
            const int r = lr0 + h * 64;
            const uint32_t d = st + r * ROWB + c4 * 16;
            const size_t g = (size_t)r * K + k0 + c4 * 8;
            cp16(d,             gAh + g);
            cp16(d + ARR_B,     gAl + g);
            cp16(d + 2 * ARR_B, gBh + g);
        }
        CP_COMMIT();
    };

    issue(0, 0);
    issue(1, 1);

    for (int i = 0; i < NC; i++) {
        if (i < NC - 1) CP_WAIT1(); else CP_WAIT0();
        __syncthreads();
        if (i + 2 < NC) issue((i + 2) % 3, i + 2);

        const uint32_t stg = sdyn + (i % 3) * STAGE_B;
#pragma unroll
        for (int kh = 0; kh < 2; kh++) {
            uint32_t ah[2][4], al[2][4], bh4[4][4];
#pragma unroll
            for (int mt = 0; mt < 2; mt++) {
                const uint32_t ad = stg +
                    (warp_m * 32 + mt * 16 + (midx & 1) * 8 + r8) * ROWB +
                    (midx >> 1) * 16 + kh * 32;
                ldsm_x4(ad,         ah[mt]);
                ldsm_x4(ad + ARR_B, al[mt]);
            }
#pragma unroll
            for (int ng = 0; ng < 4; ng++) {
                const uint32_t bd = stg + 2 * ARR_B +
                    (warp_n * 64 + ng * 16 + (midx >> 1) * 8 + r8) * ROWB +
                    (midx & 1) * 16 + kh * 32;
                ldsm_x4(bd, bh4[ng]);
            }
#pragma unroll
            for (int mt = 0; mt < 2; mt++)
#pragma unroll
                for (int nt = 0; nt < 8; nt++) {
                    const uint32_t* bp = &bh4[nt >> 1][(nt & 1) * 2];
                    mma_f16(acc[mt][nt], ah[mt], bp);
                    mma_f16(acc[mt][nt], al[mt], bp);
                }
        }
    }

    const float alpha = (scale_ptr ? scale_ptr[0] : 1.0f) * alpha_mul;
    const int crow = lane >> 2, ccol = (lane & 3) * 2;
    if (z < nhz) {
        __half* H = Hout + (size_t)z * sH;
        __half* L = Lout + (size_t)z * sH;
#pragma unroll
        for (int mt = 0; mt < 2; mt++)
#pragma unroll
            for (int nt = 0; nt < 8; nt++) {
                const int row = m0 + warp_m * 32 + mt * 16 + crow;
                const int col = n0 + warp_n * 64 + nt * 8 + ccol;
                const size_t o = (size_t)row * ldC + col;
                split_store2(H + o, L + o,
                             acc[mt][nt][0] * alpha, acc[mt][nt][1] * alpha);
                const size_t o2 = o + 8 * (size_t)ldC;
                split_store2(H + o2, L + o2,
                             acc[mt][nt][2] * alpha, acc[mt][nt][3] * alpha);
            }
    } else {
        float* C = Cbase + (size_t)z * sC;
#pragma unroll
        for (int mt = 0; mt < 2; mt++)
#pragma unroll
            for (int nt = 0; nt < 8; nt++) {
                const int row = m0 + warp_m * 32 + mt * 16 + crow;
                const int col = n0 + warp_n * 64 + nt * 8 + ccol;
                float* p = C + (size_t)row * ldC + col;
                *(float2*)p = make_float2(acc[mt][nt][0] * alpha, acc[mt][nt][1] * alpha);
                *(float2*)(p + 8 * (size_t)ldC) =
                    make_float2(acc[mt][nt][2] * alpha, acc[mt][nt][3] * alpha);
            }
    }
}

// ===========================================================================
// chunk_mma: A^T[c2][c1] = sum_r d^r V[r,c2] K[r,c1] per chunk (fp32 out)
// A = decayed V^T hi/lo (2-term), B = K^T hi. Block 128x128, K=64, one shot.
// grid (2, 2, B*NCH)
// ===========================================================================
#define CK_STR 144
#define CK_AH 0
#define CK_AL 18432
#define CK_B  36864
#define CK_SMEM 55296

__global__ void __launch_bounds__(256) chunk_mma()
{
    extern __shared__ __align__(16) char csm[];
    const uint32_t s0 = cvta_shared(csm);
    const int z = blockIdx.z, b = z >> 6, c = z & 63;
    const int m0 = blockIdx.y * 128, n0 = blockIdx.x * 128;
    const int tid = threadIdx.x, lane = tid & 31, wid = tid >> 5;
    const int r8 = lane & 7, midx = lane >> 3;

    const size_t tb = (size_t)b * C_SZ * T_SZ + (size_t)c * 64;
    const __half* gAh = g_Vdth + tb + (size_t)m0 * T_SZ;
    const __half* gAl = g_Vdtl + tb + (size_t)m0 * T_SZ;
    const __half* gB  = g_Kth  + tb + (size_t)n0 * T_SZ;

    {
        const int row = tid >> 1, c2_ = tid & 1;
#pragma unroll
        for (int it = 0; it < 4; it++) {
            const int cc = c2_ + it * 2;
            const size_t g = (size_t)row * T_SZ + cc * 8;
            cp16(s0 + CK_AH + row * CK_STR + cc * 16, gAh + g);
            cp16(s0 + CK_AL + row * CK_STR + cc * 16, gAl + g);
            cp16(s0 + CK_B  + row * CK_STR + cc * 16, gB + g);
        }
        CP_COMMIT();
    }
    CP_WAIT0();
    __syncthreads();

    const int wm = wid >> 1, wn = wid & 1;
    float acc[2][8][4];
#pragma unroll
    for (int mt = 0; mt < 2; mt++)
#pragma unroll
        for (int nt = 0; nt < 8; nt++)
#pragma unroll
            for (int e = 0; e < 4; e++) acc[mt][nt][e] = 0.0f;

#pragma unroll
    for (int ks = 0; ks < 4; ks++) {
        uint32_t ah[2][4], al[2][4], bt[4][4];
#pragma unroll
        for (int mt = 0; mt < 2; mt++) {
            const uint32_t ad = s0 + CK_AH +
                (wm * 32 + mt * 16 + (midx & 1) * 8 + r8) * CK_STR +
                (ks * 16 + (midx >> 1) * 8) * 2;
            ldsm_x4(ad, ah[mt]);
            ldsm_x4(ad + (CK_AL - CK_AH), al[mt]);
        }
#pragma unroll
        for (int ng = 0; ng < 4; ng++) {
            const uint32_t bd = s0 + CK_B +
                (wn * 64 + ng * 16 + (midx >> 1) * 8 + r8) * CK_STR +
                (ks * 16 + (midx & 1) * 8) * 2;
            ldsm_x4(bd, bt[ng]);
        }
#pragma unroll
        for (int mt = 0; mt < 2; mt++)
#pragma unroll
            for (int nt = 0; nt < 8; nt++) {
                const uint32_t* bp = &bt[nt >> 1][(nt & 1) * 2];
                mma_f16(acc[mt][nt], ah[mt], bp);
                mma_f16(acc[mt][nt], al[mt], bp);
            }
    }

    float* O = g_AS + (size_t)z * C_SZ * C_SZ;
    const int crow = lane >> 2, ccol = (lane & 3) * 2;
#pragma unroll
    for (int mt = 0; mt < 2; mt++)
#pragma unroll
        for (int nt = 0; nt < 8; nt++) {
            const int row = m0 + wm * 32 + mt * 16 + crow;
            const int col = n0 + wn * 64 + nt * 8 + ccol;
            float* p = O + (size_t)row * C_SZ + col;
            *(float2*)p = make_float2(acc[mt][nt][0], acc[mt][nt][1]);
            *(float2*)(p + 8 * C_SZ) = make_float2(acc[mt][nt][2], acc[mt][nt][3]);
        }
}

// ===========================================================================
// attn: P = mask(Q K^T) (no decay); acc = Q@Std (2-term) + P@Vdt (3-term);
// epilogue scales rows by d^(-i-1)*R_SCALE and writes Rh/Rl splits.
// ===========================================================================
#define AQ_STR 528
#define AP_STR 144
#define AB_STR 80
#define A_SQH  0
#define A_SQL  33792
#define A_SPH  67584
#define A_SPL  76800
#define A_BUF  86016
#define A_STG  40960
#define A_SMEM 208896

__global__ void __launch_bounds__(256) attn_mma(const float* __restrict__ dlp)
{
    extern __shared__ __align__(16) char asmm[];
    const uint32_t s0 = cvta_shared(asmm);
    const int c = blockIdx.x, b = blockIdx.y;
    const int tid = threadIdx.x, lane = tid & 31, wid = tid >> 5;
    const float lg2d = log2f(get_decay(dlp));

    const size_t nat = ((size_t)b * T_SZ + (size_t)c * L_SZ) * C_SZ;
    const __half* gQh = g_QKh + nat;
    const __half* gQl = g_QKl + nat;
    const __half* gKh = g_QKh + (size_t)BT * C_SZ + nat;
    const __half* gKl = g_QKl + (size_t)BT * C_SZ + nat;
    const size_t vt = (size_t)b * C_SZ * T_SZ + (size_t)c * L_SZ;
    const size_t st = ((size_t)(b * NCH + c)) * C_SZ * C_SZ;

    const int r8 = lane & 7, midx = lane >> 3;

    {
        const int row = tid >> 2, q4 = tid & 3;
#pragma unroll
        for (int it = 0; it < 8; it++) {
            const int c16 = q4 + it * 4;
            cp16(s0 + A_SQH + row * AQ_STR + c16 * 16, gQh + row * C_SZ + c16 * 8);
            cp16(s0 + A_SQL + row * AQ_STR + c16 * 16, gQl + row * C_SZ + c16 * 8);
        }
        CP_COMMIT();
    }

    auto issue = [&](int q) {
        const uint32_t bh = s0 + A_BUF + (q % 3) * A_STG;
        const uint32_t bl = bh + 20480;
        if (q < 8) {                       // K tile: 64 x 32k, hi+lo
            const int row = tid >> 2, c16 = tid & 3;
            cp16(bh + row * AB_STR + c16 * 16, gKh + row * C_SZ + q * 32 + c16 * 8);
            cp16(bl + row * AB_STR + c16 * 16, gKl + row * C_SZ + q * 32 + c16 * 8);
        } else if (q < 16) {               // Std tile: 256 x 32k, hi only
            const int ct = q - 8;
            const size_t src = st + (size_t)tid * C_SZ + ct * 32;
#pragma unroll
            for (int it = 0; it < 4; it++)
                cp16(bh + tid * AB_STR + it * 16, g_Sth + src + it * 8);
        } else {                           // Vdt tile: 256 x 32t, hi+lo
            const int ct = q - 16;
            const size_t src = vt + (size_t)tid * T_SZ + ct * 32;
#pragma unroll
            for (int it = 0; it < 4; it++) {
                cp16(bh + tid * AB_STR + it * 16, g_Vdth + src + it * 8);
                cp16(bl + tid * AB_STR + it * 16, g_Vdtl + src + it * 8);
            }
        }
        CP_COMMIT();
    };

    const int pwm = wid & 3, pwn = wid >> 2;
    const int wm = wid & 1, wn = wid >> 1;

    float accp[4][4];
#pragma unroll
    for (int a = 0; a < 4; a++)
#pragma unroll
        for (int e = 0; e < 4; e++) accp[a][e] = 0.0f;
    float acc[2][8][4];
#pragma unroll
    for (int mt = 0; mt < 2; mt++)
#pragma unroll
        for (int nt = 0; nt < 8; nt++)
#pragma unroll
            for (int e = 0; e < 4; e++) acc[mt][nt][e] = 0.0f;

    issue(0);
    issue(1);

    for (int q = 0; q < 18; q++) {
        if (q < 17) CP_WAIT1(); else CP_WAIT0();
        __syncthreads();
        if (q + 2 < 18) issue(q + 2);

        const uint32_t bh = s0 + A_BUF + (q % 3) * A_STG;

        if (q < 8) {
            // P phase (3-term, quasi-exact)
#pragma unroll
            for (int ks = 0; ks < 2; ks++) {
                uint32_t ah[4], al[4];
                const uint32_t ad = s0 + A_SQH +
                    (pwm * 16 + (midx & 1) * 8 + r8) * AQ_STR +
                    (q * 32 + ks * 16 + (midx >> 1) * 8) * 2;
                ldsm_x4(ad, ah);
                ldsm_x4(ad + (A_SQL - A_SQH), al);
#pragma unroll
                for (int ng = 0; ng < 2; ng++) {
                    uint32_t bhf[4], blf[4];
                    const uint32_t bd = bh +
                        (pwn * 32 + ng * 16 + (midx >> 1) * 8 + r8) * AB_STR +
                        (ks * 16 + (midx & 1) * 8) * 2;
                    ldsm_x4(bd, bhf);
                    ldsm_x4(bd + 20480, blf);
#pragma unroll
                    for (int sub = 0; sub < 2; sub++) {
                        float* A = accp[ng * 2 + sub];
                        mma_f16(A, ah, &bhf[sub * 2]);
                        mma_f16(A, al, &bhf[sub * 2]);
                        mma_f16(A, ah, &blf[sub * 2]);
                    }
                }
            }
            if (q == 7) {
                // P epilogue: mask only (decay handled by Vdt + row scale)
                const int prow = pwm * 16 + (lane >> 2);
#pragma unroll
                for (int nt = 0; nt < 4; nt++)
#pragma unroll
                    for (int e = 0; e < 4; e++) {
                        const int i = prow + (e >> 1) * 8;
                        const int j = pwn * 32 + nt * 8 + (lane & 3) * 2 + (e & 1);
                        float v = (j > i) ? accp[nt][e] : 0.0f;
                        __half h = __float2half_rn(v);
                        *(__half*)(asmm + A_SPH + i * AP_STR + j * 2) = h;
                        *(__half*)(asmm + A_SPL + i * AP_STR + j * 2) =
                            __float2half_rn(v - __half2float(h));
                    }
            }
        } else if (q < 16) {
            // inter: acc += Q @ Std (2-term)
            const int ct = q - 8;
#pragma unroll
            for (int ks = 0; ks < 2; ks++) {
                uint32_t ah[2][4], al[2][4], bh4[4][4];
#pragma unroll
                for (int mt = 0; mt < 2; mt++) {
                    const uint32_t ad = s0 + A_SQH +
                        (wm * 32 + mt * 16 + (midx & 1) * 8 + r8) * AQ_STR +
                        (ct * 32 + ks * 16 + (midx >> 1) * 8) * 2;
                    ldsm_x4(ad, ah[mt]);
                    ldsm_x4(ad + (A_SQL - A_SQH), al[mt]);
                }
#pragma unroll
                for (int ng = 0; ng < 4; ng++) {
                    const uint32_t bd = bh +
                        (wn * 64 + ng * 16 + (midx >> 1) * 8 + r8) * AB_STR +
                        (ks * 16 + (midx & 1) * 8) * 2;
                    ldsm_x4(bd, bh4[ng]);
                }
#pragma unroll
                for (int mt = 0; mt < 2; mt++)
#pragma unroll
                    for (int nt = 0; nt < 8; nt++) {
                        const uint32_t* bp = &bh4[nt >> 1][(nt & 1) * 2];
                        mma_f16(acc[mt][nt], ah[mt], bp);
                        mma_f16(acc[mt][nt], al[mt], bp);
                    }
            }
        } else {
            // intra: acc += P @ Vdt (3-term)
#pragma unroll
            for (int ks = 0; ks < 2; ks++) {
                uint32_t ah[2][4], al[2][4], bh4[4][4], bl4[4][4];
                const int ct = q - 16;
#pragma unroll
                for (int mt = 0; mt < 2; mt++) {
                    const uint32_t ad = s0 + A_SPH +
                        (wm * 32 + mt * 16 + (midx & 1) * 8 + r8) * AP_STR +
                        (ct * 32 + ks * 16 + (midx >> 1) * 8) * 2;
                    ldsm_x4(ad, ah[mt]);
                    ldsm_x4(ad + (A_SPL - A_SPH), al[mt]);
                }
#pragma unroll
                for (int ng = 0; ng < 4; ng++) {
                    const uint32_t bd = bh +
                        (wn * 64 + ng * 16 + (midx >> 1) * 8 + r8) * AB_STR +
                        (ks * 16 + (midx & 1) * 8) * 2;
                    ldsm_x4(bd, bh4[ng]);
                    ldsm_x4(bd + 20480, bl4[ng]);
                }
#pragma unroll
                for (int mt = 0; mt < 2; mt++)
#pragma unroll
                    for (int nt = 0; nt < 8; nt++) {
                        const uint32_t* bp  = &bh4[nt >> 1][(nt & 1) * 2];
                        const uint32_t* blp = &bl4[nt >> 1][(nt & 1) * 2];
                        mma_f16(acc[mt][nt], ah[mt], bp);
                        mma_f16(acc[mt][nt], al[mt], bp);
                        mma_f16(acc[mt][nt], ah[mt], blp);
                    }
            }
        }
    }

    // epilogue: row scale d^(-i-1) * R_SCALE, write Rh/Rl splits
    __half* Rh = g_Rh + nat;
    __half* Rl = g_Rl + nat;
#pragma unroll
    for (int mt = 0; mt < 2; mt++) {
        const int i0 = wm * 32 + mt * 16 + (lane >> 2);
        const float s1 = exp2f(-(float)(i0 + 1) * lg2d) * R_SCALE;
        const float s2 = exp2f(-(float)(i0 + 9) * lg2d) * R_SCALE;
#pragma unroll
        for (int nt = 0; nt < 8; nt++) {
            const int col = wn * 64 + nt * 8 + (lane & 3) * 2;
            const size_t o = (size_t)i0 * C_SZ + col;
            split_store2(Rh + o, Rl + o, acc[mt][nt][0] * s1, acc[mt][nt][1] * s1);
            const size_t o2 = o + 8 * (size_t)C_SZ;
            split_store2(Rh + o2, Rl + o2, acc[mt][nt][2] * s2, acc[mt][nt][3] * s2);
        }
    }
}

// ===========================================================================
// fp32 -> (hi, lo) fp16 split
// ===========================================================================
__global__ void split_kernel(const float* __restrict__ s,
                             __half* __restrict__ h,
                             __half* __restrict__ l, int n4)
{
    int i = blockIdx.x * blockDim.x + threadIdx.x;
    if (i >= n4) return;
    float4 v = ((const float4*)s)[i];
    __half h0 = __float2half_rn(v.x), h1 = __float2half_rn(v.y);
    __half h2 = __float2half_rn(v.z), h3 = __float2half_rn(v.w);
    ((__half2*)h)[2 * i]     = __half2(h0, h1);
    ((__half2*)h)[2 * i + 1] = __half2(h2, h3);
    ((__half2*)l)[2 * i]     = __half2(__float2half_rn(v.x - __half2float(h0)),
                                       __float2half_rn(v.y - __half2float(h1)));
    ((__half2*)l)[2 * i + 1] = __half2(__float2half_rn(v.z - __half2float(h2)),
                                       __float2half_rn(v.w - __half2float(h3)));
}

// ===========================================================================
// basis [1024,256] -> basis^T fp16 hi/lo
// ===========================================================================
__global__ void transpose_split(const float* __restrict__ in,
                                __half* __restrict__ oh, __half* __restrict__ ol)
{
    __shared__ float t[32][33];
    const int v0 = blockIdx.x * 32, c0 = blockIdx.y * 32;
    const int tx = threadIdx.x, ty = threadIdx.y;
#pragma unroll
    for (int j = 0; j < 32; j += 8)
        t[ty + j][tx] = in[(size_t)(v0 + ty + j) * C_SZ + c0 + tx];
    __syncthreads();
#pragma unroll
    for (int j = 0; j < 32; j += 8) {
        float val = t[tx][ty + j];
        __half h = __float2half_rn(val);
        oh[(size_t)(c0 + ty + j) * V_SZ + v0 + tx] = h;
        ol[(size_t)(c0 + ty + j) * V_SZ + v0 + tx] =
            __float2half_rn(val - __half2float(h));
    }
}

// ===========================================================================
// V [B*T, C] fp32 -> decayed V^T [B][C][T] fp16 hi/lo (decay d^(t mod 64))
// grid (T/32, C/32, B)
// ===========================================================================
__global__ void transpose_split_vd(const float* __restrict__ in,
                                   __half* __restrict__ oh, __half* __restrict__ ol,
                                   const float* __restrict__ dlp)
{
    __shared__ float t[32][33];
    const int b = blockIdx.z;
    const int t0 = blockIdx.x * 32, c0 = blockIdx.y * 32;
    const int tx = threadIdx.x, ty = threadIdx.y;
    const float lg2d = log2f(get_decay(dlp));
    const float dr = exp2f((float)((t0 + tx) & 63) * lg2d);
#pragma unroll
    for (int j = 0; j < 32; j += 8)
        t[ty + j][tx] = in[((size_t)b * T_SZ + t0 + ty + j) * C_SZ + c0 + tx];
    __syncthreads();
#pragma unroll
    for (int j = 0; j < 32; j += 8) {
        float val = t[tx][ty + j] * dr;
        __half h = __float2half_rn(val);
        const size_t o = (size_t)b * C_SZ * T_SZ + (size_t)(c0 + ty + j) * T_SZ + t0 + tx;
        oh[o] = h;
        ol[o] = __float2half_rn(val - __half2float(h));
    }
}

// ===========================================================================
// K hi [B*T, C] fp16 -> K^T [B][C][T] fp16 hi.  grid (T/32, C/32, B)
// ===========================================================================
__global__ void transpose_h(const __half* __restrict__ in, __half* __restrict__ out)
{
    __shared__ __half t[32][33];
    const int b = blockIdx.z;
    const int t0 = blockIdx.x * 32, c0 = blockIdx.y * 32;
    const int tx = threadIdx.x, ty = threadIdx.y;
#pragma unroll
    for (int j = 0; j < 32; j += 8)
        t[ty + j][tx] = in[((size_t)b * T_SZ + t0 + ty + j) * C_SZ + c0 + tx];
    __syncthreads();
#pragma unroll
    for (int j = 0; j < 32; j += 8)
        out[(size_t)b * C_SZ * T_SZ + (size_t)(c0 + ty + j) * T_SZ + t0 + tx] =
            t[tx][ty + j];
}

// ===========================================================================
// SGEMM nt (f32x2) — Wo build only
// ===========================================================================
__global__ void __launch_bounds__(256) sgemm_nt(
    const float* __restrict__ A, const float* __restrict__ B,
    float* __restrict__ C, int M, int N, int K)
{
    __shared__ __align__(16) float As[8][128];
    __shared__ __align__(16) float Bs[8][128];
    const int tid = threadIdx.x;
    const int m0 = blockIdx.y * 128, n0 = blockIdx.x * 128;
    const int tr = tid >> 4, tc = tid & 15;
    const int ar = tid >> 1, ac = (tid & 1) * 4;
    ull acc[8][4] = {};
    const float* Aptr = A + (size_t)(m0 + ar) * K + ac;
    const float* Bptr = B + (size_t)(n0 + ar) * K + ac;
    for (int k0 = 0; k0 < K; k0 += 8) {
        float4 av = *(const float4*)(Aptr + k0);
        As[ac + 0][ar] = av.x; As[ac + 1][ar] = av.y;
        As[ac + 2][ar] = av.z; As[ac + 3][ar] = av.w;
        float4 bv = *(const float4*)(Bptr + k0);
        Bs[ac + 0][ar] = bv.x; Bs[ac + 1][ar] = bv.y;
        Bs[ac + 2][ar] = bv.z; Bs[ac + 3][ar] = bv.w;
        __syncthreads();
#pragma unroll
        for (int kk = 0; kk < 8; kk++) {
            const ull* bp = (const ull*)&Bs[kk][tc * 8];
            ull b0 = bp[0], b1 = bp[1], b2 = bp[2], b3 = bp[3];
            const float* ap = &As[kk][tr * 8];
#pragma unroll
            for (int i = 0; i < 8; i++) {
                ull a2 = pack2(ap[i]);
                ffma2(acc[i][0], a2, b0); ffma2(acc[i][1], a2, b1);
                ffma2(acc[i][2], a2, b2); ffma2(acc[i][3], a2, b3);
            }
        }
        __syncthreads();
    }
#pragma unroll
    for (int i = 0; i < 8; i++) {
        float* Cp = C + (size_t)(m0 + tr * 8 + i) * N + n0 + tc * 8;
        float2 p0 = *(float2*)&acc[i][0], p1 = *(float2*)&acc[i][1];
        float2 p2 = *(float2*)&acc[i][2], p3 = *(float2*)&acc[i][3];
        *(float4*)(Cp)     = make_float4(p0.x, p0.y, p1.x, p1.y);
        *(float4*)(Cp + 4) = make_float4(p2.x, p2.y, p3.x, p3.y);
    }
}

// ===========================================================================
// scan: run=0; for c desc: store d^64*run (fp16 hi); run = d^64*run + A[c]
// ===========================================================================
__global__ void scan_kernel(const float* __restrict__ dlp)
{
    const int e = blockIdx.x * blockDim.x + threadIdx.x;
    const int b = blockIdx.y;
    const float decay = get_decay(dlp);
    const float dL = exp2f((float)L_SZ * log2f(decay));
    float run = 0.0f;
    const size_t base = (size_t)b * NCH * (C_SZ * C_SZ) + e;
    for (int c = NCH - 1; c >= 0; c--) {
        const size_t pos = base + (size_t)c * (C_SZ * C_SZ);
        const float sc_ = dL * run;
        g_Sth[pos] = __float2half_rn(sc_);
        run = sc_ + g_AS[pos];
    }
}

// ===========================================================================
extern "C" void kernel_launch(void* const* d_in, const int* in_sizes, int n_in,
                              void* d_out, int out_size)
{
    const float* x     = (const float*)d_in[0];
    const float* basis = (const float*)d_in[1];
    const float* qc    = (const float*)d_in[2];
    const float* kc    = (const float*)d_in[3];
    const float* vc    = (const float*)d_in[4];
    const float* oc    = (const float*)d_in[5];
    const float* dl    = (const float*)d_in[6];
    const float* os    = (const float*)d_in[7];
    float* out = (float*)d_out;

    float *pWo, *pQKV, *pAS;
    __half *pxh, *pxl, *pbTh, *pbTl, *pxbh, *pxbl, *pch, *pcl, *pWoh, *pWol;
    __half *pQKh, *pQKl, *pVdth, *pVdtl, *pKth, *pRh, *pRl;
    cudaGetSymbolAddress((void**)&pWo,   g_Wo);
    cudaGetSymbolAddress((void**)&pQKV,  g_QKV);
    cudaGetSymbolAddress((void**)&pAS,   g_AS);
    cudaGetSymbolAddress((void**)&pxh,   g_xh);
    cudaGetSymbolAddress((void**)&pxl,   g_xl);
    cudaGetSymbolAddress((void**)&pbTh,  g_bTh);
    cudaGetSymbolAddress((void**)&pbTl,  g_bTl);
    cudaGetSymbolAddress((void**)&pxbh,  g_xbh);
    cudaGetSymbolAddress((void**)&pxbl,  g_xbl);
    cudaGetSymbolAddress((void**)&pch,   g_ch);
    cudaGetSymbolAddress((void**)&pcl,   g_cl);
    cudaGetSymbolAddress((void**)&pWoh,  g_Woh);
    cudaGetSymbolAddress((void**)&pWol,  g_Wol);
    cudaGetSymbolAddress((void**)&pQKh,  g_QKh);
    cudaGetSymbolAddress((void**)&pQKl,  g_QKl);
    cudaGetSymbolAddress((void**)&pVdth, g_Vdth);
    cudaGetSymbolAddress((void**)&pVdtl, g_Vdtl);
    cudaGetSymbolAddress((void**)&pKth,  g_Kth);
    cudaGetSymbolAddress((void**)&pRh,   g_Rh);
    cudaGetSymbolAddress((void**)&pRl,   g_Rl);

    const int SMEM2 = 3 * 3 * ARR_B;
    cudaFuncSetAttribute(mma_gemm, cudaFuncAttributeMaxDynamicSharedMemorySize, SMEM2);
    cudaFuncSetAttribute(chunk_mma, cudaFuncAttributeMaxDynamicSharedMemorySize, CK_SMEM);
    cudaFuncSetAttribute(attn_mma, cudaFuncAttributeMaxDynamicSharedMemorySize, A_SMEM);

    // 1. prep: basis^T split, x split, coeff splits, Wo build + split
    transpose_split<<<dim3(32, 8), dim3(32, 8)>>>(basis, pbTh, pbTl);
    split_kernel<<<(BT * V_SZ / 4 + 255) / 256, 256>>>(x, pxh, pxl, BT * V_SZ / 4);
    split_kernel<<<(C_SZ * C_SZ / 4 + 255) / 256, 256>>>(qc, pch, pcl, C_SZ * C_SZ / 4);
    split_kernel<<<(C_SZ * C_SZ / 4 + 255) / 256, 256>>>(
        kc, pch + C_SZ * C_SZ, pcl + C_SZ * C_SZ, C_SZ * C_SZ / 4);
    split_kernel<<<(C_SZ * C_SZ / 4 + 255) / 256, 256>>>(
        vc, pch + 2 * C_SZ * C_SZ, pcl + 2 * C_SZ * C_SZ, C_SZ * C_SZ / 4);
    sgemm_nt<<<dim3(2, 8), 256>>>(basis, oc, pWo, 1024, 256, 256);
    split_kernel<<<(V_SZ * C_SZ / 4 + 255) / 256, 256>>>(pWo, pWoh, pWol, V_SZ * C_SZ / 4);

    // 2. xb = x @ basis (2-term) -> fp16 hi/lo directly
    mma_gemm<<<dim3(2, 128, 1), 256, SMEM2>>>(
        pxh, pxl, pbTh, pAS /*dummy*/, pxbh, pxbl, 1, 0,
        V_SZ, 0, 0, C_SZ, nullptr, 1.0f);

    // 3. QKV = xb @ coeffs^T (2-term): z=0,1 -> Q/K fp16 hi/lo; z=2 -> V fp32
    mma_gemm<<<dim3(2, 128, 3), 256, SMEM2>>>(
        pxbh, pxbl, pch, pQKV, pQKh, pQKl, 2, (size_t)BT * C_SZ,
        C_SZ, (size_t)C_SZ * C_SZ, (size_t)BT * C_SZ, C_SZ, nullptr, 1.0f);

    // 4. transposes: decayed V^T hi/lo, K^T hi
    transpose_split_vd<<<dim3(128, 8, B_SZ), dim3(32, 8)>>>(
        pQKV + 2 * (size_t)BT * C_SZ, pVdth, pVdtl, dl);
    transpose_h<<<dim3(128, 8, B_SZ), dim3(32, 8)>>>(pQKh + (size_t)BT * C_SZ, pKth);

    // 5. chunk A^T (tensor cores), scan -> fp16 states, attn -> Rh/Rl
    chunk_mma<<<dim3(2, 2, B_SZ * NCH), 256, CK_SMEM>>>();
    scan_kernel<<<dim3(256, B_SZ), 256>>>(dl);
    attn_mma<<<dim3(NCH, B_SZ), 256, A_SMEM>>>(dl);

    // 6. output projection: out = R @ Wo^T * out_scale (2-term)
    mma_gemm<<<dim3(8, 128, 1), 256, SMEM2>>>(
        pRh, pRl, pWoh, out, nullptr, nullptr, 0, 0,
        C_SZ, 0, 0, V_SZ, os, R_UNSCALE);
}

// round 11
// speedup vs baseline: 3.6741x; 1.1350x over previous
#include <cuda_runtime.h>
#include <cuda_fp16.h>
#include <math.h>
#include <stdint.h>

// Problem constants
#define B_SZ 4
#define T_SZ 4096
#define V_SZ 1024
#define C_SZ 256
#define L_SZ 64
#define NCH  64
#define BT   (B_SZ * T_SZ)

#define R_SCALE   0.00390625f
#define R_UNSCALE 256.0f

typedef unsigned long long ull;

// ---------------- scratch ---------------------------------------------------
__device__ float g_Wo [V_SZ * C_SZ];
__device__ float g_QKV[3 * BT * C_SZ];       // only V slab (z=2) written fp32
__device__ float g_AS [B_SZ * NCH * C_SZ * C_SZ];   // A^T per chunk (fp32)
__device__ __half g_xh [BT * V_SZ];          // x hi only (1-term A)
__device__ __half g_bTh[C_SZ * V_SZ];
__device__ __half g_bTl[C_SZ * V_SZ];        // written, unused (2-term B not used)
__device__ __half g_xbh[BT * C_SZ];
__device__ __half g_xbl[BT * C_SZ];
__device__ __half g_ch [3 * C_SZ * C_SZ];
__device__ __half g_cl [3 * C_SZ * C_SZ];    // dump
__device__ __half g_Woh[V_SZ * C_SZ];
__device__ __half g_Wol[V_SZ * C_SZ];        // dump
__device__ __half g_QKh[2 * BT * C_SZ];
__device__ __half g_QKl[2 * BT * C_SZ];
__device__ __half g_Vdth[BT * C_SZ];         // decayed V^T [B][C][T] hi
__device__ __half g_Vdtl[BT * C_SZ];
__device__ __half g_Kth[BT * C_SZ];          // K^T [B][C][T] hi
__device__ __half g_Sth[B_SZ * NCH * C_SZ * C_SZ];  // d^64 * S^T states, hi
__device__ __half g_Rh [BT * C_SZ];          // R hi only (1-term A)

__device__ __forceinline__ float get_decay(const float* dl) {
    return 1.0f / (1.0f + expf(-dl[0]));
}

// ---- packed fp32x2 (Wo build only) ----------------------------------------
__device__ __forceinline__ ull pack2(float x) {
    ull r; asm("mov.b64 %0, {%1, %1};" : "=l"(r) : "f"(x)); return r;
}
__device__ __forceinline__ void ffma2(ull& c, ull a, ull b) {
    asm("fma.rn.f32x2 %0, %1, %2, %0;" : "+l"(c) : "l"(a), "l"(b));
}
__device__ __forceinline__ uint32_t cvta_shared(const void* p) {
    uint32_t a;
    asm("{ .reg .u64 t; cvta.to.shared.u64 t, %1; cvt.u32.u64 %0, t; }"
        : "=r"(a) : "l"(p));
    return a;
}

// ---- mma.sync / ldmatrix / cp.async ---------------------------------------
__device__ __forceinline__ void ldsm_x4(uint32_t a, uint32_t* r) {
    asm volatile("ldmatrix.sync.aligned.m8n8.x4.shared.b16 {%0,%1,%2,%3}, [%4];"
                 : "=r"(r[0]), "=r"(r[1]), "=r"(r[2]), "=r"(r[3]) : "r"(a));
}
__device__ __forceinline__ void mma_f16(float* d, const uint32_t* a, const uint32_t* b) {
    asm volatile("mma.sync.aligned.m16n8k16.row.col.f32.f16.f16.f32 "
                 "{%0,%1,%2,%3}, {%4,%5,%6,%7}, {%8,%9}, {%0,%1,%2,%3};"
                 : "+f"(d[0]), "+f"(d[1]), "+f"(d[2]), "+f"(d[3])
                 : "r"(a[0]), "r"(a[1]), "r"(a[2]), "r"(a[3]),
                   "r"(b[0]), "r"(b[1]));
}
__device__ __forceinline__ void cp16(uint32_t dst, const void* src) {
    asm volatile("cp.async.cg.shared.global [%0], [%1], 16;" :: "r"(dst), "l"(src));
}
#define CP_COMMIT() asm volatile("cp.async.commit_group;" ::: "memory")
#define CP_WAIT1()  asm volatile("cp.async.wait_group 1;" ::: "memory")
#define CP_WAIT0()  asm volatile("cp.async.wait_group 0;" ::: "memory")

__device__ __forceinline__ void split_store2(__half* H, __half* L, float v0, float v1) {
    __half h0 = __float2half_rn(v0), h1 = __float2half_rn(v1);
    *(__half2*)H = __half2(h0, h1);
    *(__half2*)L = __half2(__float2half_rn(v0 - __half2float(h0)),
                           __float2half_rn(v1 - __half2float(h1)));
}

// smem geometry for mma_gemm
#define BK 32
#define ROWB 80
#define ARR_B (128 * ROWB)

// ===========================================================================
// fp16 tensor-core GEMM, ATERMS A-side passes (1 or 2): C = A @ Bh^T.
// Epilogue: z < nhz -> fp16 hi/lo split; else fp32. Scale (*scale_ptr)*alpha_mul.
// ===========================================================================
template <int ATERMS>
__global__ void __launch_bounds__(256) mma_gemm(
    const __half* __restrict__ Ahb, const __half* __restrict__ Alb,
    const __half* __restrict__ Bhb,
    float* __restrict__ Cbase, __half* __restrict__ Hout, __half* __restrict__ Lout,
    int nhz, size_t sH, int K, size_t sB, size_t sC, int ldC,
    const float* __restrict__ scale_ptr, float alpha_mul)
{
    extern __shared__ __align__(16) char dynsm[];
    const uint32_t sdyn = cvta_shared(dynsm);
    const uint32_t STAGE_B = (ATERMS + 1) * ARR_B;
    const uint32_t BOFF = ATERMS * ARR_B;

    const int tid = threadIdx.x, lane = tid & 31, wid = tid >> 5;
    const int m0 = blockIdx.y * 128, n0 = blockIdx.x * 128;
    const int z = blockIdx.z;
    const __half* gAh = Ahb + (size_t)m0 * K;
    const __half* gAl = Alb + (size_t)m0 * K;
    const __half* gBh = Bhb + (size_t)z * sB + (size_t)n0 * K;

    const int warp_m = wid >> 1, warp_n = wid & 1;
    const int r8 = lane & 7, midx = lane >> 3;
    const int NC = K / BK;
    const int lr0 = tid >> 2, c4 = tid & 3;

    float acc[2][8][4];
#pragma unroll
    for (int mt = 0; mt < 2; mt++)
#pragma unroll
        for (int nt = 0; nt < 8; nt++)
#pragma unroll
            for (int r = 0; r < 4; r++) acc[mt][nt][r] = 0.0f;

    auto issue = [&](int s, int kc) {
        const int k0 = kc * BK;
        const uint32_t st = sdyn + s * STAGE_B;
#pragma unroll
        for (int h = 0; h < 2; h++) {
            const int r = lr0 + h * 64;
            const uint32_t d = st + r * ROWB + c4 * 16;
            const size_t g = (size_t)r * K + k0 + c4 * 8;
            cp16(d, gAh + g);
            if (ATERMS == 2) cp16(d + ARR_B, gAl + g);
            cp16(d + BOFF, gBh + g);
        }
        CP_COMMIT();
    };

    issue(0, 0);
    issue(1, 1);

    for (int i = 0; i < NC; i++) {
        if (i < NC - 1) CP_WAIT1(); else CP_WAIT0();
        __syncthreads();
        if (i + 2 < NC) issue((i + 2) % 3, i + 2);

        const uint32_t stg = sdyn + (i % 3) * STAGE_B;
#pragma unroll
        for (int kh = 0; kh < 2; kh++) {
            uint32_t ah[2][4], al[2][4], bh4[4][4];
#pragma unroll
            for (int mt = 0; mt < 2; mt++) {
                const uint32_t ad = stg +
                    (warp_m * 32 + mt * 16 + (midx & 1) * 8 + r8) * ROWB +
                    (midx >> 1) * 16 + kh * 32;
                ldsm_x4(ad, ah[mt]);
                if (ATERMS == 2) ldsm_x4(ad + ARR_B, al[mt]);
            }
#pragma unroll
            for (int ng = 0; ng < 4; ng++) {
                const uint32_t bd = stg + BOFF +
                    (warp_n * 64 + ng * 16 + (midx >> 1) * 8 + r8) * ROWB +
                    (midx & 1) * 16 + kh * 32;
                ldsm_x4(bd, bh4[ng]);
            }
#pragma unroll
            for (int mt = 0; mt < 2; mt++)
#pragma unroll
                for (int nt = 0; nt < 8; nt++) {
                    const uint32_t* bp = &bh4[nt >> 1][(nt & 1) * 2];
                    mma_f16(acc[mt][nt], ah[mt], bp);
                    if (ATERMS == 2) mma_f16(acc[mt][nt], al[mt], bp);
                }
        }
    }

    const float alpha = (scale_ptr ? scale_ptr[0] : 1.0f) * alpha_mul;
    const int crow = lane >> 2, ccol = (lane & 3) * 2;
    if (z < nhz) {
        __half* H = Hout + (size_t)z * sH;
        __half* L = Lout + (size_t)z * sH;
#pragma unroll
        for (int mt = 0; mt < 2; mt++)
#pragma unroll
            for (int nt = 0; nt < 8; nt++) {
                const int row = m0 + warp_m * 32 + mt * 16 + crow;
                const int col = n0 + warp_n * 64 + nt * 8 + ccol;
                const size_t o = (size_t)row * ldC + col;
                split_store2(H + o, L + o,
                             acc[mt][nt][0] * alpha, acc[mt][nt][1] * alpha);
                const size_t o2 = o + 8 * (size_t)ldC;
                split_store2(H + o2, L + o2,
                             acc[mt][nt][2] * alpha, acc[mt][nt][3] * alpha);
            }
    } else {
        float* C = Cbase + (size_t)z * sC;
#pragma unroll
        for (int mt = 0; mt < 2; mt++)
#pragma unroll
            for (int nt = 0; nt < 8; nt++) {
                const int row = m0 + warp_m * 32 + mt * 16 + crow;
                const int col = n0 + warp_n * 64 + nt * 8 + ccol;
                float* p = C + (size_t)row * ldC + col;
                *(float2*)p = make_float2(acc[mt][nt][0] * alpha, acc[mt][nt][1] * alpha);
                *(float2*)(p + 8 * (size_t)ldC) =
                    make_float2(acc[mt][nt][2] * alpha, acc[mt][nt][3] * alpha);
            }
    }
}

// ===========================================================================
// chunk_mma: A^T[c2][c1] = sum_r d^r V[r,c2] K[r,c1] per chunk (fp32 out)
// A = decayed V^T hi/lo (2-term), B = K^T hi. grid (2, 2, B*NCH)
// ===========================================================================
#define CK_STR 144
#define CK_AH 0
#define CK_AL 18432
#define CK_B  36864
#define CK_SMEM 55296

__global__ void __launch_bounds__(256) chunk_mma()
{
    extern __shared__ __align__(16) char csm[];
    const uint32_t s0 = cvta_shared(csm);
    const int z = blockIdx.z, b = z >> 6, c = z & 63;
    const int m0 = blockIdx.y * 128, n0 = blockIdx.x * 128;
    const int tid = threadIdx.x, lane = tid & 31, wid = tid >> 5;
    const int r8 = lane & 7, midx = lane >> 3;

    const size_t tb = (size_t)b * C_SZ * T_SZ + (size_t)c * 64;
    const __half* gAh = g_Vdth + tb + (size_t)m0 * T_SZ;
    const __half* gAl = g_Vdtl + tb + (size_t)m0 * T_SZ;
    const __half* gB  = g_Kth  + tb + (size_t)n0 * T_SZ;

    {
        const int row = tid >> 1, c2_ = tid & 1;
#pragma unroll
        for (int it = 0; it < 4; it++) {
            const int cc = c2_ + it * 2;
            const size_t g = (size_t)row * T_SZ + cc * 8;
            cp16(s0 + CK_AH + row * CK_STR + cc * 16, gAh + g);
            cp16(s0 + CK_AL + row * CK_STR + cc * 16, gAl + g);
            cp16(s0 + CK_B  + row * CK_STR + cc * 16, gB + g);
        }
        CP_COMMIT();
    }
    CP_WAIT0();
    __syncthreads();

    const int wm = wid >> 1, wn = wid & 1;
    float acc[2][8][4];
#pragma unroll
    for (int mt = 0; mt < 2; mt++)
#pragma unroll
        for (int nt = 0; nt < 8; nt++)
#pragma unroll
            for (int e = 0; e < 4; e++) acc[mt][nt][e] = 0.0f;

#pragma unroll
    for (int ks = 0; ks < 4; ks++) {
        uint32_t ah[2][4], al[2][4], bt[4][4];
#pragma unroll
        for (int mt = 0; mt < 2; mt++) {
            const uint32_t ad = s0 + CK_AH +
                (wm * 32 + mt * 16 + (midx & 1) * 8 + r8) * CK_STR +
                (ks * 16 + (midx >> 1) * 8) * 2;
            ldsm_x4(ad, ah[mt]);
            ldsm_x4(ad + (CK_AL - CK_AH), al[mt]);
        }
#pragma unroll
        for (int ng = 0; ng < 4; ng++) {
            const uint32_t bd = s0 + CK_B +
                (wn * 64 + ng * 16 + (midx >> 1) * 8 + r8) * CK_STR +
                (ks * 16 + (midx & 1) * 8) * 2;
            ldsm_x4(bd, bt[ng]);
        }
#pragma unroll
        for (int mt = 0; mt < 2; mt++)
#pragma unroll
            for (int nt = 0; nt < 8; nt++) {
                const uint32_t* bp = &bt[nt >> 1][(nt & 1) * 2];
                mma_f16(acc[mt][nt], ah[mt], bp);
                mma_f16(acc[mt][nt], al[mt], bp);
            }
    }

    float* O = g_AS + (size_t)z * C_SZ * C_SZ;
    const int crow = lane >> 2, ccol = (lane & 3) * 2;
#pragma unroll
    for (int mt = 0; mt < 2; mt++)
#pragma unroll
        for (int nt = 0; nt < 8; nt++) {
            const int row = m0 + wm * 32 + mt * 16 + crow;
            const int col = n0 + wn * 64 + nt * 8 + ccol;
            float* p = O + (size_t)row * C_SZ + col;
            *(float2*)p = make_float2(acc[mt][nt][0], acc[mt][nt][1]);
            *(float2*)(p + 8 * C_SZ) = make_float2(acc[mt][nt][2], acc[mt][nt][3]);
        }
}

// ===========================================================================
// attn: P = mask(Q K^T); acc = Q@Std (2-term) + P@Vdt (3-term);
// epilogue scales rows by d^(-i-1)*R_SCALE, writes Rh only.
// ===========================================================================
#define AQ_STR 528
#define AP_STR 144
#define AB_STR 80
#define A_SQH  0
#define A_SQL  33792
#define A_SPH  67584
#define A_SPL  76800
#define A_BUF  86016
#define A_STG  40960
#define A_SMEM 208896

__global__ void __launch_bounds__(256) attn_mma(const float* __restrict__ dlp)
{
    extern __shared__ __align__(16) char asmm[];
    const uint32_t s0 = cvta_shared(asmm);
    const int c = blockIdx.x, b = blockIdx.y;
    const int tid = threadIdx.x, lane = tid & 31, wid = tid >> 5;
    const float lg2d = log2f(get_decay(dlp));

    const size_t nat = ((size_t)b * T_SZ + (size_t)c * L_SZ) * C_SZ;
    const __half* gQh = g_QKh + nat;
    const __half* gQl = g_QKl + nat;
    const __half* gKh = g_QKh + (size_t)BT * C_SZ + nat;
    const __half* gKl = g_QKl + (size_t)BT * C_SZ + nat;
    const size_t vt = (size_t)b * C_SZ * T_SZ + (size_t)c * L_SZ;
    const size_t st = ((size_t)(b * NCH + c)) * C_SZ * C_SZ;

    const int r8 = lane & 7, midx = lane >> 3;

    {
        const int row = tid >> 2, q4 = tid & 3;
#pragma unroll
        for (int it = 0; it < 8; it++) {
            const int c16 = q4 + it * 4;
            cp16(s0 + A_SQH + row * AQ_STR + c16 * 16, gQh + row * C_SZ + c16 * 8);
            cp16(s0 + A_SQL + row * AQ_STR + c16 * 16, gQl + row * C_SZ + c16 * 8);
        }
        CP_COMMIT();
    }

    auto issue = [&](int q) {
        const uint32_t bh = s0 + A_BUF + (q % 3) * A_STG;
        const uint32_t bl = bh + 20480;
        if (q < 8) {
            const int row = tid >> 2, c16 = tid & 3;
            cp16(bh + row * AB_STR + c16 * 16, gKh + row * C_SZ + q * 32 + c16 * 8);
            cp16(bl + row * AB_STR + c16 * 16, gKl + row * C_SZ + q * 32 + c16 * 8);
        } else if (q < 16) {
            const int ct = q - 8;
            const size_t src = st + (size_t)tid * C_SZ + ct * 32;
#pragma unroll
            for (int it = 0; it < 4; it++)
                cp16(bh + tid * AB_STR + it * 16, g_Sth + src + it * 8);
        } else {
            const int ct = q - 16;
            const size_t src = vt + (size_t)tid * T_SZ + ct * 32;
#pragma unroll
            for (int it = 0; it < 4; it++) {
                cp16(bh + tid * AB_STR + it * 16, g_Vdth + src + it * 8);
                cp16(bl + tid * AB_STR + it * 16, g_Vdtl + src + it * 8);
            }
        }
        CP_COMMIT();
    };

    const int pwm = wid & 3, pwn = wid >> 2;
    const int wm = wid & 1, wn = wid >> 1;

    float accp[4][4];
#pragma unroll
    for (int a = 0; a < 4; a++)
#pragma unroll
        for (int e = 0; e < 4; e++) accp[a][e] = 0.0f;
    float acc[2][8][4];
#pragma unroll
    for (int mt = 0; mt < 2; mt++)
#pragma unroll
        for (int nt = 0; nt < 8; nt++)
#pragma unroll
            for (int e = 0; e < 4; e++) acc[mt][nt][e] = 0.0f;

    issue(0);
    issue(1);

    for (int q = 0; q < 18; q++) {
        if (q < 17) CP_WAIT1(); else CP_WAIT0();
        __syncthreads();
        if (q + 2 < 18) issue(q + 2);

        const uint32_t bh = s0 + A_BUF + (q % 3) * A_STG;

        if (q < 8) {
#pragma unroll
            for (int ks = 0; ks < 2; ks++) {
                uint32_t ah[4], al[4];
                const uint32_t ad = s0 + A_SQH +
                    (pwm * 16 + (midx & 1) * 8 + r8) * AQ_STR +
                    (q * 32 + ks * 16 + (midx >> 1) * 8) * 2;
                ldsm_x4(ad, ah);
                ldsm_x4(ad + (A_SQL - A_SQH), al);
#pragma unroll
                for (int ng = 0; ng < 2; ng++) {
                    uint32_t bhf[4], blf[4];
                    const uint32_t bd = bh +
                        (pwn * 32 + ng * 16 + (midx >> 1) * 8 + r8) * AB_STR +
                        (ks * 16 + (midx & 1) * 8) * 2;
                    ldsm_x4(bd, bhf);
                    ldsm_x4(bd + 20480, blf);
#pragma unroll
                    for (int sub = 0; sub < 2; sub++) {
                        float* A = accp[ng * 2 + sub];
                        mma_f16(A, ah, &bhf[sub * 2]);
                        mma_f16(A, al, &bhf[sub * 2]);
                        mma_f16(A, ah, &blf[sub * 2]);
                    }
                }
            }
            if (q == 7) {
                const int prow = pwm * 16 + (lane >> 2);
#pragma unroll
                for (int nt = 0; nt < 4; nt++)
#pragma unroll
                    for (int e = 0; e < 4; e++) {
                        const int i = prow + (e >> 1) * 8;
                        const int j = pwn * 32 + nt * 8 + (lane & 3) * 2 + (e & 1);
                        float v = (j > i) ? accp[nt][e] : 0.0f;
                        __half h = __float2half_rn(v);
                        *(__half*)(asmm + A_SPH + i * AP_STR + j * 2) = h;
                        *(__half*)(asmm + A_SPL + i * AP_STR + j * 2) =
                            __float2half_rn(v - __half2float(h));
                    }
            }
        } else if (q < 16) {
            const int ct = q - 8;
#pragma unroll
            for (int ks = 0; ks < 2; ks++) {
                uint32_t ah[2][4], al[2][4], bh4[4][4];
#pragma unroll
                for (int mt = 0; mt < 2; mt++) {
                    const uint32_t ad = s0 + A_SQH +
                        (wm * 32 + mt * 16 + (midx & 1) * 8 + r8) * AQ_STR +
                        (ct * 32 + ks * 16 + (midx >> 1) * 8) * 2;
                    ldsm_x4(ad, ah[mt]);
                    ldsm_x4(ad + (A_SQL - A_SQH), al[mt]);
                }
#pragma unroll
                for (int ng = 0; ng < 4; ng++) {
                    const uint32_t bd = bh +
                        (wn * 64 + ng * 16 + (midx >> 1) * 8 + r8) * AB_STR +
                        (ks * 16 + (midx & 1) * 8) * 2;
                    ldsm_x4(bd, bh4[ng]);
                }
#pragma unroll
                for (int mt = 0; mt < 2; mt++)
#pragma unroll
                    for (int nt = 0; nt < 8; nt++) {
                        const uint32_t* bp = &bh4[nt >> 1][(nt & 1) * 2];
                        mma_f16(acc[mt][nt], ah[mt], bp);
                        mma_f16(acc[mt][nt], al[mt], bp);
                    }
            }
        } else {
#pragma unroll
            for (int ks = 0; ks < 2; ks++) {
                uint32_t ah[2][4], al[2][4], bh4[4][4], bl4[4][4];
                const int ct = q - 16;
#pragma unroll
                for (int mt = 0; mt < 2; mt++) {
                    const uint32_t ad = s0 + A_SPH +
                        (wm * 32 + mt * 16 + (midx & 1) * 8 + r8) * AP_STR +
                        (ct * 32 + ks * 16 + (midx >> 1) * 8) * 2;
                    ldsm_x4(ad, ah[mt]);
                    ldsm_x4(ad + (A_SPL - A_SPH), al[mt]);
                }
#pragma unroll
                for (int ng = 0; ng < 4; ng++) {
                    const uint32_t bd = bh +
                        (wn * 64 + ng * 16 + (midx >> 1) * 8 + r8) * AB_STR +
                        (ks * 16 + (midx & 1) * 8) * 2;
                    ldsm_x4(bd, bh4[ng]);
                    ldsm_x4(bd + 20480, bl4[ng]);
                }
#pragma unroll
                for (int mt = 0; mt < 2; mt++)
#pragma unroll
                    for (int nt = 0; nt < 8; nt++) {
                        const uint32_t* bp  = &bh4[nt >> 1][(nt & 1) * 2];
                        const uint32_t* blp = &bl4[nt >> 1][(nt & 1) * 2];
                        mma_f16(acc[mt][nt], ah[mt], bp);
                        mma_f16(acc[mt][nt], al[mt], bp);
                        mma_f16(acc[mt][nt], ah[mt], blp);
                    }
            }
        }
    }

    // epilogue: row scale d^(-i-1) * R_SCALE, write Rh only (1-term out GEMM)
    __half* Rh = g_Rh + nat;
#pragma unroll
    for (int mt = 0; mt < 2; mt++) {
        const int i0 = wm * 32 + mt * 16 + (lane >> 2);
        const float s1 = exp2f(-(float)(i0 + 1) * lg2d) * R_SCALE;
        const float s2 = exp2f(-(float)(i0 + 9) * lg2d) * R_SCALE;
#pragma unroll
        for (int nt = 0; nt < 8; nt++) {
            const int col = wn * 64 + nt * 8 + (lane & 3) * 2;
            const size_t o = (size_t)i0 * C_SZ + col;
            *(__half2*)(Rh + o) = __half2(__float2half_rn(acc[mt][nt][0] * s1),
                                          __float2half_rn(acc[mt][nt][1] * s1));
            const size_t o2 = o + 8 * (size_t)C_SZ;
            *(__half2*)(Rh + o2) = __half2(__float2half_rn(acc[mt][nt][2] * s2),
                                           __float2half_rn(acc[mt][nt][3] * s2));
        }
    }
}

// ===========================================================================
// fp32 -> (hi, lo) fp16 split
// ===========================================================================
__global__ void split_kernel(const float* __restrict__ s,
                             __half* __restrict__ h,
                             __half* __restrict__ l, int n4)
{
    int i = blockIdx.x * blockDim.x + threadIdx.x;
    if (i >= n4) return;
    float4 v = ((const float4*)s)[i];
    __half h0 = __float2half_rn(v.x), h1 = __float2half_rn(v.y);
    __half h2 = __float2half_rn(v.z), h3 = __float2half_rn(v.w);
    ((__half2*)h)[2 * i]     = __half2(h0, h1);
    ((__half2*)h)[2 * i + 1] = __half2(h2, h3);
    ((__half2*)l)[2 * i]     = __half2(__float2half_rn(v.x - __half2float(h0)),
                                       __float2half_rn(v.y - __half2float(h1)));
    ((__half2*)l)[2 * i + 1] = __half2(__float2half_rn(v.z - __half2float(h2)),
                                       __float2half_rn(v.w - __half2float(h3)));
}

// ===========================================================================
// fp32 -> fp16 hi only (for 1-term A operands)
// ===========================================================================
__global__ void tohalf_kernel(const float* __restrict__ s,
                              __half* __restrict__ h, int n4)
{
    int i = blockIdx.x * blockDim.x + threadIdx.x;
    if (i >= n4) return;
    float4 v = ((const float4*)s)[i];
    ((__half2*)h)[2 * i]     = __half2(__float2half_rn(v.x), __float2half_rn(v.y));
    ((__half2*)h)[2 * i + 1] = __half2(__float2half_rn(v.z), __float2half_rn(v.w));
}

// ===========================================================================
// basis [1024,256] -> basis^T fp16 hi/lo
// ===========================================================================
__global__ void transpose_split(const float* __restrict__ in,
                                __half* __restrict__ oh, __half* __restrict__ ol)
{
    __shared__ float t[32][33];
    const int v0 = blockIdx.x * 32, c0 = blockIdx.y * 32;
    const int tx = threadIdx.x, ty = threadIdx.y;
#pragma unroll
    for (int j = 0; j < 32; j += 8)
        t[ty + j][tx] = in[(size_t)(v0 + ty + j) * C_SZ + c0 + tx];
    __syncthreads();
#pragma unroll
    for (int j = 0; j < 32; j += 8) {
        float val = t[tx][ty + j];
        __half h = __float2half_rn(val);
        oh[(size_t)(c0 + ty + j) * V_SZ + v0 + tx] = h;
        ol[(size_t)(c0 + ty + j) * V_SZ + v0 + tx] =
            __float2half_rn(val - __half2float(h));
    }
}

// ===========================================================================
// V [B*T, C] fp32 -> decayed V^T [B][C][T] fp16 hi/lo (decay d^(t mod 64))
// ===========================================================================
__global__ void transpose_split_vd(const float* __restrict__ in,
                                   __half* __restrict__ oh, __half* __restrict__ ol,
                                   const float* __restrict__ dlp)
{
    __shared__ float t[32][33];
    const int b = blockIdx.z;
    const int t0 = blockIdx.x * 32, c0 = blockIdx.y * 32;
    const int tx = threadIdx.x, ty = threadIdx.y;
    const float lg2d = log2f(get_decay(dlp));
    const float dr = exp2f((float)((t0 + tx) & 63) * lg2d);
#pragma unroll
    for (int j = 0; j < 32; j += 8)
        t[ty + j][tx] = in[((size_t)b * T_SZ + t0 + ty + j) * C_SZ + c0 + tx];
    __syncthreads();
#pragma unroll
    for (int j = 0; j < 32; j += 8) {
        float val = t[tx][ty + j] * dr;
        __half h = __float2half_rn(val);
        const size_t o = (size_t)b * C_SZ * T_SZ + (size_t)(c0 + ty + j) * T_SZ + t0 + tx;
        oh[o] = h;
        ol[o] = __float2half_rn(val - __half2float(h));
    }
}

// ===========================================================================
// K hi [B*T, C] fp16 -> K^T [B][C][T] fp16 hi
// ===========================================================================
__global__ void transpose_h(const __half* __restrict__ in, __half* __restrict__ out)
{
    __shared__ __half t[32][33];
    const int b = blockIdx.z;
    const int t0 = blockIdx.x * 32, c0 = blockIdx.y * 32;
    const int tx = threadIdx.x, ty = threadIdx.y;
#pragma unroll
    for (int j = 0; j < 32; j += 8)
        t[ty + j][tx] = in[((size_t)b * T_SZ + t0 + ty + j) * C_SZ + c0 + tx];
    __syncthreads();
#pragma unroll
    for (int j = 0; j < 32; j += 8)
        out[(size_t)b * C_SZ * T_SZ + (size_t)(c0 + ty + j) * T_SZ + t0 + tx] =
            t[tx][ty + j];
}

// ===========================================================================
// SGEMM nt (f32x2) — Wo build only
// ===========================================================================
__global__ void __launch_bounds__(256) sgemm_nt(
    const float* __restrict__ A, const float* __restrict__ B,
    float* __restrict__ C, int M, int N, int K)
{
    __shared__ __align__(16) float As[8][128];
    __shared__ __align__(16) float Bs[8][128];
    const int tid = threadIdx.x;
    const int m0 = blockIdx.y * 128, n0 = blockIdx.x * 128;
    const int tr = tid >> 4, tc = tid & 15;
    const int ar = tid >> 1, ac = (tid & 1) * 4;
    ull acc[8][4] = {};
    const float* Aptr = A + (size_t)(m0 + ar) * K + ac;
    const float* Bptr = B + (size_t)(n0 + ar) * K + ac;
    for (int k0 = 0; k0 < K; k0 += 8) {
        float4 av = *(const float4*)(Aptr + k0);
        As[ac + 0][ar] = av.x; As[ac + 1][ar] = av.y;
        As[ac + 2][ar] = av.z; As[ac + 3][ar] = av.w;
        float4 bv = *(const float4*)(Bptr + k0);
        Bs[ac + 0][ar] = bv.x; Bs[ac + 1][ar] = bv.y;
        Bs[ac + 2][ar] = bv.z; Bs[ac + 3][ar] = bv.w;
        __syncthreads();
#pragma unroll
        for (int kk = 0; kk < 8; kk++) {
            const ull* bp = (const ull*)&Bs[kk][tc * 8];
            ull b0 = bp[0], b1 = bp[1], b2 = bp[2], b3 = bp[3];
            const float* ap = &As[kk][tr * 8];
#pragma unroll
            for (int i = 0; i < 8; i++) {
                ull a2 = pack2(ap[i]);
                ffma2(acc[i][0], a2, b0); ffma2(acc[i][1], a2, b1);
                ffma2(acc[i][2], a2, b2); ffma2(acc[i][3], a2, b3);
            }
        }
        __syncthreads();
    }
#pragma unroll
    for (int i = 0; i < 8; i++) {
        float* Cp = C + (size_t)(m0 + tr * 8 + i) * N + n0 + tc * 8;
        float2 p0 = *(float2*)&acc[i][0], p1 = *(float2*)&acc[i][1];
        float2 p2 = *(float2*)&acc[i][2], p3 = *(float2*)&acc[i][3];
        *(float4*)(Cp)     = make_float4(p0.x, p0.y, p1.x, p1.y);
        *(float4*)(Cp + 4) = make_float4(p2.x, p2.y, p3.x, p3.y);
    }
}

// ===========================================================================
// scan: run=0; for c desc: store d^64*run (fp16 hi); run = d^64*run + A[c]
// ===========================================================================
__global__ void scan_kernel(const float* __restrict__ dlp)
{
    const int e = blockIdx.x * blockDim.x + threadIdx.x;
    const int b = blockIdx.y;
    const float decay = get_decay(dlp);
    const float dL = exp2f((float)L_SZ * log2f(decay));
    float run = 0.0f;
    const size_t base = (size_t)b * NCH * (C_SZ * C_SZ) + e;
    for (int c = NCH - 1; c >= 0; c--) {
        const size_t pos = base + (size_t)c * (C_SZ * C_SZ);
        const float sc_ = dL * run;
        g_Sth[pos] = __float2half_rn(sc_);
        run = sc_ + g_AS[pos];
    }
}

// ===========================================================================
extern "C" void kernel_launch(void* const* d_in, const int* in_sizes, int n_in,
                              void* d_out, int out_size)
{
    const float* x     = (const float*)d_in[0];
    const float* basis = (const float*)d_in[1];
    const float* qc    = (const float*)d_in[2];
    const float* kc    = (const float*)d_in[3];
    const float* vc    = (const float*)d_in[4];
    const float* oc    = (const float*)d_in[5];
    const float* dl    = (const float*)d_in[6];
    const float* os    = (const float*)d_in[7];
    float* out = (float*)d_out;

    float *pWo, *pQKV, *pAS;
    __half *pxh, *pbTh, *pbTl, *pxbh, *pxbl, *pch, *pcl, *pWoh, *pWol;
    __half *pQKh, *pQKl, *pVdth, *pVdtl, *pKth, *pRh;
    cudaGetSymbolAddress((void**)&pWo,   g_Wo);
    cudaGetSymbolAddress((void**)&pQKV,  g_QKV);
    cudaGetSymbolAddress((void**)&pAS,   g_AS);
    cudaGetSymbolAddress((void**)&pxh,   g_xh);
    cudaGetSymbolAddress((void**)&pbTh,  g_bTh);
    cudaGetSymbolAddress((void**)&pbTl,  g_bTl);
    cudaGetSymbolAddress((void**)&pxbh,  g_xbh);
    cudaGetSymbolAddress((void**)&pxbl,  g_xbl);
    cudaGetSymbolAddress((void**)&pch,   g_ch);
    cudaGetSymbolAddress((void**)&pcl,   g_cl);
    cudaGetSymbolAddress((void**)&pWoh,  g_Woh);
    cudaGetSymbolAddress((void**)&pWol,  g_Wol);
    cudaGetSymbolAddress((void**)&pQKh,  g_QKh);
    cudaGetSymbolAddress((void**)&pQKl,  g_QKl);
    cudaGetSymbolAddress((void**)&pVdth, g_Vdth);
    cudaGetSymbolAddress((void**)&pVdtl, g_Vdtl);
    cudaGetSymbolAddress((void**)&pKth,  g_Kth);
    cudaGetSymbolAddress((void**)&pRh,   g_Rh);

    const int SMEM_A1 = 3 * 2 * ARR_B;   // 61440
    const int SMEM_A2 = 3 * 3 * ARR_B;   // 92160
    cudaFuncSetAttribute(mma_gemm<1>, cudaFuncAttributeMaxDynamicSharedMemorySize, SMEM_A1);
    cudaFuncSetAttribute(mma_gemm<2>, cudaFuncAttributeMaxDynamicSharedMemorySize, SMEM_A2);
    cudaFuncSetAttribute(chunk_mma, cudaFuncAttributeMaxDynamicSharedMemorySize, CK_SMEM);
    cudaFuncSetAttribute(attn_mma, cudaFuncAttributeMaxDynamicSharedMemorySize, A_SMEM);

    // 1. prep: basis^T split, x hi-convert, coeff splits, Wo build + split
    transpose_split<<<dim3(32, 8), dim3(32, 8)>>>(basis, pbTh, pbTl);
    tohalf_kernel<<<(BT * V_SZ / 4 + 255) / 256, 256>>>(x, pxh, BT * V_SZ / 4);
    split_kernel<<<(C_SZ * C_SZ / 4 + 255) / 256, 256>>>(qc, pch, pcl, C_SZ * C_SZ / 4);
    split_kernel<<<(C_SZ * C_SZ / 4 + 255) / 256, 256>>>(
        kc, pch + C_SZ * C_SZ, pcl + C_SZ * C_SZ, C_SZ * C_SZ / 4);
    split_kernel<<<(C_SZ * C_SZ / 4 + 255) / 256, 256>>>(
        vc, pch + 2 * C_SZ * C_SZ, pcl + 2 * C_SZ * C_SZ, C_SZ * C_SZ / 4);
    sgemm_nt<<<dim3(2, 8), 256>>>(basis, oc, pWo, 1024, 256, 256);
    split_kernel<<<(V_SZ * C_SZ / 4 + 255) / 256, 256>>>(pWo, pWoh, pWol, V_SZ * C_SZ / 4);

    // 2. xb = x @ basis (1-term A) -> fp16 hi/lo
    mma_gemm<1><<<dim3(2, 128, 1), 256, SMEM_A1>>>(
        pxh, pxh, pbTh, pAS /*dummy*/, pxbh, pxbl, 1, 0,
        V_SZ, 0, 0, C_SZ, nullptr, 1.0f);

    // 3. QKV = xb @ coeffs^T (2-term A): z=0,1 -> Q/K fp16 hi/lo; z=2 -> V fp32
    mma_gemm<2><<<dim3(2, 128, 3), 256, SMEM_A2>>>(
        pxbh, pxbl, pch, pQKV, pQKh, pQKl, 2, (size_t)BT * C_SZ,
        C_SZ, (size_t)C_SZ * C_SZ, (size_t)BT * C_SZ, C_SZ, nullptr, 1.0f);

    // 4. transposes: decayed V^T hi/lo, K^T hi
    transpose_split_vd<<<dim3(128, 8, B_SZ), dim3(32, 8)>>>(
        pQKV + 2 * (size_t)BT * C_SZ, pVdth, pVdtl, dl);
    transpose_h<<<dim3(128, 8, B_SZ), dim3(32, 8)>>>(pQKh + (size_t)BT * C_SZ, pKth);

    // 5. chunk A^T, scan -> fp16 states, attn -> Rh
    chunk_mma<<<dim3(2, 2, B_SZ * NCH), 256, CK_SMEM>>>();
    scan_kernel<<<dim3(256, B_SZ), 256>>>(dl);
    attn_mma<<<dim3(NCH, B_SZ), 256, A_SMEM>>>(dl);

    // 6. output projection: out = R @ Wo^T * out_scale (1-term A)
    mma_gemm<1><<<dim3(8, 128, 1), 256, SMEM_A1>>>(
        pRh, pRh, pWoh, out, nullptr, nullptr, 0, 0,
        C_SZ, 0, 0, V_SZ, os, R_UNSCALE);
}